// round 9
// baseline (speedup 1.0000x reference)
#include <cuda_runtime.h>
#include <cuda_fp16.h>
#include <stdint.h>

#define Bdim 4
#define Ndim 512
#define NCdim 128
#define ECdim 32
#define OCdim 64
#define KNdim 10
#define KEdim 5
#define NIN 192   // 2*EC + NC
#define EWARPS 8
#define PX 12     // node-kernel transposed pitch (float4-aligned, 8 nodes + pad)

// packed per-node vectors: {n1, n2, q1, q2} per channel (float4-interleaved)
__device__ float g_pk[Bdim*Ndim*OCdim*4];

__device__ __forceinline__ float silu_f(float x) {
    return __fdividef(x, 1.0f + __expf(-x));
}

__device__ __forceinline__ void mma16816(float& c0, float& c1, float& c2, float& c3,
                                         uint32_t a0, uint32_t a1, uint32_t a2, uint32_t a3,
                                         uint32_t b0, uint32_t b1) {
    asm volatile("mma.sync.aligned.m16n8k16.row.col.f32.f16.f16.f32 "
                 "{%0,%1,%2,%3},{%4,%5,%6,%7},{%8,%9},{%0,%1,%2,%3};\n"
                 : "+f"(c0), "+f"(c1), "+f"(c2), "+f"(c3)
                 : "r"(a0), "r"(a1), "r"(a2), "r"(a3), "r"(b0), "r"(b1));
}

__device__ __forceinline__ void split_h2(float x, float y, uint32_t& hi, uint32_t& lo) {
    __half hx = __float2half_rn(x), hy = __float2half_rn(y);
    __half lx = __float2half_rn(x - __half2float(hx));
    __half ly = __float2half_rn(y - __half2float(hy));
    __half2 h = __halves2half2(hx, hy), l = __halves2half2(lx, ly);
    hi = *(uint32_t*)&h;  lo = *(uint32_t*)&l;
}

__device__ __forceinline__ float2 unpack_sum(uint32_t h, uint32_t l) {
    float2 fh = __half22float2(*(__half2*)&h);
    float2 fl = __half22float2(*(__half2*)&l);
    return make_float2(fh.x + fl.x, fh.y + fl.y);
}

// ---------------------------------------------------------------------------
// Kernel 1: per-node work, 8 nodes per block. Warp w = node i0+w for the
// masked edge reductions (DRAM-bound); GEMVs batched over 8 nodes with
// transposed smem activations so weight loads amortize 8x.
// ---------------------------------------------------------------------------
__global__ __launch_bounds__(256)
void node_kernel(const float* __restrict__ node,
                 const float* __restrict__ edge,
                 const int* __restrict__ block_id,
                 const int* __restrict__ vmask,
                 const float* __restrict__ W_nt, const float* __restrict__ b_nt,
                 const float* __restrict__ W_n1, const float* __restrict__ b_n1,
                 const float* __restrict__ W_f1,
                 const float* __restrict__ W_no1, const float* __restrict__ b_no1,
                 const float* __restrict__ g_no, const float* __restrict__ be_no,
                 const float* __restrict__ W_no2, const float* __restrict__ b_no2,
                 float* __restrict__ out_node)
{
    const int b  = blockIdx.x >> 6;
    const int i0 = (blockIdx.x & 63) * 8;
    const int tid = threadIdx.x;
    const int w    = tid >> 5;
    const int lane = tid & 31;

    __shared__ int           s_bid[Ndim];
    __shared__ unsigned char s_vm[Ndim];
    __shared__ float s_x[NIN*PX];     // transposed inputs [k][node]
    __shared__ float s_hT[NCdim*PX];
    __shared__ float s_nT[NCdim*PX];
    __shared__ float s_tT[NCdim*PX];
    __shared__ float s_vT[NCdim*PX];

    for (int k = tid; k < Ndim; k += 256) {
        s_bid[k] = block_id[b*Ndim + k];
        s_vm[k]  = (vmask[b*Ndim + k] != 0) ? 1 : 0;
    }
    __syncthreads();

    // ---- masked reductions: warp w -> node i0+w ----
    {
        const int i = i0 + w;
        const int  bii  = s_bid[i];
        const bool nm_i = (bii >= 0);
        const bool vm_i = (s_vm[i] != 0);
        float acc_in = 0.f, acc_out = 0.f, cnt_in = 0.f, cnt_out = 0.f;
        const float* erow = edge + ((size_t)(b*Ndim + i) * Ndim) * ECdim;
        const float* ecol = edge + ((size_t)b*Ndim) * Ndim * ECdim + (size_t)i*ECdim;

        for (int j0 = 0; j0 < Ndim; j0 += 8) {
            #pragma unroll
            for (int u = 0; u < 8; u++) {
                int j = j0 + u;
                int  bj   = s_bid[j];
                bool nm_j = (bj >= 0);
                bool pv   = nm_i && nm_j;
                bool cij  = pv && ((bii > bj) || (bii == bj && !vm_i));
                bool cji  = pv && ((bj > bii) || (bj == bii && (s_vm[j] == 0)));
                if (cij) { acc_in  += erow[(size_t)j*ECdim + lane];        cnt_in  += 1.f; }
                if (cji) { acc_out += ecol[(size_t)j*Ndim*ECdim + lane];   cnt_out += 1.f; }
            }
        }
        s_x[lane*PX + w]        = acc_in  / fmaxf(cnt_in,  1.f);
        s_x[(lane+32)*PX + w]   = acc_out / fmaxf(cnt_out, 1.f);
        // node features (masked)
        float msk = nm_i ? 1.f : 0.f;
        float4 nd = *(const float4*)&node[(size_t)(b*Ndim + i)*NCdim + lane*4];
        s_x[(64 + lane*4 + 0)*PX + w] = nd.x * msk;
        s_x[(64 + lane*4 + 1)*PX + w] = nd.y * msk;
        s_x[(64 + lane*4 + 2)*PX + w] = nd.z * msk;
        s_x[(64 + lane*4 + 3)*PX + w] = nd.w * msk;
    }
    __syncthreads();

    const int o = tid & 127;
    const int g = tid >> 7;       // nodes 4g..4g+3

    // ---- h = silu(x @ W_nt + b_nt) * nm ----
    {
        float bb = b_nt[o];
        float4 acc = make_float4(bb, bb, bb, bb);
        #pragma unroll 4
        for (int k = 0; k < NIN; k++) {
            float wv = W_nt[k*NCdim + o];
            float4 xi = *(const float4*)&s_x[k*PX + g*4];
            acc.x += wv*xi.x; acc.y += wv*xi.y; acc.z += wv*xi.z; acc.w += wv*xi.w;
        }
        #pragma unroll
        for (int c4 = 0; c4 < 4; c4++) {
            int nn = g*4 + c4;
            float v = (c4 == 0) ? acc.x : (c4 == 1) ? acc.y : (c4 == 2) ? acc.z : acc.w;
            s_hT[o*PX + nn] = (s_bid[i0+nn] >= 0) ? silu_f(v) : 0.f;
        }
    }
    __syncthreads();

    // ---- n = h @ W_n1 + b_n1 ; t = h @ W_no1 + b_no1 ----
    {
        float bn = b_n1[o], bt = b_no1[o];
        float4 an = make_float4(bn, bn, bn, bn);
        float4 at = make_float4(bt, bt, bt, bt);
        #pragma unroll 4
        for (int k = 0; k < NCdim; k++) {
            float wn = W_n1[k*NCdim + o];
            float wt = W_no1[k*NCdim + o];
            float4 xi = *(const float4*)&s_hT[k*PX + g*4];
            an.x += wn*xi.x; an.y += wn*xi.y; an.z += wn*xi.z; an.w += wn*xi.w;
            at.x += wt*xi.x; at.y += wt*xi.y; at.z += wt*xi.z; at.w += wt*xi.w;
        }
        s_nT[o*PX + g*4+0] = an.x; s_nT[o*PX + g*4+1] = an.y;
        s_nT[o*PX + g*4+2] = an.z; s_nT[o*PX + g*4+3] = an.w;
        s_tT[o*PX + g*4+0] = at.x; s_tT[o*PX + g*4+1] = at.y;
        s_tT[o*PX + g*4+2] = at.z; s_tT[o*PX + g*4+3] = at.w;
    }
    __syncthreads();

    // ---- q{1,2} = n{1,2} @ W_f1 ; write packed g_pk ----
    {
        const int oq = tid & 63;
        const int wh = (tid >> 6) & 1;
        float4 aq = make_float4(0.f, 0.f, 0.f, 0.f);
        #pragma unroll 4
        for (int k = 0; k < OCdim; k++) {
            float wq = W_f1[k*OCdim + oq];
            float4 xi = *(const float4*)&s_nT[(wh*OCdim + k)*PX + g*4];
            aq.x += wq*xi.x; aq.y += wq*xi.y; aq.z += wq*xi.z; aq.w += wq*xi.w;
        }
        #pragma unroll
        for (int c4 = 0; c4 < 4; c4++) {
            int nn = g*4 + c4;
            float qv = (c4 == 0) ? aq.x : (c4 == 1) ? aq.y : (c4 == 2) ? aq.z : aq.w;
            size_t base = ((size_t)(b*Ndim + i0 + nn)*OCdim + oq)*4;
            g_pk[base + wh]     = s_nT[(wh*OCdim + oq)*PX + nn];
            g_pk[base + 2 + wh] = qv;
        }
    }

    // ---- LayerNorm(t) + silu -> s_vT (warp w = node w) ----
    {
        float tv0 = s_tT[lane*PX + w];
        float tv1 = s_tT[(lane+32)*PX + w];
        float tv2 = s_tT[(lane+64)*PX + w];
        float tv3 = s_tT[(lane+96)*PX + w];
        float s = tv0 + tv1 + tv2 + tv3;
        #pragma unroll
        for (int o2 = 16; o2; o2 >>= 1) s += __shfl_xor_sync(0xffffffffu, s, o2);
        float mean = s * (1.f/NCdim);
        float d0 = tv0-mean, d1 = tv1-mean, d2 = tv2-mean, d3 = tv3-mean;
        float var = d0*d0 + d1*d1 + d2*d2 + d3*d3;
        #pragma unroll
        for (int o2 = 16; o2; o2 >>= 1) var += __shfl_xor_sync(0xffffffffu, var, o2);
        float rstd = rsqrtf(var * (1.f/NCdim) + 1e-5f);
        s_vT[lane*PX + w]      = silu_f(d0*rstd*g_no[lane]    + be_no[lane]);
        s_vT[(lane+32)*PX + w] = silu_f(d1*rstd*g_no[lane+32] + be_no[lane+32]);
        s_vT[(lane+64)*PX + w] = silu_f(d2*rstd*g_no[lane+64] + be_no[lane+64]);
        s_vT[(lane+96)*PX + w] = silu_f(d3*rstd*g_no[lane+96] + be_no[lane+96]);
    }
    __syncthreads();

    // ---- node logits: warp w = node w, lanes 0..9 = channels ----
    if (lane < KNdim) {
        float a = b_no2[lane];
        #pragma unroll 4
        for (int k = 0; k < NCdim; k++)
            a += s_vT[k*PX + w] * W_no2[k*KNdim + lane];
        bool nm_i = (s_bid[i0 + w] >= 0);
        out_node[(size_t)(b*Ndim + i0 + w)*KNdim + lane] = nm_i ? a : 0.f;
    }
}

// ---------------------------------------------------------------------------
// Kernel 2: edge work (round-8 structure; B-fragments packed as uint4).
// ---------------------------------------------------------------------------
#define SM_KEY     0         // 512 int
#define SM_BE1B    2048      // 64 f
#define SM_BF2B    2304      // 64 f
#define SM_BF1     2560      // 64 f
#define SM_NIPK    2816      // 128 float4
#define SM_BEO1    4864      // 32 f
#define SM_GEO     4992      // 32 f
#define SM_BEEO    5120      // 32 f
#define SM_BEO2    5248      // 8 f (+pad)
#define SM_EO1T    5296      // 32*68 f
#define SM_EO2T    14000     // 8*36 f
#define SM_BE1P    15152     // 512 uint4 (hi.x hi.y lo.x lo.y)
#define SM_BF2P    23344     // 1024 uint4
#define SM_WARP    39728
#define SM_PERW    3456      // es [8][68]f 2176 | sv [8][36]f 1152 | meta 128
#define SM_TOTAL   (SM_WARP + EWARPS*SM_PERW)   // 67376

__global__ __launch_bounds__(256, 2)
void edge_kernel(const float* __restrict__ edge,
                 const int* __restrict__ block_id,
                 const int* __restrict__ vmask,
                 const float* __restrict__ W_e1, const float* __restrict__ b_e1,
                 const float* __restrict__ b_f1,
                 const float* __restrict__ W_f2, const float* __restrict__ b_f2,
                 const float* __restrict__ W_eo1, const float* __restrict__ b_eo1,
                 const float* __restrict__ g_eo, const float* __restrict__ be_eo,
                 const float* __restrict__ W_eo2, const float* __restrict__ b_eo2,
                 float* __restrict__ out_edge)
{
    extern __shared__ char dsm[];
    const int b = blockIdx.x >> 8;
    const int r = blockIdx.x & 255;
    const int tid  = threadIdx.x;
    const int w    = tid >> 5;
    const int lane = tid & 31;
    const int grp  = lane >> 2;
    const int q    = lane & 3;

    int*    s_key  = (int*)(dsm + SM_KEY);
    float*  sbe1b  = (float*)(dsm + SM_BE1B);
    float*  sbf2b  = (float*)(dsm + SM_BF2B);
    float*  sbF1   = (float*)(dsm + SM_BF1);
    float4* s_nipk = (float4*)(dsm + SM_NIPK);
    float*  sbeo1  = (float*)(dsm + SM_BEO1);
    float*  sgeo   = (float*)(dsm + SM_GEO);
    float*  sbeeo  = (float*)(dsm + SM_BEEO);
    float*  sbeo2  = (float*)(dsm + SM_BEO2);
    float*  sw_eo1T = (float*)(dsm + SM_EO1T);
    float*  sw_eo2T = (float*)(dsm + SM_EO2T);
    uint4*  be1p   = (uint4*)(dsm + SM_BE1P);
    uint4*  bf2p   = (uint4*)(dsm + SM_BF2P);

    char*  wbase = dsm + SM_WARP + w*SM_PERW;
    float* es    = (float*)wbase;            // [8][68]
    float* sv    = (float*)(wbase + 2176);   // [8][36]
    int*   smi   = (int*)(wbase + 3328);
    int*   smj   = smi + 8;
    float* sem   = (float*)(smi + 16);
    int*   sact  = smi + 24;

    const int i_a = r, i_b = Ndim - 1 - r;

    for (int k = tid; k < Ndim; k += 256)
        s_key[k] = block_id[b*Ndim + k]*2 + ((vmask[b*Ndim + k] != 0) ? 1 : 0);
    if (tid < 64)  sbe1b[tid] = b_e1[tid];
    if (tid >= 64 && tid < 128)  sbf2b[tid-64] = b_f2[tid-64];
    if (tid >= 128 && tid < 192) sbF1[tid-128] = b_f1[tid-128];
    if (tid >= 192 && tid < 224) sbeo1[tid-192] = b_eo1[tid-192];
    if (tid >= 224 && tid < 256) sgeo[tid-224] = g_eo[tid-224];
    if (tid < 32)  sbeeo[tid] = be_eo[tid];
    if (tid >= 32 && tid < 40) sbeo2[tid-32] = b_eo2[tid-32];
    if (tid >= 40 && tid < 168) {
        int k = tid - 40;
        int row = k >> 6, ch = k & 63;
        int irow = row ? i_b : i_a;
        s_nipk[k] = *(const float4*)&g_pk[((size_t)(b*Ndim + irow)*OCdim + ch)*4];
    }
    for (int k = tid; k < OCdim*32; k += 256) {
        int kk = k >> 5, c = k & 31;
        sw_eo1T[c*68 + kk] = W_eo1[k];
    }
    for (int k = tid; k < 8*36; k += 256) {
        int ch = k / 36, kk = k % 36;
        sw_eo2T[k] = (ch < KEdim && kk < ECdim) ? W_eo2[kk*KEdim + ch] : 0.f;
    }
    for (int e = tid; e < 512; e += 256) {
        int lane_ = e & 31, nt = (e >> 5) & 7, ks = e >> 8;
        int q_ = lane_ & 3, g_ = lane_ >> 2;
        int k0 = ks*16 + 2*q_;
        int n  = nt*8 + g_;
        uint32_t h0, l0, h1, l1;
        split_h2(W_e1[k0*OCdim + n],     W_e1[(k0+1)*OCdim + n], h0, l0);
        split_h2(W_e1[(k0+8)*OCdim + n], W_e1[(k0+9)*OCdim + n], h1, l1);
        be1p[e] = make_uint4(h0, h1, l0, l1);
    }
    for (int e = tid; e < 1024; e += 256) {
        int lane_ = e & 31, nt = (e >> 5) & 7, ks = e >> 8;
        int q_ = lane_ & 3, g_ = lane_ >> 2;
        int k0 = ks*16 + 2*q_;
        int n  = nt*8 + g_;
        uint32_t h0, l0, h1, l1;
        split_h2(W_f2[k0*OCdim + n],     W_f2[(k0+1)*OCdim + n], h0, l0);
        split_h2(W_f2[(k0+8)*OCdim + n], W_f2[(k0+9)*OCdim + n], h1, l1);
        bf2p[e] = make_uint4(h0, h1, l0, l1);
    }
    __syncthreads();

    const float beo1v = sbeo1[lane];
    const float geov  = sgeo[lane];
    const float beeov = sbeeo[lane];

    const int npa   = Ndim - i_a;
    const int total = Ndim + 1;

    for (int base = w*8; base < total; base += EWARPS*8) {
        if (lane < 8) {
            int p = base + lane;
            int act = (p < total) ? 1 : 0;
            int pc = act ? p : 0;
            bool aA = pc < npa;
            int i2 = aA ? i_a : i_b;
            int j2 = aA ? (i_a + pc) : (i_b + (pc - npa));
            int ki = s_key[i2], kj = s_key[j2];
            int bi_ = ki >> 1, bj_ = kj >> 1;
            bool nm2 = (bi_ >= 0) && (bj_ >= 0);
            bool cij = (bi_ > bj_) || (bi_ == bj_ && !(ki & 1));
            bool cji = (bj_ > bi_) || (bj_ == bi_ && !(kj & 1));
            smi[lane] = i2; smj[lane] = j2;
            sem[lane] = (nm2 && (cij || cji)) ? 1.f : 0.f;
            sact[lane] = act;
        }
        __syncwarp();

        const int   i2  = smi[grp];
        const int   j2  = smj[grp];
        const float emv = sem[grp];
        const bool  isA = (i2 == i_a);

        uint32_t aEh[8], aEl[8];
        {
            const float* eij = edge + ((size_t)(b*Ndim + i2)*Ndim + j2)*ECdim;
            const float* eji = edge + ((size_t)(b*Ndim + j2)*Ndim + i2)*ECdim;
            #pragma unroll
            for (int ks = 0; ks < 2; ks++) {
                float2 v0 = *(const float2*)(eij + ks*16 + 2*q);
                float2 v1 = *(const float2*)(eji + ks*16 + 2*q);
                float2 v2 = *(const float2*)(eij + ks*16 + 8 + 2*q);
                float2 v3 = *(const float2*)(eji + ks*16 + 8 + 2*q);
                split_h2(v0.x*emv, v0.y*emv, aEh[ks*4+0], aEl[ks*4+0]);
                split_h2(v1.x*emv, v1.y*emv, aEh[ks*4+1], aEl[ks*4+1]);
                split_h2(v2.x*emv, v2.y*emv, aEh[ks*4+2], aEl[ks*4+2]);
                split_h2(v3.x*emv, v3.y*emv, aEh[ks*4+3], aEl[ks*4+3]);
            }
        }

        float cE[8][4];
        #pragma unroll
        for (int nt = 0; nt < 8; nt++) {
            float2 bb = *(const float2*)&sbe1b[nt*8 + 2*q];
            cE[nt][0] = bb.x; cE[nt][1] = bb.y; cE[nt][2] = bb.x; cE[nt][3] = bb.y;
        }
        #pragma unroll
        for (int ks = 0; ks < 2; ks++) {
            #pragma unroll
            for (int nt = 0; nt < 8; nt++) {
                uint4 Bp = be1p[(ks*8 + nt)*32 + lane];
                mma16816(cE[nt][0], cE[nt][1], cE[nt][2], cE[nt][3],
                         aEh[ks*4+0], aEh[ks*4+1], aEh[ks*4+2], aEh[ks*4+3], Bp.x, Bp.y);
                mma16816(cE[nt][0], cE[nt][1], cE[nt][2], cE[nt][3],
                         aEl[ks*4+0], aEl[ks*4+1], aEl[ks*4+2], aEl[ks*4+3], Bp.x, Bp.y);
                mma16816(cE[nt][0], cE[nt][1], cE[nt][2], cE[nt][3],
                         aEh[ks*4+0], aEh[ks*4+1], aEh[ks*4+2], aEh[ks*4+3], Bp.z, Bp.w);
            }
        }

        uint32_t e1h[16], e1l[16];
        #pragma unroll
        for (int ks = 0; ks < 4; ks++) {
            split_h2(cE[2*ks][0],   cE[2*ks][1],   e1h[ks*4+0], e1l[ks*4+0]);
            split_h2(cE[2*ks][2],   cE[2*ks][3],   e1h[ks*4+1], e1l[ks*4+1]);
            split_h2(cE[2*ks+1][0], cE[2*ks+1][1], e1h[ks*4+2], e1l[ks*4+2]);
            split_h2(cE[2*ks+1][2], cE[2*ks+1][3], e1h[ks*4+3], e1l[ks*4+3]);
        }

        float cF[8][4];
        #pragma unroll
        for (int nt = 0; nt < 8; nt++) {
            float2 bb = *(const float2*)&sbf2b[nt*8 + 2*q];
            cF[nt][0] = bb.x; cF[nt][1] = bb.y; cF[nt][2] = bb.x; cF[nt][3] = bb.y;
        }
        #pragma unroll
        for (int ks = 0; ks < 4; ks++) {
            #pragma unroll
            for (int nt = 0; nt < 8; nt++) {
                uint4 Bp = bf2p[(ks*8 + nt)*32 + lane];
                mma16816(cF[nt][0], cF[nt][1], cF[nt][2], cF[nt][3],
                         e1h[ks*4+0], e1h[ks*4+1], e1h[ks*4+2], e1h[ks*4+3], Bp.x, Bp.y);
                mma16816(cF[nt][0], cF[nt][1], cF[nt][2], cF[nt][3],
                         e1l[ks*4+0], e1l[ks*4+1], e1l[ks*4+2], e1l[ks*4+3], Bp.x, Bp.y);
                mma16816(cF[nt][0], cF[nt][1], cF[nt][2], cF[nt][3],
                         e1h[ks*4+0], e1h[ks*4+1], e1h[ks*4+2], e1h[ks*4+3], Bp.z, Bp.w);
            }
        }

        {
            const float4* gpk = (const float4*)g_pk;
            const size_t jo = (size_t)(b*Ndim + j2)*OCdim;
            const int    ib = isA ? 0 : 64;
            #pragma unroll
            for (int nt = 0; nt < 8; nt++) {
                const int ch0 = nt*8 + 2*q;
                const int ksi = (nt >> 1)*4 + (nt & 1)*2;
                float2 e1a = unpack_sum(e1h[ksi],   e1l[ksi]);
                float2 e1b = unpack_sum(e1h[ksi+1], e1l[ksi+1]);
                float4 pj0 = gpk[jo + ch0];
                float4 pj1 = gpk[jo + ch0 + 1];
                float4 pi0 = s_nipk[ib + ch0];
                float4 pi1 = s_nipk[ib + ch0 + 1];
                float2 bf  = *(const float2*)&sbF1[ch0];
                float Q00 = silu_f(pj0.z + pi0.w + bf.x);
                float Q01 = silu_f(pj1.z + pi1.w + bf.y);
                float Q10 = silu_f(pi0.z + pj0.w + bf.x);
                float Q11 = silu_f(pi1.z + pj1.w + bf.y);
                float E00 = silu_f(pj0.x + pi0.y + e1a.x + Q00*silu_f(cF[nt][0]));
                float E01 = silu_f(pj1.x + pi1.y + e1a.y + Q01*silu_f(cF[nt][1]));
                float E10 = silu_f(pi0.x + pj0.y + e1b.x + Q10*silu_f(cF[nt][2]));
                float E11 = silu_f(pi1.x + pj1.y + e1b.y + Q11*silu_f(cF[nt][3]));
                *(float2*)&es[grp*68 + ch0] = make_float2((E00+E10)*emv, (E01+E11)*emv);
            }
        }
        __syncwarp();

        float u[8];
        #pragma unroll
        for (int pr = 0; pr < 8; pr++) u[pr] = beo1v;
        #pragma unroll
        for (int k4 = 0; k4 < 16; k4++) {
            float4 w4 = *(const float4*)&sw_eo1T[lane*68 + k4*4];
            #pragma unroll
            for (int pr = 0; pr < 8; pr++) {
                float4 e4 = *(const float4*)&es[pr*68 + k4*4];
                u[pr] += e4.x*w4.x + e4.y*w4.y + e4.z*w4.z + e4.w*w4.w;
            }
        }
        #pragma unroll
        for (int pr = 0; pr < 8; pr++) {
            float m = u[pr];
            #pragma unroll
            for (int o2 = 16; o2; o2 >>= 1) m += __shfl_xor_sync(0xffffffffu, m, o2);
            m *= (1.f/32.f);
            float dd = u[pr] - m;
            float var = dd*dd;
            #pragma unroll
            for (int o2 = 16; o2; o2 >>= 1) var += __shfl_xor_sync(0xffffffffu, var, o2);
            var *= (1.f/32.f);
            sv[pr*36 + lane] = silu_f(dd * rsqrtf(var + 1e-5f) * geov + beeov);
        }
        __syncwarp();

        #pragma unroll
        for (int h = 0; h < 2; h++) {
            const int pr  = h*4 + (lane >> 3);
            const int ch2 = lane & 7;
            float t = 0.f;
            #pragma unroll
            for (int k4 = 0; k4 < 8; k4++) {
                float4 vv = *(const float4*)&sv[pr*36 + k4*4];
                float4 w4 = *(const float4*)&sw_eo2T[ch2*36 + k4*4];
                t += vv.x*w4.x + vv.y*w4.y + vv.z*w4.z + vv.w*w4.w;
            }
            if (ch2 < KEdim && sact[pr]) {
                const int io = smi[pr], jo2 = smj[pr];
                float outv = (t + sbeo2[ch2]) * sem[pr];
                out_edge[((size_t)(b*Ndim + io)*Ndim + jo2)*KEdim + ch2] = outv;
                out_edge[((size_t)(b*Ndim + jo2)*Ndim + io)*KEdim + ch2] = outv;
            }
        }
        __syncwarp();
    }
}

// ---------------------------------------------------------------------------
extern "C" void kernel_launch(void* const* d_in, const int* in_sizes, int n_in,
                              void* d_out, int out_size)
{
    const float* node      = (const float*)d_in[0];
    const float* edge      = (const float*)d_in[1];
    const int*   block_id  = (const int*)d_in[2];
    const int*   vmask     = (const int*)d_in[3];
    const float* W_nt  = (const float*)d_in[4];
    const float* b_nt  = (const float*)d_in[5];
    const float* W_n1  = (const float*)d_in[6];
    const float* b_n1  = (const float*)d_in[7];
    const float* W_e1  = (const float*)d_in[8];
    const float* b_e1  = (const float*)d_in[9];
    const float* W_f1  = (const float*)d_in[10];
    const float* b_f1  = (const float*)d_in[11];
    const float* W_f2  = (const float*)d_in[12];
    const float* b_f2  = (const float*)d_in[13];
    const float* W_no1 = (const float*)d_in[14];
    const float* b_no1 = (const float*)d_in[15];
    const float* g_no  = (const float*)d_in[16];
    const float* be_no = (const float*)d_in[17];
    const float* W_no2 = (const float*)d_in[18];
    const float* b_no2 = (const float*)d_in[19];
    const float* W_eo1 = (const float*)d_in[20];
    const float* b_eo1 = (const float*)d_in[21];
    const float* g_eo  = (const float*)d_in[22];
    const float* be_eo = (const float*)d_in[23];
    const float* W_eo2 = (const float*)d_in[24];
    const float* b_eo2 = (const float*)d_in[25];

    float* out_node = (float*)d_out;                       // (B,N,KN)
    float* out_edge = (float*)d_out + Bdim*Ndim*KNdim;     // (B,N,N,KE)

    static int smem_set = 0;
    if (!smem_set) {
        cudaFuncSetAttribute(edge_kernel, cudaFuncAttributeMaxDynamicSharedMemorySize, SM_TOTAL);
        smem_set = 1;
    }

    node_kernel<<<Bdim*64, 256>>>(node, edge, block_id, vmask,
                                  W_nt, b_nt, W_n1, b_n1, W_f1,
                                  W_no1, b_no1, g_no, be_no, W_no2, b_no2,
                                  out_node);

    edge_kernel<<<Bdim*256, 256, SM_TOTAL>>>(edge, block_id, vmask,
                                   W_e1, b_e1, b_f1, W_f2, b_f2,
                                   W_eo1, b_eo1, g_eo, be_eo, W_eo2, b_eo2,
                                   out_edge);
}

// round 10
// speedup vs baseline: 1.3624x; 1.3624x over previous
#include <cuda_runtime.h>
#include <cuda_fp16.h>
#include <stdint.h>

#define Bdim 4
#define Ndim 512
#define NCdim 128
#define ECdim 32
#define OCdim 64
#define KNdim 10
#define KEdim 5
#define NIN 192   // 2*EC + NC
#define EWARPS 8
#define PX 12     // node-kernel transposed pitch

// packed per-node vectors: {n1, n2, q1, q2} per channel (float4-interleaved)
__device__ float g_pk[Bdim*Ndim*OCdim*4];
// x_in (0..31) ++ x_out (32..63) per node
__device__ float g_x[Bdim*Ndim*64];

__device__ __forceinline__ float silu_f(float x) {
    return __fdividef(x, 1.0f + __expf(-x));
}

__device__ __forceinline__ void mma16816(float& c0, float& c1, float& c2, float& c3,
                                         uint32_t a0, uint32_t a1, uint32_t a2, uint32_t a3,
                                         uint32_t b0, uint32_t b1) {
    asm volatile("mma.sync.aligned.m16n8k16.row.col.f32.f16.f16.f32 "
                 "{%0,%1,%2,%3},{%4,%5,%6,%7},{%8,%9},{%0,%1,%2,%3};\n"
                 : "+f"(c0), "+f"(c1), "+f"(c2), "+f"(c3)
                 : "r"(a0), "r"(a1), "r"(a2), "r"(a3), "r"(b0), "r"(b1));
}

__device__ __forceinline__ void split_h2(float x, float y, uint32_t& hi, uint32_t& lo) {
    __half hx = __float2half_rn(x), hy = __float2half_rn(y);
    __half lx = __float2half_rn(x - __half2float(hx));
    __half ly = __float2half_rn(y - __half2float(hy));
    __half2 h = __halves2half2(hx, hy), l = __halves2half2(lx, ly);
    hi = *(uint32_t*)&h;  lo = *(uint32_t*)&l;
}

__device__ __forceinline__ float2 unpack_sum(uint32_t h, uint32_t l) {
    float2 fh = __half22float2(*(__half2*)&h);
    float2 fl = __half22float2(*(__half2*)&l);
    return make_float2(fh.x + fl.x, fh.y + fl.y);
}

// ---------------------------------------------------------------------------
// Kernel A: masked-mean reduction. One block per (b,i), warp-striped over j
// (round-6 structure: max parallelism for the latency-bound gathers).
// ---------------------------------------------------------------------------
__global__ __launch_bounds__(256)
void reduce_kernel(const float* __restrict__ edge,
                   const int* __restrict__ block_id,
                   const int* __restrict__ vmask)
{
    const int bi = blockIdx.x;
    const int b  = bi / Ndim;
    const int i  = bi % Ndim;
    const int tid = threadIdx.x;

    __shared__ int           s_bid[Ndim];
    __shared__ unsigned char s_vm[Ndim];
    __shared__ float s_red[8][64];
    __shared__ float s_cnt[2][8];

    for (int k = tid; k < Ndim; k += 256) {
        s_bid[k] = block_id[b*Ndim + k];
        s_vm[k]  = (vmask[b*Ndim + k] != 0) ? 1 : 0;
    }
    __syncthreads();

    const int  bii  = s_bid[i];
    const bool nm_i = (bii >= 0);
    const bool vm_i = (s_vm[i] != 0);

    const int c  = tid & 31;
    const int jl = tid >> 5;

    float acc_in = 0.f, acc_out = 0.f, cnt_in = 0.f, cnt_out = 0.f;
    const float* erow = edge + ((size_t)(b*Ndim + i) * Ndim) * ECdim;
    const float* ecol = edge + ((size_t)b*Ndim) * Ndim * ECdim + (size_t)i*ECdim;

    for (int j = jl; j < Ndim; j += 8) {
        int  bj   = s_bid[j];
        bool nm_j = (bj >= 0);
        bool pv   = nm_i && nm_j;
        bool cij  = pv && ((bii > bj) || (bii == bj && !vm_i));
        bool cji  = pv && ((bj > bii) || (bj == bii && (s_vm[j] == 0)));
        if (cij) { acc_in  += erow[(size_t)j*ECdim + c];        cnt_in  += 1.f; }
        if (cji) { acc_out += ecol[(size_t)j*Ndim*ECdim + c];   cnt_out += 1.f; }
    }
    s_red[jl][c]      = acc_in;
    s_red[jl][c + 32] = acc_out;
    if (c == 0) { s_cnt[0][jl] = cnt_in; s_cnt[1][jl] = cnt_out; }
    __syncthreads();

    if (tid < 64) {
        float s = 0.f, cnt = 0.f;
        #pragma unroll
        for (int r2 = 0; r2 < 8; r2++) { s += s_red[r2][tid]; cnt += s_cnt[tid >> 5][r2]; }
        g_x[(size_t)(b*Ndim + i)*64 + tid] = s / fmaxf(cnt, 1.f);
    }
}

// ---------------------------------------------------------------------------
// Kernel B: batched node GEMVs, 8 nodes per block (weights amortized 8x).
// ---------------------------------------------------------------------------
__global__ __launch_bounds__(256)
void node_kernel(const float* __restrict__ node,
                 const int* __restrict__ block_id,
                 const float* __restrict__ W_nt, const float* __restrict__ b_nt,
                 const float* __restrict__ W_n1, const float* __restrict__ b_n1,
                 const float* __restrict__ W_f1,
                 const float* __restrict__ W_no1, const float* __restrict__ b_no1,
                 const float* __restrict__ g_no, const float* __restrict__ be_no,
                 const float* __restrict__ W_no2, const float* __restrict__ b_no2,
                 float* __restrict__ out_node)
{
    const int b  = blockIdx.x >> 6;
    const int i0 = (blockIdx.x & 63) * 8;
    const int tid = threadIdx.x;
    const int w    = tid >> 5;
    const int lane = tid & 31;

    __shared__ int s_bid8[8];
    __shared__ float s_x[NIN*PX];     // transposed inputs [k][node]
    __shared__ float s_hT[NCdim*PX];
    __shared__ float s_nT[NCdim*PX];
    __shared__ float s_tT[NCdim*PX];
    __shared__ float s_vT[NCdim*PX];

    if (tid < 8) s_bid8[tid] = block_id[b*Ndim + i0 + tid];
    __syncthreads();

    // ---- load inputs transposed: warp w = node i0+w ----
    {
        const int i = i0 + w;
        const bool nm_i = (s_bid8[w] >= 0);
        const size_t xo = (size_t)(b*Ndim + i)*64;
        s_x[lane*PX + w]      = g_x[xo + lane];
        s_x[(lane+32)*PX + w] = g_x[xo + 32 + lane];
        float msk = nm_i ? 1.f : 0.f;
        float4 nd = *(const float4*)&node[(size_t)(b*Ndim + i)*NCdim + lane*4];
        s_x[(64 + lane*4 + 0)*PX + w] = nd.x * msk;
        s_x[(64 + lane*4 + 1)*PX + w] = nd.y * msk;
        s_x[(64 + lane*4 + 2)*PX + w] = nd.z * msk;
        s_x[(64 + lane*4 + 3)*PX + w] = nd.w * msk;
    }
    __syncthreads();

    const int o = tid & 127;
    const int g = tid >> 7;       // nodes 4g..4g+3

    // ---- h = silu(x @ W_nt + b_nt) * nm ----
    {
        float bb = b_nt[o];
        float4 acc = make_float4(bb, bb, bb, bb);
        #pragma unroll 4
        for (int k = 0; k < NIN; k++) {
            float wv = W_nt[k*NCdim + o];
            float4 xi = *(const float4*)&s_x[k*PX + g*4];
            acc.x += wv*xi.x; acc.y += wv*xi.y; acc.z += wv*xi.z; acc.w += wv*xi.w;
        }
        #pragma unroll
        for (int c4 = 0; c4 < 4; c4++) {
            int nn = g*4 + c4;
            float v = (c4 == 0) ? acc.x : (c4 == 1) ? acc.y : (c4 == 2) ? acc.z : acc.w;
            s_hT[o*PX + nn] = (s_bid8[nn] >= 0) ? silu_f(v) : 0.f;
        }
    }
    __syncthreads();

    // ---- n = h @ W_n1 + b_n1 ; t = h @ W_no1 + b_no1 ----
    {
        float bn = b_n1[o], bt = b_no1[o];
        float4 an = make_float4(bn, bn, bn, bn);
        float4 at = make_float4(bt, bt, bt, bt);
        #pragma unroll 4
        for (int k = 0; k < NCdim; k++) {
            float wn = W_n1[k*NCdim + o];
            float wt = W_no1[k*NCdim + o];
            float4 xi = *(const float4*)&s_hT[k*PX + g*4];
            an.x += wn*xi.x; an.y += wn*xi.y; an.z += wn*xi.z; an.w += wn*xi.w;
            at.x += wt*xi.x; at.y += wt*xi.y; at.z += wt*xi.z; at.w += wt*xi.w;
        }
        s_nT[o*PX + g*4+0] = an.x; s_nT[o*PX + g*4+1] = an.y;
        s_nT[o*PX + g*4+2] = an.z; s_nT[o*PX + g*4+3] = an.w;
        s_tT[o*PX + g*4+0] = at.x; s_tT[o*PX + g*4+1] = at.y;
        s_tT[o*PX + g*4+2] = at.z; s_tT[o*PX + g*4+3] = at.w;
    }
    __syncthreads();

    // ---- q{1,2} = n{1,2} @ W_f1 ; write packed g_pk ----
    {
        const int oq = tid & 63;
        const int wh = (tid >> 6) & 1;
        float4 aq = make_float4(0.f, 0.f, 0.f, 0.f);
        #pragma unroll 4
        for (int k = 0; k < OCdim; k++) {
            float wq = W_f1[k*OCdim + oq];
            float4 xi = *(const float4*)&s_nT[(wh*OCdim + k)*PX + g*4];
            aq.x += wq*xi.x; aq.y += wq*xi.y; aq.z += wq*xi.z; aq.w += wq*xi.w;
        }
        #pragma unroll
        for (int c4 = 0; c4 < 4; c4++) {
            int nn = g*4 + c4;
            float qv = (c4 == 0) ? aq.x : (c4 == 1) ? aq.y : (c4 == 2) ? aq.z : aq.w;
            size_t base = ((size_t)(b*Ndim + i0 + nn)*OCdim + oq)*4;
            g_pk[base + wh]     = s_nT[(wh*OCdim + oq)*PX + nn];
            g_pk[base + 2 + wh] = qv;
        }
    }

    // ---- LayerNorm(t) + silu -> s_vT (warp w = node w) ----
    {
        float tv0 = s_tT[lane*PX + w];
        float tv1 = s_tT[(lane+32)*PX + w];
        float tv2 = s_tT[(lane+64)*PX + w];
        float tv3 = s_tT[(lane+96)*PX + w];
        float s = tv0 + tv1 + tv2 + tv3;
        #pragma unroll
        for (int o2 = 16; o2; o2 >>= 1) s += __shfl_xor_sync(0xffffffffu, s, o2);
        float mean = s * (1.f/NCdim);
        float d0 = tv0-mean, d1 = tv1-mean, d2 = tv2-mean, d3 = tv3-mean;
        float var = d0*d0 + d1*d1 + d2*d2 + d3*d3;
        #pragma unroll
        for (int o2 = 16; o2; o2 >>= 1) var += __shfl_xor_sync(0xffffffffu, var, o2);
        float rstd = rsqrtf(var * (1.f/NCdim) + 1e-5f);
        s_vT[lane*PX + w]      = silu_f(d0*rstd*g_no[lane]    + be_no[lane]);
        s_vT[(lane+32)*PX + w] = silu_f(d1*rstd*g_no[lane+32] + be_no[lane+32]);
        s_vT[(lane+64)*PX + w] = silu_f(d2*rstd*g_no[lane+64] + be_no[lane+64]);
        s_vT[(lane+96)*PX + w] = silu_f(d3*rstd*g_no[lane+96] + be_no[lane+96]);
    }
    __syncthreads();

    // ---- node logits ----
    if (lane < KNdim) {
        float a = b_no2[lane];
        #pragma unroll 4
        for (int k = 0; k < NCdim; k++)
            a += s_vT[k*PX + w] * W_no2[k*KNdim + lane];
        bool nm_i = (s_bid8[w] >= 0);
        out_node[(size_t)(b*Ndim + i0 + w)*KNdim + lane] = nm_i ? a : 0.f;
    }
}

// ---------------------------------------------------------------------------
// Kernel 2: edge work — byte-for-byte round-8 winner (uint2 B-fragments).
// ---------------------------------------------------------------------------
#define SM_KEY     0
#define SM_BE1B    2048
#define SM_BF2B    2304
#define SM_BF1     2560
#define SM_NIPK    2816
#define SM_BEO1    4864
#define SM_GEO     4992
#define SM_BEEO    5120
#define SM_BEO2    5248
#define SM_EO1T    5296
#define SM_EO2T    14000
#define SM_BE1H    15152
#define SM_BE1L    19248
#define SM_BF2H    23344
#define SM_BF2L    31536
#define SM_WARP    39728
#define SM_PERW    3456
#define SM_TOTAL   (SM_WARP + EWARPS*SM_PERW)   // 67376

__global__ __launch_bounds__(256, 2)
void edge_kernel(const float* __restrict__ edge,
                 const int* __restrict__ block_id,
                 const int* __restrict__ vmask,
                 const float* __restrict__ W_e1, const float* __restrict__ b_e1,
                 const float* __restrict__ b_f1,
                 const float* __restrict__ W_f2, const float* __restrict__ b_f2,
                 const float* __restrict__ W_eo1, const float* __restrict__ b_eo1,
                 const float* __restrict__ g_eo, const float* __restrict__ be_eo,
                 const float* __restrict__ W_eo2, const float* __restrict__ b_eo2,
                 float* __restrict__ out_edge)
{
    extern __shared__ char dsm[];
    const int b = blockIdx.x >> 8;
    const int r = blockIdx.x & 255;
    const int tid  = threadIdx.x;
    const int w    = tid >> 5;
    const int lane = tid & 31;
    const int grp  = lane >> 2;
    const int q    = lane & 3;

    int*    s_key  = (int*)(dsm + SM_KEY);
    float*  sbe1b  = (float*)(dsm + SM_BE1B);
    float*  sbf2b  = (float*)(dsm + SM_BF2B);
    float*  sbF1   = (float*)(dsm + SM_BF1);
    float4* s_nipk = (float4*)(dsm + SM_NIPK);
    float*  sbeo1  = (float*)(dsm + SM_BEO1);
    float*  sgeo   = (float*)(dsm + SM_GEO);
    float*  sbeeo  = (float*)(dsm + SM_BEEO);
    float*  sbeo2  = (float*)(dsm + SM_BEO2);
    float*  sw_eo1T = (float*)(dsm + SM_EO1T);
    float*  sw_eo2T = (float*)(dsm + SM_EO2T);
    uint2*  be1h   = (uint2*)(dsm + SM_BE1H);
    uint2*  be1l   = (uint2*)(dsm + SM_BE1L);
    uint2*  bf2h   = (uint2*)(dsm + SM_BF2H);
    uint2*  bf2l   = (uint2*)(dsm + SM_BF2L);

    char*  wbase = dsm + SM_WARP + w*SM_PERW;
    float* es    = (float*)wbase;
    float* sv    = (float*)(wbase + 2176);
    int*   smi   = (int*)(wbase + 3328);
    int*   smj   = smi + 8;
    float* sem   = (float*)(smi + 16);
    int*   sact  = smi + 24;

    const int i_a = r, i_b = Ndim - 1 - r;

    for (int k = tid; k < Ndim; k += 256)
        s_key[k] = block_id[b*Ndim + k]*2 + ((vmask[b*Ndim + k] != 0) ? 1 : 0);
    if (tid < 64)  sbe1b[tid] = b_e1[tid];
    if (tid >= 64 && tid < 128)  sbf2b[tid-64] = b_f2[tid-64];
    if (tid >= 128 && tid < 192) sbF1[tid-128] = b_f1[tid-128];
    if (tid >= 192 && tid < 224) sbeo1[tid-192] = b_eo1[tid-192];
    if (tid >= 224 && tid < 256) sgeo[tid-224] = g_eo[tid-224];
    if (tid < 32)  sbeeo[tid] = be_eo[tid];
    if (tid >= 32 && tid < 40) sbeo2[tid-32] = b_eo2[tid-32];
    if (tid >= 40 && tid < 168) {
        int k = tid - 40;
        int row = k >> 6, ch = k & 63;
        int irow = row ? i_b : i_a;
        s_nipk[k] = *(const float4*)&g_pk[((size_t)(b*Ndim + irow)*OCdim + ch)*4];
    }
    for (int k = tid; k < OCdim*32; k += 256) {
        int kk = k >> 5, c = k & 31;
        sw_eo1T[c*68 + kk] = W_eo1[k];
    }
    for (int k = tid; k < 8*36; k += 256) {
        int ch = k / 36, kk = k % 36;
        sw_eo2T[k] = (ch < KEdim && kk < ECdim) ? W_eo2[kk*KEdim + ch] : 0.f;
    }
    for (int e = tid; e < 512; e += 256) {
        int lane_ = e & 31, nt = (e >> 5) & 7, ks = e >> 8;
        int q_ = lane_ & 3, g_ = lane_ >> 2;
        int k0 = ks*16 + 2*q_;
        int n  = nt*8 + g_;
        uint32_t h0, l0, h1, l1;
        split_h2(W_e1[k0*OCdim + n],     W_e1[(k0+1)*OCdim + n], h0, l0);
        split_h2(W_e1[(k0+8)*OCdim + n], W_e1[(k0+9)*OCdim + n], h1, l1);
        be1h[e] = make_uint2(h0, h1);
        be1l[e] = make_uint2(l0, l1);
    }
    for (int e = tid; e < 1024; e += 256) {
        int lane_ = e & 31, nt = (e >> 5) & 7, ks = e >> 8;
        int q_ = lane_ & 3, g_ = lane_ >> 2;
        int k0 = ks*16 + 2*q_;
        int n  = nt*8 + g_;
        uint32_t h0, l0, h1, l1;
        split_h2(W_f2[k0*OCdim + n],     W_f2[(k0+1)*OCdim + n], h0, l0);
        split_h2(W_f2[(k0+8)*OCdim + n], W_f2[(k0+9)*OCdim + n], h1, l1);
        bf2h[e] = make_uint2(h0, h1);
        bf2l[e] = make_uint2(l0, l1);
    }
    __syncthreads();

    const float beo1v = sbeo1[lane];
    const float geov  = sgeo[lane];
    const float beeov = sbeeo[lane];

    const int npa   = Ndim - i_a;
    const int total = Ndim + 1;

    for (int base = w*8; base < total; base += EWARPS*8) {
        if (lane < 8) {
            int p = base + lane;
            int act = (p < total) ? 1 : 0;
            int pc = act ? p : 0;
            bool aA = pc < npa;
            int i2 = aA ? i_a : i_b;
            int j2 = aA ? (i_a + pc) : (i_b + (pc - npa));
            int ki = s_key[i2], kj = s_key[j2];
            int bi_ = ki >> 1, bj_ = kj >> 1;
            bool nm2 = (bi_ >= 0) && (bj_ >= 0);
            bool cij = (bi_ > bj_) || (bi_ == bj_ && !(ki & 1));
            bool cji = (bj_ > bi_) || (bj_ == bi_ && !(kj & 1));
            smi[lane] = i2; smj[lane] = j2;
            sem[lane] = (nm2 && (cij || cji)) ? 1.f : 0.f;
            sact[lane] = act;
        }
        __syncwarp();

        const int   i2  = smi[grp];
        const int   j2  = smj[grp];
        const float emv = sem[grp];
        const bool  isA = (i2 == i_a);

        uint32_t aEh[8], aEl[8];
        {
            const float* eij = edge + ((size_t)(b*Ndim + i2)*Ndim + j2)*ECdim;
            const float* eji = edge + ((size_t)(b*Ndim + j2)*Ndim + i2)*ECdim;
            #pragma unroll
            for (int ks = 0; ks < 2; ks++) {
                float2 v0 = *(const float2*)(eij + ks*16 + 2*q);
                float2 v1 = *(const float2*)(eji + ks*16 + 2*q);
                float2 v2 = *(const float2*)(eij + ks*16 + 8 + 2*q);
                float2 v3 = *(const float2*)(eji + ks*16 + 8 + 2*q);
                split_h2(v0.x*emv, v0.y*emv, aEh[ks*4+0], aEl[ks*4+0]);
                split_h2(v1.x*emv, v1.y*emv, aEh[ks*4+1], aEl[ks*4+1]);
                split_h2(v2.x*emv, v2.y*emv, aEh[ks*4+2], aEl[ks*4+2]);
                split_h2(v3.x*emv, v3.y*emv, aEh[ks*4+3], aEl[ks*4+3]);
            }
        }

        float cE[8][4];
        #pragma unroll
        for (int nt = 0; nt < 8; nt++) {
            float2 bb = *(const float2*)&sbe1b[nt*8 + 2*q];
            cE[nt][0] = bb.x; cE[nt][1] = bb.y; cE[nt][2] = bb.x; cE[nt][3] = bb.y;
        }
        #pragma unroll
        for (int ks = 0; ks < 2; ks++) {
            #pragma unroll
            for (int nt = 0; nt < 8; nt++) {
                uint2 Bh = be1h[(ks*8 + nt)*32 + lane];
                uint2 Bl = be1l[(ks*8 + nt)*32 + lane];
                mma16816(cE[nt][0], cE[nt][1], cE[nt][2], cE[nt][3],
                         aEh[ks*4+0], aEh[ks*4+1], aEh[ks*4+2], aEh[ks*4+3], Bh.x, Bh.y);
                mma16816(cE[nt][0], cE[nt][1], cE[nt][2], cE[nt][3],
                         aEl[ks*4+0], aEl[ks*4+1], aEl[ks*4+2], aEl[ks*4+3], Bh.x, Bh.y);
                mma16816(cE[nt][0], cE[nt][1], cE[nt][2], cE[nt][3],
                         aEh[ks*4+0], aEh[ks*4+1], aEh[ks*4+2], aEh[ks*4+3], Bl.x, Bl.y);
            }
        }

        uint32_t e1h[16], e1l[16];
        #pragma unroll
        for (int ks = 0; ks < 4; ks++) {
            split_h2(cE[2*ks][0],   cE[2*ks][1],   e1h[ks*4+0], e1l[ks*4+0]);
            split_h2(cE[2*ks][2],   cE[2*ks][3],   e1h[ks*4+1], e1l[ks*4+1]);
            split_h2(cE[2*ks+1][0], cE[2*ks+1][1], e1h[ks*4+2], e1l[ks*4+2]);
            split_h2(cE[2*ks+1][2], cE[2*ks+1][3], e1h[ks*4+3], e1l[ks*4+3]);
        }

        float cF[8][4];
        #pragma unroll
        for (int nt = 0; nt < 8; nt++) {
            float2 bb = *(const float2*)&sbf2b[nt*8 + 2*q];
            cF[nt][0] = bb.x; cF[nt][1] = bb.y; cF[nt][2] = bb.x; cF[nt][3] = bb.y;
        }
        #pragma unroll
        for (int ks = 0; ks < 4; ks++) {
            #pragma unroll
            for (int nt = 0; nt < 8; nt++) {
                uint2 Bh = bf2h[(ks*8 + nt)*32 + lane];
                uint2 Bl = bf2l[(ks*8 + nt)*32 + lane];
                mma16816(cF[nt][0], cF[nt][1], cF[nt][2], cF[nt][3],
                         e1h[ks*4+0], e1h[ks*4+1], e1h[ks*4+2], e1h[ks*4+3], Bh.x, Bh.y);
                mma16816(cF[nt][0], cF[nt][1], cF[nt][2], cF[nt][3],
                         e1l[ks*4+0], e1l[ks*4+1], e1l[ks*4+2], e1l[ks*4+3], Bh.x, Bh.y);
                mma16816(cF[nt][0], cF[nt][1], cF[nt][2], cF[nt][3],
                         e1h[ks*4+0], e1h[ks*4+1], e1h[ks*4+2], e1h[ks*4+3], Bl.x, Bl.y);
            }
        }

        {
            const float4* gpk = (const float4*)g_pk;
            const size_t jo = (size_t)(b*Ndim + j2)*OCdim;
            const int    ib = isA ? 0 : 64;
            #pragma unroll
            for (int nt = 0; nt < 8; nt++) {
                const int ch0 = nt*8 + 2*q;
                const int ksi = (nt >> 1)*4 + (nt & 1)*2;
                float2 e1a = unpack_sum(e1h[ksi],   e1l[ksi]);
                float2 e1b = unpack_sum(e1h[ksi+1], e1l[ksi+1]);
                float4 pj0 = gpk[jo + ch0];
                float4 pj1 = gpk[jo + ch0 + 1];
                float4 pi0 = s_nipk[ib + ch0];
                float4 pi1 = s_nipk[ib + ch0 + 1];
                float2 bf  = *(const float2*)&sbF1[ch0];
                float Q00 = silu_f(pj0.z + pi0.w + bf.x);
                float Q01 = silu_f(pj1.z + pi1.w + bf.y);
                float Q10 = silu_f(pi0.z + pj0.w + bf.x);
                float Q11 = silu_f(pi1.z + pj1.w + bf.y);
                float E00 = silu_f(pj0.x + pi0.y + e1a.x + Q00*silu_f(cF[nt][0]));
                float E01 = silu_f(pj1.x + pi1.y + e1a.y + Q01*silu_f(cF[nt][1]));
                float E10 = silu_f(pi0.x + pj0.y + e1b.x + Q10*silu_f(cF[nt][2]));
                float E11 = silu_f(pi1.x + pj1.y + e1b.y + Q11*silu_f(cF[nt][3]));
                *(float2*)&es[grp*68 + ch0] = make_float2((E00+E10)*emv, (E01+E11)*emv);
            }
        }
        __syncwarp();

        float u[8];
        #pragma unroll
        for (int pr = 0; pr < 8; pr++) u[pr] = beo1v;
        #pragma unroll
        for (int k4 = 0; k4 < 16; k4++) {
            float4 w4 = *(const float4*)&sw_eo1T[lane*68 + k4*4];
            #pragma unroll
            for (int pr = 0; pr < 8; pr++) {
                float4 e4 = *(const float4*)&es[pr*68 + k4*4];
                u[pr] += e4.x*w4.x + e4.y*w4.y + e4.z*w4.z + e4.w*w4.w;
            }
        }
        #pragma unroll
        for (int pr = 0; pr < 8; pr++) {
            float m = u[pr];
            #pragma unroll
            for (int o2 = 16; o2; o2 >>= 1) m += __shfl_xor_sync(0xffffffffu, m, o2);
            m *= (1.f/32.f);
            float dd = u[pr] - m;
            float var = dd*dd;
            #pragma unroll
            for (int o2 = 16; o2; o2 >>= 1) var += __shfl_xor_sync(0xffffffffu, var, o2);
            var *= (1.f/32.f);
            sv[pr*36 + lane] = silu_f(dd * rsqrtf(var + 1e-5f) * geov + beeov);
        }
        __syncwarp();

        #pragma unroll
        for (int h = 0; h < 2; h++) {
            const int pr  = h*4 + (lane >> 3);
            const int ch2 = lane & 7;
            float t = 0.f;
            #pragma unroll
            for (int k4 = 0; k4 < 8; k4++) {
                float4 vv = *(const float4*)&sv[pr*36 + k4*4];
                float4 w4 = *(const float4*)&sw_eo2T[ch2*36 + k4*4];
                t += vv.x*w4.x + vv.y*w4.y + vv.z*w4.z + vv.w*w4.w;
            }
            if (ch2 < KEdim && sact[pr]) {
                const int io = smi[pr], jo2 = smj[pr];
                float outv = (t + sbeo2[ch2]) * sem[pr];
                out_edge[((size_t)(b*Ndim + io)*Ndim + jo2)*KEdim + ch2] = outv;
                out_edge[((size_t)(b*Ndim + jo2)*Ndim + io)*KEdim + ch2] = outv;
            }
        }
        __syncwarp();
    }
}

// ---------------------------------------------------------------------------
extern "C" void kernel_launch(void* const* d_in, const int* in_sizes, int n_in,
                              void* d_out, int out_size)
{
    const float* node      = (const float*)d_in[0];
    const float* edge      = (const float*)d_in[1];
    const int*   block_id  = (const int*)d_in[2];
    const int*   vmask     = (const int*)d_in[3];
    const float* W_nt  = (const float*)d_in[4];
    const float* b_nt  = (const float*)d_in[5];
    const float* W_n1  = (const float*)d_in[6];
    const float* b_n1  = (const float*)d_in[7];
    const float* W_e1  = (const float*)d_in[8];
    const float* b_e1  = (const float*)d_in[9];
    const float* W_f1  = (const float*)d_in[10];
    const float* b_f1  = (const float*)d_in[11];
    const float* W_f2  = (const float*)d_in[12];
    const float* b_f2  = (const float*)d_in[13];
    const float* W_no1 = (const float*)d_in[14];
    const float* b_no1 = (const float*)d_in[15];
    const float* g_no  = (const float*)d_in[16];
    const float* be_no = (const float*)d_in[17];
    const float* W_no2 = (const float*)d_in[18];
    const float* b_no2 = (const float*)d_in[19];
    const float* W_eo1 = (const float*)d_in[20];
    const float* b_eo1 = (const float*)d_in[21];
    const float* g_eo  = (const float*)d_in[22];
    const float* be_eo = (const float*)d_in[23];
    const float* W_eo2 = (const float*)d_in[24];
    const float* b_eo2 = (const float*)d_in[25];

    float* out_node = (float*)d_out;                       // (B,N,KN)
    float* out_edge = (float*)d_out + Bdim*Ndim*KNdim;     // (B,N,N,KE)

    static int smem_set = 0;
    if (!smem_set) {
        cudaFuncSetAttribute(edge_kernel, cudaFuncAttributeMaxDynamicSharedMemorySize, SM_TOTAL);
        smem_set = 1;
    }

    reduce_kernel<<<Bdim*Ndim, 256>>>(edge, block_id, vmask);

    node_kernel<<<Bdim*64, 256>>>(node, block_id,
                                  W_nt, b_nt, W_n1, b_n1, W_f1,
                                  W_no1, b_no1, g_no, be_no, W_no2, b_no2,
                                  out_node);

    edge_kernel<<<Bdim*256, 256, SM_TOTAL>>>(edge, block_id, vmask,
                                   W_e1, b_e1, b_f1, W_f2, b_f2,
                                   W_eo1, b_eo1, g_eo, be_eo, W_eo2, b_eo2,
                                   out_edge);
}

// round 11
// speedup vs baseline: 1.6835x; 1.2357x over previous
#include <cuda_runtime.h>
#include <cuda_fp16.h>
#include <stdint.h>

#define Bdim 4
#define Ndim 512
#define NCdim 128
#define ECdim 32
#define OCdim 64
#define KNdim 10
#define KEdim 5
#define NIN 192   // 2*EC + NC
#define EWARPS 8
#define PX 12     // node-kernel transposed pitch

// packed per-node vectors: {n1, n2, q1, q2} per channel (float4-interleaved)
__device__ float g_pk[Bdim*Ndim*OCdim*4];
// x_in (0..31) ++ x_out (32..63) per node
__device__ float g_x[Bdim*Ndim*64];

__device__ __forceinline__ float silu_f(float x) {
    return __fdividef(x, 1.0f + __expf(-x));
}

__device__ __forceinline__ void mma16816(float& c0, float& c1, float& c2, float& c3,
                                         uint32_t a0, uint32_t a1, uint32_t a2, uint32_t a3,
                                         uint32_t b0, uint32_t b1) {
    asm volatile("mma.sync.aligned.m16n8k16.row.col.f32.f16.f16.f32 "
                 "{%0,%1,%2,%3},{%4,%5,%6,%7},{%8,%9},{%0,%1,%2,%3};\n"
                 : "+f"(c0), "+f"(c1), "+f"(c2), "+f"(c3)
                 : "r"(a0), "r"(a1), "r"(a2), "r"(a3), "r"(b0), "r"(b1));
}

__device__ __forceinline__ void split_h2(float x, float y, uint32_t& hi, uint32_t& lo) {
    __half hx = __float2half_rn(x), hy = __float2half_rn(y);
    __half lx = __float2half_rn(x - __half2float(hx));
    __half ly = __float2half_rn(y - __half2float(hy));
    __half2 h = __halves2half2(hx, hy), l = __halves2half2(lx, ly);
    hi = *(uint32_t*)&h;  lo = *(uint32_t*)&l;
}

__device__ __forceinline__ float2 unpack_sum(uint32_t h, uint32_t l) {
    float2 fh = __half22float2(*(__half2*)&h);
    float2 fl = __half22float2(*(__half2*)&l);
    return make_float2(fh.x + fl.x, fh.y + fl.y);
}

// ---------------------------------------------------------------------------
// Kernel A: masked-mean reduction (round-10 winner, unchanged).
// ---------------------------------------------------------------------------
__global__ __launch_bounds__(256)
void reduce_kernel(const float* __restrict__ edge,
                   const int* __restrict__ block_id,
                   const int* __restrict__ vmask)
{
    const int bi = blockIdx.x;
    const int b  = bi / Ndim;
    const int i  = bi % Ndim;
    const int tid = threadIdx.x;

    __shared__ int           s_bid[Ndim];
    __shared__ unsigned char s_vm[Ndim];
    __shared__ float s_red[8][64];
    __shared__ float s_cnt[2][8];

    for (int k = tid; k < Ndim; k += 256) {
        s_bid[k] = block_id[b*Ndim + k];
        s_vm[k]  = (vmask[b*Ndim + k] != 0) ? 1 : 0;
    }
    __syncthreads();

    const int  bii  = s_bid[i];
    const bool nm_i = (bii >= 0);
    const bool vm_i = (s_vm[i] != 0);

    const int c  = tid & 31;
    const int jl = tid >> 5;

    float acc_in = 0.f, acc_out = 0.f, cnt_in = 0.f, cnt_out = 0.f;
    const float* erow = edge + ((size_t)(b*Ndim + i) * Ndim) * ECdim;
    const float* ecol = edge + ((size_t)b*Ndim) * Ndim * ECdim + (size_t)i*ECdim;

    for (int j = jl; j < Ndim; j += 8) {
        int  bj   = s_bid[j];
        bool nm_j = (bj >= 0);
        bool pv   = nm_i && nm_j;
        bool cij  = pv && ((bii > bj) || (bii == bj && !vm_i));
        bool cji  = pv && ((bj > bii) || (bj == bii && (s_vm[j] == 0)));
        if (cij) { acc_in  += erow[(size_t)j*ECdim + c];        cnt_in  += 1.f; }
        if (cji) { acc_out += ecol[(size_t)j*Ndim*ECdim + c];   cnt_out += 1.f; }
    }
    s_red[jl][c]      = acc_in;
    s_red[jl][c + 32] = acc_out;
    if (c == 0) { s_cnt[0][jl] = cnt_in; s_cnt[1][jl] = cnt_out; }
    __syncthreads();

    if (tid < 64) {
        float s = 0.f, cnt = 0.f;
        #pragma unroll
        for (int r2 = 0; r2 < 8; r2++) { s += s_red[r2][tid]; cnt += s_cnt[tid >> 5][r2]; }
        g_x[(size_t)(b*Ndim + i)*64 + tid] = s / fmaxf(cnt, 1.f);
    }
}

// ---------------------------------------------------------------------------
// Kernel B: batched node GEMVs (round-10 winner, unchanged).
// ---------------------------------------------------------------------------
__global__ __launch_bounds__(256)
void node_kernel(const float* __restrict__ node,
                 const int* __restrict__ block_id,
                 const float* __restrict__ W_nt, const float* __restrict__ b_nt,
                 const float* __restrict__ W_n1, const float* __restrict__ b_n1,
                 const float* __restrict__ W_f1,
                 const float* __restrict__ W_no1, const float* __restrict__ b_no1,
                 const float* __restrict__ g_no, const float* __restrict__ be_no,
                 const float* __restrict__ W_no2, const float* __restrict__ b_no2,
                 float* __restrict__ out_node)
{
    const int b  = blockIdx.x >> 6;
    const int i0 = (blockIdx.x & 63) * 8;
    const int tid = threadIdx.x;
    const int w    = tid >> 5;
    const int lane = tid & 31;

    __shared__ int s_bid8[8];
    __shared__ float s_x[NIN*PX];
    __shared__ float s_hT[NCdim*PX];
    __shared__ float s_nT[NCdim*PX];
    __shared__ float s_tT[NCdim*PX];
    __shared__ float s_vT[NCdim*PX];

    if (tid < 8) s_bid8[tid] = block_id[b*Ndim + i0 + tid];
    __syncthreads();

    {
        const int i = i0 + w;
        const bool nm_i = (s_bid8[w] >= 0);
        const size_t xo = (size_t)(b*Ndim + i)*64;
        s_x[lane*PX + w]      = g_x[xo + lane];
        s_x[(lane+32)*PX + w] = g_x[xo + 32 + lane];
        float msk = nm_i ? 1.f : 0.f;
        float4 nd = *(const float4*)&node[(size_t)(b*Ndim + i)*NCdim + lane*4];
        s_x[(64 + lane*4 + 0)*PX + w] = nd.x * msk;
        s_x[(64 + lane*4 + 1)*PX + w] = nd.y * msk;
        s_x[(64 + lane*4 + 2)*PX + w] = nd.z * msk;
        s_x[(64 + lane*4 + 3)*PX + w] = nd.w * msk;
    }
    __syncthreads();

    const int o = tid & 127;
    const int g = tid >> 7;

    {
        float bb = b_nt[o];
        float4 acc = make_float4(bb, bb, bb, bb);
        #pragma unroll 4
        for (int k = 0; k < NIN; k++) {
            float wv = W_nt[k*NCdim + o];
            float4 xi = *(const float4*)&s_x[k*PX + g*4];
            acc.x += wv*xi.x; acc.y += wv*xi.y; acc.z += wv*xi.z; acc.w += wv*xi.w;
        }
        #pragma unroll
        for (int c4 = 0; c4 < 4; c4++) {
            int nn = g*4 + c4;
            float v = (c4 == 0) ? acc.x : (c4 == 1) ? acc.y : (c4 == 2) ? acc.z : acc.w;
            s_hT[o*PX + nn] = (s_bid8[nn] >= 0) ? silu_f(v) : 0.f;
        }
    }
    __syncthreads();

    {
        float bn = b_n1[o], bt = b_no1[o];
        float4 an = make_float4(bn, bn, bn, bn);
        float4 at = make_float4(bt, bt, bt, bt);
        #pragma unroll 4
        for (int k = 0; k < NCdim; k++) {
            float wn = W_n1[k*NCdim + o];
            float wt = W_no1[k*NCdim + o];
            float4 xi = *(const float4*)&s_hT[k*PX + g*4];
            an.x += wn*xi.x; an.y += wn*xi.y; an.z += wn*xi.z; an.w += wn*xi.w;
            at.x += wt*xi.x; at.y += wt*xi.y; at.z += wt*xi.z; at.w += wt*xi.w;
        }
        s_nT[o*PX + g*4+0] = an.x; s_nT[o*PX + g*4+1] = an.y;
        s_nT[o*PX + g*4+2] = an.z; s_nT[o*PX + g*4+3] = an.w;
        s_tT[o*PX + g*4+0] = at.x; s_tT[o*PX + g*4+1] = at.y;
        s_tT[o*PX + g*4+2] = at.z; s_tT[o*PX + g*4+3] = at.w;
    }
    __syncthreads();

    {
        const int oq = tid & 63;
        const int wh = (tid >> 6) & 1;
        float4 aq = make_float4(0.f, 0.f, 0.f, 0.f);
        #pragma unroll 4
        for (int k = 0; k < OCdim; k++) {
            float wq = W_f1[k*OCdim + oq];
            float4 xi = *(const float4*)&s_nT[(wh*OCdim + k)*PX + g*4];
            aq.x += wq*xi.x; aq.y += wq*xi.y; aq.z += wq*xi.z; aq.w += wq*xi.w;
        }
        #pragma unroll
        for (int c4 = 0; c4 < 4; c4++) {
            int nn = g*4 + c4;
            float qv = (c4 == 0) ? aq.x : (c4 == 1) ? aq.y : (c4 == 2) ? aq.z : aq.w;
            size_t base = ((size_t)(b*Ndim + i0 + nn)*OCdim + oq)*4;
            g_pk[base + wh]     = s_nT[(wh*OCdim + oq)*PX + nn];
            g_pk[base + 2 + wh] = qv;
        }
    }

    {
        float tv0 = s_tT[lane*PX + w];
        float tv1 = s_tT[(lane+32)*PX + w];
        float tv2 = s_tT[(lane+64)*PX + w];
        float tv3 = s_tT[(lane+96)*PX + w];
        float s = tv0 + tv1 + tv2 + tv3;
        #pragma unroll
        for (int o2 = 16; o2; o2 >>= 1) s += __shfl_xor_sync(0xffffffffu, s, o2);
        float mean = s * (1.f/NCdim);
        float d0 = tv0-mean, d1 = tv1-mean, d2 = tv2-mean, d3 = tv3-mean;
        float var = d0*d0 + d1*d1 + d2*d2 + d3*d3;
        #pragma unroll
        for (int o2 = 16; o2; o2 >>= 1) var += __shfl_xor_sync(0xffffffffu, var, o2);
        float rstd = rsqrtf(var * (1.f/NCdim) + 1e-5f);
        s_vT[lane*PX + w]      = silu_f(d0*rstd*g_no[lane]    + be_no[lane]);
        s_vT[(lane+32)*PX + w] = silu_f(d1*rstd*g_no[lane+32] + be_no[lane+32]);
        s_vT[(lane+64)*PX + w] = silu_f(d2*rstd*g_no[lane+64] + be_no[lane+64]);
        s_vT[(lane+96)*PX + w] = silu_f(d3*rstd*g_no[lane+96] + be_no[lane+96]);
    }
    __syncthreads();

    if (lane < KNdim) {
        float a = b_no2[lane];
        #pragma unroll 4
        for (int k = 0; k < NCdim; k++)
            a += s_vT[k*PX + w] * W_no2[k*KNdim + lane];
        bool nm_i = (s_bid8[w] >= 0);
        out_node[(size_t)(b*Ndim + i0 + w)*KNdim + lane] = nm_i ? a : 0.f;
    }
}

// ---------------------------------------------------------------------------
// Kernel 2: edge work. e1, f2 AND eo1 on tensor cores (compensated fp16 MMA).
// eo1's A-fragments come straight from the masked E-values in registers; the
// (E_ij + E_ji) symmetrization is c0+c2 in the C-fragment. LayerNorm reduces
// within a quad (thread holds 8 channels of one pair).
// ---------------------------------------------------------------------------
#define SM_KEY     0         // 512 int
#define SM_BE1B    2048
#define SM_BF2B    2304
#define SM_BF1     2560
#define SM_NIPK    2816      // 128 float4
#define SM_BEO1    4864
#define SM_GEO     4992
#define SM_BEEO    5120
#define SM_BEO2    5248      // 8 f + pad
#define SM_EO2T    5296      // 8*36 f = 1152
#define SM_BE1H    6448      // 512 uint2
#define SM_BE1L    10544
#define SM_BF2H    14640     // 1024 uint2
#define SM_BF2L    22832
#define SM_BO1H    31024     // 512 uint2 (W_eo1 B-frags hi)
#define SM_BO1L    35120     // 512 uint2 (lo)
#define SM_WARP    39216
#define SM_PERW    1280      // sv [8][36]f 1152 | meta 128
#define SM_TOTAL   (SM_WARP + EWARPS*SM_PERW)   // 49456

__global__ __launch_bounds__(256, 2)
void edge_kernel(const float* __restrict__ edge,
                 const int* __restrict__ block_id,
                 const int* __restrict__ vmask,
                 const float* __restrict__ W_e1, const float* __restrict__ b_e1,
                 const float* __restrict__ b_f1,
                 const float* __restrict__ W_f2, const float* __restrict__ b_f2,
                 const float* __restrict__ W_eo1, const float* __restrict__ b_eo1,
                 const float* __restrict__ g_eo, const float* __restrict__ be_eo,
                 const float* __restrict__ W_eo2, const float* __restrict__ b_eo2,
                 float* __restrict__ out_edge)
{
    extern __shared__ char dsm[];
    const int b = blockIdx.x >> 8;
    const int r = blockIdx.x & 255;
    const int tid  = threadIdx.x;
    const int w    = tid >> 5;
    const int lane = tid & 31;
    const int grp  = lane >> 2;
    const int q    = lane & 3;

    int*    s_key  = (int*)(dsm + SM_KEY);
    float*  sbe1b  = (float*)(dsm + SM_BE1B);
    float*  sbf2b  = (float*)(dsm + SM_BF2B);
    float*  sbF1   = (float*)(dsm + SM_BF1);
    float4* s_nipk = (float4*)(dsm + SM_NIPK);
    float*  sbeo1  = (float*)(dsm + SM_BEO1);
    float*  sgeo   = (float*)(dsm + SM_GEO);
    float*  sbeeo  = (float*)(dsm + SM_BEEO);
    float*  sbeo2  = (float*)(dsm + SM_BEO2);
    float*  sw_eo2T = (float*)(dsm + SM_EO2T);
    uint2*  be1h   = (uint2*)(dsm + SM_BE1H);
    uint2*  be1l   = (uint2*)(dsm + SM_BE1L);
    uint2*  bf2h   = (uint2*)(dsm + SM_BF2H);
    uint2*  bf2l   = (uint2*)(dsm + SM_BF2L);
    uint2*  bo1h   = (uint2*)(dsm + SM_BO1H);
    uint2*  bo1l   = (uint2*)(dsm + SM_BO1L);

    char*  wbase = dsm + SM_WARP + w*SM_PERW;
    float* sv    = (float*)wbase;            // [8][36]
    int*   smi   = (int*)(wbase + 1152);
    int*   smj   = smi + 8;
    float* sem   = (float*)(smi + 16);
    int*   sact  = smi + 24;

    const int i_a = r, i_b = Ndim - 1 - r;

    for (int k = tid; k < Ndim; k += 256)
        s_key[k] = block_id[b*Ndim + k]*2 + ((vmask[b*Ndim + k] != 0) ? 1 : 0);
    if (tid < 64)  sbe1b[tid] = b_e1[tid];
    if (tid >= 64 && tid < 128)  sbf2b[tid-64] = b_f2[tid-64];
    if (tid >= 128 && tid < 192) sbF1[tid-128] = b_f1[tid-128];
    if (tid >= 192 && tid < 224) sbeo1[tid-192] = b_eo1[tid-192];
    if (tid >= 224 && tid < 256) sgeo[tid-224] = g_eo[tid-224];
    if (tid < 32)  sbeeo[tid] = be_eo[tid];
    if (tid >= 32 && tid < 40) sbeo2[tid-32] = b_eo2[tid-32];
    if (tid >= 40 && tid < 168) {
        int k = tid - 40;
        int row = k >> 6, ch = k & 63;
        int irow = row ? i_b : i_a;
        s_nipk[k] = *(const float4*)&g_pk[((size_t)(b*Ndim + irow)*OCdim + ch)*4];
    }
    for (int k = tid; k < 8*36; k += 256) {
        int ch = k / 36, kk = k % 36;
        sw_eo2T[k] = (ch < KEdim && kk < ECdim) ? W_eo2[kk*KEdim + ch] : 0.f;
    }
    // B-fragments: W_e1 (k=32, n=64: 2 ks x 8 nt)
    for (int e = tid; e < 512; e += 256) {
        int lane_ = e & 31, nt = (e >> 5) & 7, ks = e >> 8;
        int q_ = lane_ & 3, g_ = lane_ >> 2;
        int k0 = ks*16 + 2*q_;
        int n  = nt*8 + g_;
        uint32_t h0, l0, h1, l1;
        split_h2(W_e1[k0*OCdim + n],     W_e1[(k0+1)*OCdim + n], h0, l0);
        split_h2(W_e1[(k0+8)*OCdim + n], W_e1[(k0+9)*OCdim + n], h1, l1);
        be1h[e] = make_uint2(h0, h1);
        be1l[e] = make_uint2(l0, l1);
    }
    // W_f2 (k=64, n=64: 4 ks x 8 nt)
    for (int e = tid; e < 1024; e += 256) {
        int lane_ = e & 31, nt = (e >> 5) & 7, ks = e >> 8;
        int q_ = lane_ & 3, g_ = lane_ >> 2;
        int k0 = ks*16 + 2*q_;
        int n  = nt*8 + g_;
        uint32_t h0, l0, h1, l1;
        split_h2(W_f2[k0*OCdim + n],     W_f2[(k0+1)*OCdim + n], h0, l0);
        split_h2(W_f2[(k0+8)*OCdim + n], W_f2[(k0+9)*OCdim + n], h1, l1);
        bf2h[e] = make_uint2(h0, h1);
        bf2l[e] = make_uint2(l0, l1);
    }
    // W_eo1 (k=64, n=32: 4 ks x 4 nt) — index [(ks*4 + nt)*32 + lane]
    for (int e = tid; e < 512; e += 256) {
        int lane_ = e & 31, nt = (e >> 5) & 3, ks = e >> 7;
        int q_ = lane_ & 3, g_ = lane_ >> 2;
        int k0 = ks*16 + 2*q_;
        int n  = nt*8 + g_;
        uint32_t h0, l0, h1, l1;
        split_h2(W_eo1[k0*32 + n],     W_eo1[(k0+1)*32 + n], h0, l0);
        split_h2(W_eo1[(k0+8)*32 + n], W_eo1[(k0+9)*32 + n], h1, l1);
        bo1h[e] = make_uint2(h0, h1);
        bo1l[e] = make_uint2(l0, l1);
    }
    __syncthreads();

    const int npa   = Ndim - i_a;
    const int total = Ndim + 1;

    for (int base = w*8; base < total; base += EWARPS*8) {
        if (lane < 8) {
            int p = base + lane;
            int act = (p < total) ? 1 : 0;
            int pc = act ? p : 0;
            bool aA = pc < npa;
            int i2 = aA ? i_a : i_b;
            int j2 = aA ? (i_a + pc) : (i_b + (pc - npa));
            int ki = s_key[i2], kj = s_key[j2];
            int bi_ = ki >> 1, bj_ = kj >> 1;
            bool nm2 = (bi_ >= 0) && (bj_ >= 0);
            bool cij = (bi_ > bj_) || (bi_ == bj_ && !(ki & 1));
            bool cji = (bj_ > bi_) || (bj_ == bi_ && !(kj & 1));
            smi[lane] = i2; smj[lane] = j2;
            sem[lane] = (nm2 && (cij || cji)) ? 1.f : 0.f;
            sact[lane] = act;
        }
        __syncwarp();

        const int   i2  = smi[grp];
        const int   j2  = smj[grp];
        const float emv = sem[grp];
        const bool  isA = (i2 == i_a);

        // ---- edge rows -> A-fragments (registers) ----
        uint32_t aEh[8], aEl[8];
        {
            const float* eij = edge + ((size_t)(b*Ndim + i2)*Ndim + j2)*ECdim;
            const float* eji = edge + ((size_t)(b*Ndim + j2)*Ndim + i2)*ECdim;
            #pragma unroll
            for (int ks = 0; ks < 2; ks++) {
                float2 v0 = *(const float2*)(eij + ks*16 + 2*q);
                float2 v1 = *(const float2*)(eji + ks*16 + 2*q);
                float2 v2 = *(const float2*)(eij + ks*16 + 8 + 2*q);
                float2 v3 = *(const float2*)(eji + ks*16 + 8 + 2*q);
                split_h2(v0.x*emv, v0.y*emv, aEh[ks*4+0], aEl[ks*4+0]);
                split_h2(v1.x*emv, v1.y*emv, aEh[ks*4+1], aEl[ks*4+1]);
                split_h2(v2.x*emv, v2.y*emv, aEh[ks*4+2], aEl[ks*4+2]);
                split_h2(v3.x*emv, v3.y*emv, aEh[ks*4+3], aEl[ks*4+3]);
            }
        }

        // ---- e1 = er @ W_e1 + b_e1 ----
        float cE[8][4];
        #pragma unroll
        for (int nt = 0; nt < 8; nt++) {
            float2 bb = *(const float2*)&sbe1b[nt*8 + 2*q];
            cE[nt][0] = bb.x; cE[nt][1] = bb.y; cE[nt][2] = bb.x; cE[nt][3] = bb.y;
        }
        #pragma unroll
        for (int ks = 0; ks < 2; ks++) {
            #pragma unroll
            for (int nt = 0; nt < 8; nt++) {
                uint2 Bh = be1h[(ks*8 + nt)*32 + lane];
                uint2 Bl = be1l[(ks*8 + nt)*32 + lane];
                mma16816(cE[nt][0], cE[nt][1], cE[nt][2], cE[nt][3],
                         aEh[ks*4+0], aEh[ks*4+1], aEh[ks*4+2], aEh[ks*4+3], Bh.x, Bh.y);
                mma16816(cE[nt][0], cE[nt][1], cE[nt][2], cE[nt][3],
                         aEl[ks*4+0], aEl[ks*4+1], aEl[ks*4+2], aEl[ks*4+3], Bh.x, Bh.y);
                mma16816(cE[nt][0], cE[nt][1], cE[nt][2], cE[nt][3],
                         aEh[ks*4+0], aEh[ks*4+1], aEh[ks*4+2], aEh[ks*4+3], Bl.x, Bl.y);
            }
        }

        // ---- thread-local repack: e1 C-frag -> f2 A-frags ----
        uint32_t e1h[16], e1l[16];
        #pragma unroll
        for (int ks = 0; ks < 4; ks++) {
            split_h2(cE[2*ks][0],   cE[2*ks][1],   e1h[ks*4+0], e1l[ks*4+0]);
            split_h2(cE[2*ks][2],   cE[2*ks][3],   e1h[ks*4+1], e1l[ks*4+1]);
            split_h2(cE[2*ks+1][0], cE[2*ks+1][1], e1h[ks*4+2], e1l[ks*4+2]);
            split_h2(cE[2*ks+1][2], cE[2*ks+1][3], e1h[ks*4+3], e1l[ks*4+3]);
        }

        // ---- f2raw = e1 @ W_f2 + b_f2 ----
        float cF[8][4];
        #pragma unroll
        for (int nt = 0; nt < 8; nt++) {
            float2 bb = *(const float2*)&sbf2b[nt*8 + 2*q];
            cF[nt][0] = bb.x; cF[nt][1] = bb.y; cF[nt][2] = bb.x; cF[nt][3] = bb.y;
        }
        #pragma unroll
        for (int ks = 0; ks < 4; ks++) {
            #pragma unroll
            for (int nt = 0; nt < 8; nt++) {
                uint2 Bh = bf2h[(ks*8 + nt)*32 + lane];
                uint2 Bl = bf2l[(ks*8 + nt)*32 + lane];
                mma16816(cF[nt][0], cF[nt][1], cF[nt][2], cF[nt][3],
                         e1h[ks*4+0], e1h[ks*4+1], e1h[ks*4+2], e1h[ks*4+3], Bh.x, Bh.y);
                mma16816(cF[nt][0], cF[nt][1], cF[nt][2], cF[nt][3],
                         e1l[ks*4+0], e1l[ks*4+1], e1l[ks*4+2], e1l[ks*4+3], Bh.x, Bh.y);
                mma16816(cF[nt][0], cF[nt][1], cF[nt][2], cF[nt][3],
                         e1h[ks*4+0], e1h[ks*4+1], e1h[ks*4+2], e1h[ks*4+3], Bl.x, Bl.y);
            }
        }

        // ---- combine -> masked E, packed directly into eo1 A-fragments ----
        uint32_t aUh[16], aUl[16];
        {
            const float4* gpk = (const float4*)g_pk;
            const size_t jo = (size_t)(b*Ndim + j2)*OCdim;
            const int    ib = isA ? 0 : 64;
            #pragma unroll
            for (int nt = 0; nt < 8; nt++) {
                const int ch0 = nt*8 + 2*q;
                const int ksi = (nt >> 1)*4 + (nt & 1)*2;
                float2 e1a = unpack_sum(e1h[ksi],   e1l[ksi]);
                float2 e1b = unpack_sum(e1h[ksi+1], e1l[ksi+1]);
                float4 pj0 = gpk[jo + ch0];
                float4 pj1 = gpk[jo + ch0 + 1];
                float4 pi0 = s_nipk[ib + ch0];
                float4 pi1 = s_nipk[ib + ch0 + 1];
                float2 bf  = *(const float2*)&sbF1[ch0];
                float Q00 = silu_f(pj0.z + pi0.w + bf.x);
                float Q01 = silu_f(pj1.z + pi1.w + bf.y);
                float Q10 = silu_f(pi0.z + pj0.w + bf.x);
                float Q11 = silu_f(pi1.z + pj1.w + bf.y);
                float E00 = silu_f(pj0.x + pi0.y + e1a.x + Q00*silu_f(cF[nt][0])) * emv;
                float E01 = silu_f(pj1.x + pi1.y + e1a.y + Q01*silu_f(cF[nt][1])) * emv;
                float E10 = silu_f(pi0.x + pj0.y + e1b.x + Q10*silu_f(cF[nt][2])) * emv;
                float E11 = silu_f(pi1.x + pj1.y + e1b.y + Q11*silu_f(cF[nt][3])) * emv;
                const int bse = (nt >> 1)*4 + (nt & 1)*2;
                split_h2(E00, E01, aUh[bse],   aUl[bse]);     // row grp
                split_h2(E10, E11, aUh[bse+1], aUl[bse+1]);   // row grp+8
            }
        }

        // ---- eo1 = E @ W_eo1 via MMA; symmetrize in C-frag (c0+c2) ----
        float cU[4][4];
        #pragma unroll
        for (int nt = 0; nt < 4; nt++)
            cU[nt][0] = cU[nt][1] = cU[nt][2] = cU[nt][3] = 0.f;
        #pragma unroll
        for (int ks = 0; ks < 4; ks++) {
            #pragma unroll
            for (int nt = 0; nt < 4; nt++) {
                uint2 Bh = bo1h[(ks*4 + nt)*32 + lane];
                uint2 Bl = bo1l[(ks*4 + nt)*32 + lane];
                mma16816(cU[nt][0], cU[nt][1], cU[nt][2], cU[nt][3],
                         aUh[ks*4+0], aUh[ks*4+1], aUh[ks*4+2], aUh[ks*4+3], Bh.x, Bh.y);
                mma16816(cU[nt][0], cU[nt][1], cU[nt][2], cU[nt][3],
                         aUl[ks*4+0], aUl[ks*4+1], aUl[ks*4+2], aUl[ks*4+3], Bh.x, Bh.y);
                mma16816(cU[nt][0], cU[nt][1], cU[nt][2], cU[nt][3],
                         aUh[ks*4+0], aUh[ks*4+1], aUh[ks*4+2], aUh[ks*4+3], Bl.x, Bl.y);
            }
        }

        // u[pair grp][ch nt*8+2q(+1)] = c0+c2 (+ bias); LayerNorm within quad
        float u0[4], u1[4];
        float s = 0.f;
        #pragma unroll
        for (int nt = 0; nt < 4; nt++) {
            float2 bb = *(const float2*)&sbeo1[nt*8 + 2*q];
            u0[nt] = cU[nt][0] + cU[nt][2] + bb.x;
            u1[nt] = cU[nt][1] + cU[nt][3] + bb.y;
            s += u0[nt] + u1[nt];
        }
        s += __shfl_xor_sync(0xffffffffu, s, 1);
        s += __shfl_xor_sync(0xffffffffu, s, 2);
        const float mean = s * (1.f/32.f);
        float var = 0.f;
        #pragma unroll
        for (int nt = 0; nt < 4; nt++) {
            float d0 = u0[nt] - mean, d1 = u1[nt] - mean;
            var += d0*d0 + d1*d1;
        }
        var += __shfl_xor_sync(0xffffffffu, var, 1);
        var += __shfl_xor_sync(0xffffffffu, var, 2);
        const float rstd = rsqrtf(var * (1.f/32.f) + 1e-5f);
        #pragma unroll
        for (int nt = 0; nt < 4; nt++) {
            const int ch0 = nt*8 + 2*q;
            float2 ge = *(const float2*)&sgeo[ch0];
            float2 be = *(const float2*)&sbeeo[ch0];
            float v0 = silu_f((u0[nt] - mean)*rstd*ge.x + be.x);
            float v1 = silu_f((u1[nt] - mean)*rstd*ge.y + be.y);
            *(float2*)&sv[grp*36 + ch0] = make_float2(v0, v1);
        }
        __syncwarp();

        // ---- eo2 + write (two halves of 4 pairs) ----
        #pragma unroll
        for (int h = 0; h < 2; h++) {
            const int pr  = h*4 + (lane >> 3);
            const int ch2 = lane & 7;
            float t = 0.f;
            #pragma unroll
            for (int k4 = 0; k4 < 8; k4++) {
                float4 vv = *(const float4*)&sv[pr*36 + k4*4];
                float4 w4 = *(const float4*)&sw_eo2T[ch2*36 + k4*4];
                t += vv.x*w4.x + vv.y*w4.y + vv.z*w4.z + vv.w*w4.w;
            }
            if (ch2 < KEdim && sact[pr]) {
                const int io = smi[pr], jo2 = smj[pr];
                float outv = (t + sbeo2[ch2]) * sem[pr];
                out_edge[((size_t)(b*Ndim + io)*Ndim + jo2)*KEdim + ch2] = outv;
                out_edge[((size_t)(b*Ndim + jo2)*Ndim + io)*KEdim + ch2] = outv;
            }
        }
        __syncwarp();
    }
}

// ---------------------------------------------------------------------------
extern "C" void kernel_launch(void* const* d_in, const int* in_sizes, int n_in,
                              void* d_out, int out_size)
{
    const float* node      = (const float*)d_in[0];
    const float* edge      = (const float*)d_in[1];
    const int*   block_id  = (const int*)d_in[2];
    const int*   vmask     = (const int*)d_in[3];
    const float* W_nt  = (const float*)d_in[4];
    const float* b_nt  = (const float*)d_in[5];
    const float* W_n1  = (const float*)d_in[6];
    const float* b_n1  = (const float*)d_in[7];
    const float* W_e1  = (const float*)d_in[8];
    const float* b_e1  = (const float*)d_in[9];
    const float* W_f1  = (const float*)d_in[10];
    const float* b_f1  = (const float*)d_in[11];
    const float* W_f2  = (const float*)d_in[12];
    const float* b_f2  = (const float*)d_in[13];
    const float* W_no1 = (const float*)d_in[14];
    const float* b_no1 = (const float*)d_in[15];
    const float* g_no  = (const float*)d_in[16];
    const float* be_no = (const float*)d_in[17];
    const float* W_no2 = (const float*)d_in[18];
    const float* b_no2 = (const float*)d_in[19];
    const float* W_eo1 = (const float*)d_in[20];
    const float* b_eo1 = (const float*)d_in[21];
    const float* g_eo  = (const float*)d_in[22];
    const float* be_eo = (const float*)d_in[23];
    const float* W_eo2 = (const float*)d_in[24];
    const float* b_eo2 = (const float*)d_in[25];

    float* out_node = (float*)d_out;                       // (B,N,KN)
    float* out_edge = (float*)d_out + Bdim*Ndim*KNdim;     // (B,N,N,KE)

    static int smem_set = 0;
    if (!smem_set) {
        cudaFuncSetAttribute(edge_kernel, cudaFuncAttributeMaxDynamicSharedMemorySize, SM_TOTAL);
        smem_set = 1;
    }

    reduce_kernel<<<Bdim*Ndim, 256>>>(edge, block_id, vmask);

    node_kernel<<<Bdim*64, 256>>>(node, block_id,
                                  W_nt, b_nt, W_n1, b_n1, W_f1,
                                  W_no1, b_no1, g_no, be_no, W_no2, b_no2,
                                  out_node);

    edge_kernel<<<Bdim*256, 256, SM_TOTAL>>>(edge, block_id, vmask,
                                   W_e1, b_e1, b_f1, W_f2, b_f2,
                                   W_eo1, b_eo1, g_eo, be_eo, W_eo2, b_eo2,
                                   out_edge);
}

// round 12
// speedup vs baseline: 1.7898x; 1.0632x over previous
#include <cuda_runtime.h>
#include <cuda_fp16.h>
#include <stdint.h>

#define Bdim 4
#define Ndim 512
#define NCdim 128
#define ECdim 32
#define OCdim 64
#define KNdim 10
#define KEdim 5
#define NIN 192   // 2*EC + NC
#define EWARPS 8
#define PX 12     // node-kernel transposed pitch

// packed per-node vectors: {n1, n2, q1, q2} per channel (float4-interleaved)
__device__ float g_pk[Bdim*Ndim*OCdim*4];
// x_in (0..31) ++ x_out (32..63) per node
__device__ float g_x[Bdim*Ndim*64];

__device__ __forceinline__ float silu_f(float x) {
    return __fdividef(x, 1.0f + __expf(-x));
}
// fast silu: x * sigmoid(x) = 0.5x(1 + tanh(x/2)); 1 MUFU instead of 2
__device__ __forceinline__ float silu_t(float x) {
    float th;
    asm("tanh.approx.f32 %0, %1;" : "=f"(th) : "f"(x * 0.5f));
    return fmaf(0.5f*x, th, 0.5f*x);
}

__device__ __forceinline__ void mma16816(float& c0, float& c1, float& c2, float& c3,
                                         uint32_t a0, uint32_t a1, uint32_t a2, uint32_t a3,
                                         uint32_t b0, uint32_t b1) {
    asm volatile("mma.sync.aligned.m16n8k16.row.col.f32.f16.f16.f32 "
                 "{%0,%1,%2,%3},{%4,%5,%6,%7},{%8,%9},{%0,%1,%2,%3};\n"
                 : "+f"(c0), "+f"(c1), "+f"(c2), "+f"(c3)
                 : "r"(a0), "r"(a1), "r"(a2), "r"(a3), "r"(b0), "r"(b1));
}

__device__ __forceinline__ void split_h2(float x, float y, uint32_t& hi, uint32_t& lo) {
    __half hx = __float2half_rn(x), hy = __float2half_rn(y);
    __half lx = __float2half_rn(x - __half2float(hx));
    __half ly = __float2half_rn(y - __half2float(hy));
    __half2 h = __halves2half2(hx, hy), l = __halves2half2(lx, ly);
    hi = *(uint32_t*)&h;  lo = *(uint32_t*)&l;
}

__device__ __forceinline__ float2 unpack_sum(uint32_t h, uint32_t l) {
    float2 fh = __half22float2(*(__half2*)&h);
    float2 fl = __half22float2(*(__half2*)&l);
    return make_float2(fh.x + fl.x, fh.y + fl.y);
}

// ---------------------------------------------------------------------------
// Kernel A: masked-mean reduction. Warp takes 4 consecutive j per step
// (unrolled, 2 accumulator pairs) for higher MLP.
// ---------------------------------------------------------------------------
__global__ __launch_bounds__(256)
void reduce_kernel(const float* __restrict__ edge,
                   const int* __restrict__ block_id,
                   const int* __restrict__ vmask)
{
    const int bi = blockIdx.x;
    const int b  = bi / Ndim;
    const int i  = bi % Ndim;
    const int tid = threadIdx.x;

    __shared__ int           s_bid[Ndim];
    __shared__ unsigned char s_vm[Ndim];
    __shared__ float s_red[8][64];
    __shared__ float s_cnt[2][8];

    for (int k = tid; k < Ndim; k += 256) {
        s_bid[k] = block_id[b*Ndim + k];
        s_vm[k]  = (vmask[b*Ndim + k] != 0) ? 1 : 0;
    }
    __syncthreads();

    const int  bii  = s_bid[i];
    const bool nm_i = (bii >= 0);
    const bool vm_i = (s_vm[i] != 0);

    const int c  = tid & 31;
    const int jl = tid >> 5;

    float acc_in0 = 0.f, acc_in1 = 0.f, acc_out0 = 0.f, acc_out1 = 0.f;
    float cnt_in = 0.f, cnt_out = 0.f;
    const float* erow = edge + ((size_t)(b*Ndim + i) * Ndim) * ECdim;
    const float* ecol = edge + ((size_t)b*Ndim) * Ndim * ECdim + (size_t)i*ECdim;

    for (int j0 = jl*4; j0 < Ndim; j0 += 32) {
        #pragma unroll
        for (int u = 0; u < 4; u++) {
            int j = j0 + u;
            int  bj   = s_bid[j];
            bool nm_j = (bj >= 0);
            bool pv   = nm_i && nm_j;
            bool cij  = pv && ((bii > bj) || (bii == bj && !vm_i));
            bool cji  = pv && ((bj > bii) || (bj == bii && (s_vm[j] == 0)));
            if (cij) {
                float v = erow[(size_t)j*ECdim + c];
                if (u & 1) acc_in1 += v; else acc_in0 += v;
                cnt_in  += 1.f;
            }
            if (cji) {
                float v = ecol[(size_t)j*Ndim*ECdim + c];
                if (u & 1) acc_out1 += v; else acc_out0 += v;
                cnt_out += 1.f;
            }
        }
    }
    s_red[jl][c]      = acc_in0 + acc_in1;
    s_red[jl][c + 32] = acc_out0 + acc_out1;
    if (c == 0) { s_cnt[0][jl] = cnt_in; s_cnt[1][jl] = cnt_out; }
    __syncthreads();

    if (tid < 64) {
        float s = 0.f, cnt = 0.f;
        #pragma unroll
        for (int r2 = 0; r2 < 8; r2++) { s += s_red[r2][tid]; cnt += s_cnt[tid >> 5][r2]; }
        g_x[(size_t)(b*Ndim + i)*64 + tid] = s / fmaxf(cnt, 1.f);
    }
}

// ---------------------------------------------------------------------------
// Kernel B: batched node GEMVs (round-10 winner, unchanged).
// ---------------------------------------------------------------------------
__global__ __launch_bounds__(256)
void node_kernel(const float* __restrict__ node,
                 const int* __restrict__ block_id,
                 const float* __restrict__ W_nt, const float* __restrict__ b_nt,
                 const float* __restrict__ W_n1, const float* __restrict__ b_n1,
                 const float* __restrict__ W_f1,
                 const float* __restrict__ W_no1, const float* __restrict__ b_no1,
                 const float* __restrict__ g_no, const float* __restrict__ be_no,
                 const float* __restrict__ W_no2, const float* __restrict__ b_no2,
                 float* __restrict__ out_node)
{
    const int b  = blockIdx.x >> 6;
    const int i0 = (blockIdx.x & 63) * 8;
    const int tid = threadIdx.x;
    const int w    = tid >> 5;
    const int lane = tid & 31;

    __shared__ int s_bid8[8];
    __shared__ float s_x[NIN*PX];
    __shared__ float s_hT[NCdim*PX];
    __shared__ float s_nT[NCdim*PX];
    __shared__ float s_tT[NCdim*PX];
    __shared__ float s_vT[NCdim*PX];

    if (tid < 8) s_bid8[tid] = block_id[b*Ndim + i0 + tid];
    __syncthreads();

    {
        const int i = i0 + w;
        const bool nm_i = (s_bid8[w] >= 0);
        const size_t xo = (size_t)(b*Ndim + i)*64;
        s_x[lane*PX + w]      = g_x[xo + lane];
        s_x[(lane+32)*PX + w] = g_x[xo + 32 + lane];
        float msk = nm_i ? 1.f : 0.f;
        float4 nd = *(const float4*)&node[(size_t)(b*Ndim + i)*NCdim + lane*4];
        s_x[(64 + lane*4 + 0)*PX + w] = nd.x * msk;
        s_x[(64 + lane*4 + 1)*PX + w] = nd.y * msk;
        s_x[(64 + lane*4 + 2)*PX + w] = nd.z * msk;
        s_x[(64 + lane*4 + 3)*PX + w] = nd.w * msk;
    }
    __syncthreads();

    const int o = tid & 127;
    const int g = tid >> 7;

    {
        float bb = b_nt[o];
        float4 acc = make_float4(bb, bb, bb, bb);
        #pragma unroll 4
        for (int k = 0; k < NIN; k++) {
            float wv = W_nt[k*NCdim + o];
            float4 xi = *(const float4*)&s_x[k*PX + g*4];
            acc.x += wv*xi.x; acc.y += wv*xi.y; acc.z += wv*xi.z; acc.w += wv*xi.w;
        }
        #pragma unroll
        for (int c4 = 0; c4 < 4; c4++) {
            int nn = g*4 + c4;
            float v = (c4 == 0) ? acc.x : (c4 == 1) ? acc.y : (c4 == 2) ? acc.z : acc.w;
            s_hT[o*PX + nn] = (s_bid8[nn] >= 0) ? silu_f(v) : 0.f;
        }
    }
    __syncthreads();

    {
        float bn = b_n1[o], bt = b_no1[o];
        float4 an = make_float4(bn, bn, bn, bn);
        float4 at = make_float4(bt, bt, bt, bt);
        #pragma unroll 4
        for (int k = 0; k < NCdim; k++) {
            float wn = W_n1[k*NCdim + o];
            float wt = W_no1[k*NCdim + o];
            float4 xi = *(const float4*)&s_hT[k*PX + g*4];
            an.x += wn*xi.x; an.y += wn*xi.y; an.z += wn*xi.z; an.w += wn*xi.w;
            at.x += wt*xi.x; at.y += wt*xi.y; at.z += wt*xi.z; at.w += wt*xi.w;
        }
        s_nT[o*PX + g*4+0] = an.x; s_nT[o*PX + g*4+1] = an.y;
        s_nT[o*PX + g*4+2] = an.z; s_nT[o*PX + g*4+3] = an.w;
        s_tT[o*PX + g*4+0] = at.x; s_tT[o*PX + g*4+1] = at.y;
        s_tT[o*PX + g*4+2] = at.z; s_tT[o*PX + g*4+3] = at.w;
    }
    __syncthreads();

    {
        const int oq = tid & 63;
        const int wh = (tid >> 6) & 1;
        float4 aq = make_float4(0.f, 0.f, 0.f, 0.f);
        #pragma unroll 4
        for (int k = 0; k < OCdim; k++) {
            float wq = W_f1[k*OCdim + oq];
            float4 xi = *(const float4*)&s_nT[(wh*OCdim + k)*PX + g*4];
            aq.x += wq*xi.x; aq.y += wq*xi.y; aq.z += wq*xi.z; aq.w += wq*xi.w;
        }
        #pragma unroll
        for (int c4 = 0; c4 < 4; c4++) {
            int nn = g*4 + c4;
            float qv = (c4 == 0) ? aq.x : (c4 == 1) ? aq.y : (c4 == 2) ? aq.z : aq.w;
            size_t base = ((size_t)(b*Ndim + i0 + nn)*OCdim + oq)*4;
            g_pk[base + wh]     = s_nT[(wh*OCdim + oq)*PX + nn];
            g_pk[base + 2 + wh] = qv;
        }
    }

    {
        float tv0 = s_tT[lane*PX + w];
        float tv1 = s_tT[(lane+32)*PX + w];
        float tv2 = s_tT[(lane+64)*PX + w];
        float tv3 = s_tT[(lane+96)*PX + w];
        float s = tv0 + tv1 + tv2 + tv3;
        #pragma unroll
        for (int o2 = 16; o2; o2 >>= 1) s += __shfl_xor_sync(0xffffffffu, s, o2);
        float mean = s * (1.f/NCdim);
        float d0 = tv0-mean, d1 = tv1-mean, d2 = tv2-mean, d3 = tv3-mean;
        float var = d0*d0 + d1*d1 + d2*d2 + d3*d3;
        #pragma unroll
        for (int o2 = 16; o2; o2 >>= 1) var += __shfl_xor_sync(0xffffffffu, var, o2);
        float rstd = rsqrtf(var * (1.f/NCdim) + 1e-5f);
        s_vT[lane*PX + w]      = silu_f(d0*rstd*g_no[lane]    + be_no[lane]);
        s_vT[(lane+32)*PX + w] = silu_f(d1*rstd*g_no[lane+32] + be_no[lane+32]);
        s_vT[(lane+64)*PX + w] = silu_f(d2*rstd*g_no[lane+64] + be_no[lane+64]);
        s_vT[(lane+96)*PX + w] = silu_f(d3*rstd*g_no[lane+96] + be_no[lane+96]);
    }
    __syncthreads();

    if (lane < KNdim) {
        float a = b_no2[lane];
        #pragma unroll 4
        for (int k = 0; k < NCdim; k++)
            a += s_vT[k*PX + w] * W_no2[k*KNdim + lane];
        bool nm_i = (s_bid8[w] >= 0);
        out_node[(size_t)(b*Ndim + i0 + w)*KNdim + lane] = nm_i ? a : 0.f;
    }
}

// ---------------------------------------------------------------------------
// Kernel 2: edge work (round-11 structure; silu via tanh.approx in hot loop).
// ---------------------------------------------------------------------------
#define SM_KEY     0
#define SM_BE1B    2048
#define SM_BF2B    2304
#define SM_BF1     2560
#define SM_NIPK    2816
#define SM_BEO1    4864
#define SM_GEO     4992
#define SM_BEEO    5120
#define SM_BEO2    5248
#define SM_EO2T    5296
#define SM_BE1H    6448
#define SM_BE1L    10544
#define SM_BF2H    14640
#define SM_BF2L    22832
#define SM_BO1H    31024
#define SM_BO1L    35120
#define SM_WARP    39216
#define SM_PERW    1280
#define SM_TOTAL   (SM_WARP + EWARPS*SM_PERW)   // 49456

__global__ __launch_bounds__(256, 2)
void edge_kernel(const float* __restrict__ edge,
                 const int* __restrict__ block_id,
                 const int* __restrict__ vmask,
                 const float* __restrict__ W_e1, const float* __restrict__ b_e1,
                 const float* __restrict__ b_f1,
                 const float* __restrict__ W_f2, const float* __restrict__ b_f2,
                 const float* __restrict__ W_eo1, const float* __restrict__ b_eo1,
                 const float* __restrict__ g_eo, const float* __restrict__ be_eo,
                 const float* __restrict__ W_eo2, const float* __restrict__ b_eo2,
                 float* __restrict__ out_edge)
{
    extern __shared__ char dsm[];
    const int b = blockIdx.x >> 8;
    const int r = blockIdx.x & 255;
    const int tid  = threadIdx.x;
    const int w    = tid >> 5;
    const int lane = tid & 31;
    const int grp  = lane >> 2;
    const int q    = lane & 3;

    int*    s_key  = (int*)(dsm + SM_KEY);
    float*  sbe1b  = (float*)(dsm + SM_BE1B);
    float*  sbf2b  = (float*)(dsm + SM_BF2B);
    float*  sbF1   = (float*)(dsm + SM_BF1);
    float4* s_nipk = (float4*)(dsm + SM_NIPK);
    float*  sbeo1  = (float*)(dsm + SM_BEO1);
    float*  sgeo   = (float*)(dsm + SM_GEO);
    float*  sbeeo  = (float*)(dsm + SM_BEEO);
    float*  sbeo2  = (float*)(dsm + SM_BEO2);
    float*  sw_eo2T = (float*)(dsm + SM_EO2T);
    uint2*  be1h   = (uint2*)(dsm + SM_BE1H);
    uint2*  be1l   = (uint2*)(dsm + SM_BE1L);
    uint2*  bf2h   = (uint2*)(dsm + SM_BF2H);
    uint2*  bf2l   = (uint2*)(dsm + SM_BF2L);
    uint2*  bo1h   = (uint2*)(dsm + SM_BO1H);
    uint2*  bo1l   = (uint2*)(dsm + SM_BO1L);

    char*  wbase = dsm + SM_WARP + w*SM_PERW;
    float* sv    = (float*)wbase;            // [8][36]
    int*   smi   = (int*)(wbase + 1152);
    int*   smj   = smi + 8;
    float* sem   = (float*)(smi + 16);
    int*   sact  = smi + 24;

    const int i_a = r, i_b = Ndim - 1 - r;

    for (int k = tid; k < Ndim; k += 256)
        s_key[k] = block_id[b*Ndim + k]*2 + ((vmask[b*Ndim + k] != 0) ? 1 : 0);
    if (tid < 64)  sbe1b[tid] = b_e1[tid];
    if (tid >= 64 && tid < 128)  sbf2b[tid-64] = b_f2[tid-64];
    if (tid >= 128 && tid < 192) sbF1[tid-128] = b_f1[tid-128];
    if (tid >= 192 && tid < 224) sbeo1[tid-192] = b_eo1[tid-192];
    if (tid >= 224 && tid < 256) sgeo[tid-224] = g_eo[tid-224];
    if (tid < 32)  sbeeo[tid] = be_eo[tid];
    if (tid >= 32 && tid < 40) sbeo2[tid-32] = b_eo2[tid-32];
    if (tid >= 40 && tid < 168) {
        int k = tid - 40;
        int row = k >> 6, ch = k & 63;
        int irow = row ? i_b : i_a;
        s_nipk[k] = *(const float4*)&g_pk[((size_t)(b*Ndim + irow)*OCdim + ch)*4];
    }
    for (int k = tid; k < 8*36; k += 256) {
        int ch = k / 36, kk = k % 36;
        sw_eo2T[k] = (ch < KEdim && kk < ECdim) ? W_eo2[kk*KEdim + ch] : 0.f;
    }
    for (int e = tid; e < 512; e += 256) {
        int lane_ = e & 31, nt = (e >> 5) & 7, ks = e >> 8;
        int q_ = lane_ & 3, g_ = lane_ >> 2;
        int k0 = ks*16 + 2*q_;
        int n  = nt*8 + g_;
        uint32_t h0, l0, h1, l1;
        split_h2(W_e1[k0*OCdim + n],     W_e1[(k0+1)*OCdim + n], h0, l0);
        split_h2(W_e1[(k0+8)*OCdim + n], W_e1[(k0+9)*OCdim + n], h1, l1);
        be1h[e] = make_uint2(h0, h1);
        be1l[e] = make_uint2(l0, l1);
    }
    for (int e = tid; e < 1024; e += 256) {
        int lane_ = e & 31, nt = (e >> 5) & 7, ks = e >> 8;
        int q_ = lane_ & 3, g_ = lane_ >> 2;
        int k0 = ks*16 + 2*q_;
        int n  = nt*8 + g_;
        uint32_t h0, l0, h1, l1;
        split_h2(W_f2[k0*OCdim + n],     W_f2[(k0+1)*OCdim + n], h0, l0);
        split_h2(W_f2[(k0+8)*OCdim + n], W_f2[(k0+9)*OCdim + n], h1, l1);
        bf2h[e] = make_uint2(h0, h1);
        bf2l[e] = make_uint2(l0, l1);
    }
    for (int e = tid; e < 512; e += 256) {
        int lane_ = e & 31, nt = (e >> 5) & 3, ks = e >> 7;
        int q_ = lane_ & 3, g_ = lane_ >> 2;
        int k0 = ks*16 + 2*q_;
        int n  = nt*8 + g_;
        uint32_t h0, l0, h1, l1;
        split_h2(W_eo1[k0*32 + n],     W_eo1[(k0+1)*32 + n], h0, l0);
        split_h2(W_eo1[(k0+8)*32 + n], W_eo1[(k0+9)*32 + n], h1, l1);
        bo1h[e] = make_uint2(h0, h1);
        bo1l[e] = make_uint2(l0, l1);
    }
    __syncthreads();

    const int npa   = Ndim - i_a;
    const int total = Ndim + 1;

    for (int base = w*8; base < total; base += EWARPS*8) {
        if (lane < 8) {
            int p = base + lane;
            int act = (p < total) ? 1 : 0;
            int pc = act ? p : 0;
            bool aA = pc < npa;
            int i2 = aA ? i_a : i_b;
            int j2 = aA ? (i_a + pc) : (i_b + (pc - npa));
            int ki = s_key[i2], kj = s_key[j2];
            int bi_ = ki >> 1, bj_ = kj >> 1;
            bool nm2 = (bi_ >= 0) && (bj_ >= 0);
            bool cij = (bi_ > bj_) || (bi_ == bj_ && !(ki & 1));
            bool cji = (bj_ > bi_) || (bj_ == bi_ && !(kj & 1));
            smi[lane] = i2; smj[lane] = j2;
            sem[lane] = (nm2 && (cij || cji)) ? 1.f : 0.f;
            sact[lane] = act;
        }
        __syncwarp();

        const int   i2  = smi[grp];
        const int   j2  = smj[grp];
        const float emv = sem[grp];
        const bool  isA = (i2 == i_a);

        uint32_t aEh[8], aEl[8];
        {
            const float* eij = edge + ((size_t)(b*Ndim + i2)*Ndim + j2)*ECdim;
            const float* eji = edge + ((size_t)(b*Ndim + j2)*Ndim + i2)*ECdim;
            #pragma unroll
            for (int ks = 0; ks < 2; ks++) {
                float2 v0 = *(const float2*)(eij + ks*16 + 2*q);
                float2 v1 = *(const float2*)(eji + ks*16 + 2*q);
                float2 v2 = *(const float2*)(eij + ks*16 + 8 + 2*q);
                float2 v3 = *(const float2*)(eji + ks*16 + 8 + 2*q);
                split_h2(v0.x*emv, v0.y*emv, aEh[ks*4+0], aEl[ks*4+0]);
                split_h2(v1.x*emv, v1.y*emv, aEh[ks*4+1], aEl[ks*4+1]);
                split_h2(v2.x*emv, v2.y*emv, aEh[ks*4+2], aEl[ks*4+2]);
                split_h2(v3.x*emv, v3.y*emv, aEh[ks*4+3], aEl[ks*4+3]);
            }
        }

        float cE[8][4];
        #pragma unroll
        for (int nt = 0; nt < 8; nt++) {
            float2 bb = *(const float2*)&sbe1b[nt*8 + 2*q];
            cE[nt][0] = bb.x; cE[nt][1] = bb.y; cE[nt][2] = bb.x; cE[nt][3] = bb.y;
        }
        #pragma unroll
        for (int ks = 0; ks < 2; ks++) {
            #pragma unroll
            for (int nt = 0; nt < 8; nt++) {
                uint2 Bh = be1h[(ks*8 + nt)*32 + lane];
                uint2 Bl = be1l[(ks*8 + nt)*32 + lane];
                mma16816(cE[nt][0], cE[nt][1], cE[nt][2], cE[nt][3],
                         aEh[ks*4+0], aEh[ks*4+1], aEh[ks*4+2], aEh[ks*4+3], Bh.x, Bh.y);
                mma16816(cE[nt][0], cE[nt][1], cE[nt][2], cE[nt][3],
                         aEl[ks*4+0], aEl[ks*4+1], aEl[ks*4+2], aEl[ks*4+3], Bh.x, Bh.y);
                mma16816(cE[nt][0], cE[nt][1], cE[nt][2], cE[nt][3],
                         aEh[ks*4+0], aEh[ks*4+1], aEh[ks*4+2], aEh[ks*4+3], Bl.x, Bl.y);
            }
        }

        uint32_t e1h[16], e1l[16];
        #pragma unroll
        for (int ks = 0; ks < 4; ks++) {
            split_h2(cE[2*ks][0],   cE[2*ks][1],   e1h[ks*4+0], e1l[ks*4+0]);
            split_h2(cE[2*ks][2],   cE[2*ks][3],   e1h[ks*4+1], e1l[ks*4+1]);
            split_h2(cE[2*ks+1][0], cE[2*ks+1][1], e1h[ks*4+2], e1l[ks*4+2]);
            split_h2(cE[2*ks+1][2], cE[2*ks+1][3], e1h[ks*4+3], e1l[ks*4+3]);
        }

        float cF[8][4];
        #pragma unroll
        for (int nt = 0; nt < 8; nt++) {
            float2 bb = *(const float2*)&sbf2b[nt*8 + 2*q];
            cF[nt][0] = bb.x; cF[nt][1] = bb.y; cF[nt][2] = bb.x; cF[nt][3] = bb.y;
        }
        #pragma unroll
        for (int ks = 0; ks < 4; ks++) {
            #pragma unroll
            for (int nt = 0; nt < 8; nt++) {
                uint2 Bh = bf2h[(ks*8 + nt)*32 + lane];
                uint2 Bl = bf2l[(ks*8 + nt)*32 + lane];
                mma16816(cF[nt][0], cF[nt][1], cF[nt][2], cF[nt][3],
                         e1h[ks*4+0], e1h[ks*4+1], e1h[ks*4+2], e1h[ks*4+3], Bh.x, Bh.y);
                mma16816(cF[nt][0], cF[nt][1], cF[nt][2], cF[nt][3],
                         e1l[ks*4+0], e1l[ks*4+1], e1l[ks*4+2], e1l[ks*4+3], Bh.x, Bh.y);
                mma16816(cF[nt][0], cF[nt][1], cF[nt][2], cF[nt][3],
                         e1h[ks*4+0], e1h[ks*4+1], e1h[ks*4+2], e1h[ks*4+3], Bl.x, Bl.y);
            }
        }

        uint32_t aUh[16], aUl[16];
        {
            const float4* gpk = (const float4*)g_pk;
            const size_t jo = (size_t)(b*Ndim + j2)*OCdim;
            const int    ib = isA ? 0 : 64;
            #pragma unroll
            for (int nt = 0; nt < 8; nt++) {
                const int ch0 = nt*8 + 2*q;
                const int ksi = (nt >> 1)*4 + (nt & 1)*2;
                float2 e1a = unpack_sum(e1h[ksi],   e1l[ksi]);
                float2 e1b = unpack_sum(e1h[ksi+1], e1l[ksi+1]);
                float4 pj0 = gpk[jo + ch0];
                float4 pj1 = gpk[jo + ch0 + 1];
                float4 pi0 = s_nipk[ib + ch0];
                float4 pi1 = s_nipk[ib + ch0 + 1];
                float2 bf  = *(const float2*)&sbF1[ch0];
                float Q00 = silu_t(pj0.z + pi0.w + bf.x);
                float Q01 = silu_t(pj1.z + pi1.w + bf.y);
                float Q10 = silu_t(pi0.z + pj0.w + bf.x);
                float Q11 = silu_t(pi1.z + pj1.w + bf.y);
                float E00 = silu_t(pj0.x + pi0.y + e1a.x + Q00*silu_t(cF[nt][0])) * emv;
                float E01 = silu_t(pj1.x + pi1.y + e1a.y + Q01*silu_t(cF[nt][1])) * emv;
                float E10 = silu_t(pi0.x + pj0.y + e1b.x + Q10*silu_t(cF[nt][2])) * emv;
                float E11 = silu_t(pi1.x + pj1.y + e1b.y + Q11*silu_t(cF[nt][3])) * emv;
                const int bse = (nt >> 1)*4 + (nt & 1)*2;
                split_h2(E00, E01, aUh[bse],   aUl[bse]);
                split_h2(E10, E11, aUh[bse+1], aUl[bse+1]);
            }
        }

        float cU[4][4];
        #pragma unroll
        for (int nt = 0; nt < 4; nt++)
            cU[nt][0] = cU[nt][1] = cU[nt][2] = cU[nt][3] = 0.f;
        #pragma unroll
        for (int ks = 0; ks < 4; ks++) {
            #pragma unroll
            for (int nt = 0; nt < 4; nt++) {
                uint2 Bh = bo1h[(ks*4 + nt)*32 + lane];
                uint2 Bl = bo1l[(ks*4 + nt)*32 + lane];
                mma16816(cU[nt][0], cU[nt][1], cU[nt][2], cU[nt][3],
                         aUh[ks*4+0], aUh[ks*4+1], aUh[ks*4+2], aUh[ks*4+3], Bh.x, Bh.y);
                mma16816(cU[nt][0], cU[nt][1], cU[nt][2], cU[nt][3],
                         aUl[ks*4+0], aUl[ks*4+1], aUl[ks*4+2], aUl[ks*4+3], Bh.x, Bh.y);
                mma16816(cU[nt][0], cU[nt][1], cU[nt][2], cU[nt][3],
                         aUh[ks*4+0], aUh[ks*4+1], aUh[ks*4+2], aUh[ks*4+3], Bl.x, Bl.y);
            }
        }

        float u0[4], u1[4];
        float s = 0.f;
        #pragma unroll
        for (int nt = 0; nt < 4; nt++) {
            float2 bb = *(const float2*)&sbeo1[nt*8 + 2*q];
            u0[nt] = cU[nt][0] + cU[nt][2] + bb.x;
            u1[nt] = cU[nt][1] + cU[nt][3] + bb.y;
            s += u0[nt] + u1[nt];
        }
        s += __shfl_xor_sync(0xffffffffu, s, 1);
        s += __shfl_xor_sync(0xffffffffu, s, 2);
        const float mean = s * (1.f/32.f);
        float var = 0.f;
        #pragma unroll
        for (int nt = 0; nt < 4; nt++) {
            float d0 = u0[nt] - mean, d1 = u1[nt] - mean;
            var += d0*d0 + d1*d1;
        }
        var += __shfl_xor_sync(0xffffffffu, var, 1);
        var += __shfl_xor_sync(0xffffffffu, var, 2);
        const float rstd = rsqrtf(var * (1.f/32.f) + 1e-5f);
        #pragma unroll
        for (int nt = 0; nt < 4; nt++) {
            const int ch0 = nt*8 + 2*q;
            float2 ge = *(const float2*)&sgeo[ch0];
            float2 be = *(const float2*)&sbeeo[ch0];
            float v0 = silu_t((u0[nt] - mean)*rstd*ge.x + be.x);
            float v1 = silu_t((u1[nt] - mean)*rstd*ge.y + be.y);
            *(float2*)&sv[grp*36 + ch0] = make_float2(v0, v1);
        }
        __syncwarp();

        #pragma unroll
        for (int h = 0; h < 2; h++) {
            const int pr  = h*4 + (lane >> 3);
            const int ch2 = lane & 7;
            float t = 0.f;
            #pragma unroll
            for (int k4 = 0; k4 < 8; k4++) {
                float4 vv = *(const float4*)&sv[pr*36 + k4*4];
                float4 w4 = *(const float4*)&sw_eo2T[ch2*36 + k4*4];
                t += vv.x*w4.x + vv.y*w4.y + vv.z*w4.z + vv.w*w4.w;
            }
            if (ch2 < KEdim && sact[pr]) {
                const int io = smi[pr], jo2 = smj[pr];
                float outv = (t + sbeo2[ch2]) * sem[pr];
                out_edge[((size_t)(b*Ndim + io)*Ndim + jo2)*KEdim + ch2] = outv;
                out_edge[((size_t)(b*Ndim + jo2)*Ndim + io)*KEdim + ch2] = outv;
            }
        }
        __syncwarp();
    }
}

// ---------------------------------------------------------------------------
extern "C" void kernel_launch(void* const* d_in, const int* in_sizes, int n_in,
                              void* d_out, int out_size)
{
    const float* node      = (const float*)d_in[0];
    const float* edge      = (const float*)d_in[1];
    const int*   block_id  = (const int*)d_in[2];
    const int*   vmask     = (const int*)d_in[3];
    const float* W_nt  = (const float*)d_in[4];
    const float* b_nt  = (const float*)d_in[5];
    const float* W_n1  = (const float*)d_in[6];
    const float* b_n1  = (const float*)d_in[7];
    const float* W_e1  = (const float*)d_in[8];
    const float* b_e1  = (const float*)d_in[9];
    const float* W_f1  = (const float*)d_in[10];
    const float* b_f1  = (const float*)d_in[11];
    const float* W_f2  = (const float*)d_in[12];
    const float* b_f2  = (const float*)d_in[13];
    const float* W_no1 = (const float*)d_in[14];
    const float* b_no1 = (const float*)d_in[15];
    const float* g_no  = (const float*)d_in[16];
    const float* be_no = (const float*)d_in[17];
    const float* W_no2 = (const float*)d_in[18];
    const float* b_no2 = (const float*)d_in[19];
    const float* W_eo1 = (const float*)d_in[20];
    const float* b_eo1 = (const float*)d_in[21];
    const float* g_eo  = (const float*)d_in[22];
    const float* be_eo = (const float*)d_in[23];
    const float* W_eo2 = (const float*)d_in[24];
    const float* b_eo2 = (const float*)d_in[25];

    float* out_node = (float*)d_out;                       // (B,N,KN)
    float* out_edge = (float*)d_out + Bdim*Ndim*KNdim;     // (B,N,N,KE)

    static int smem_set = 0;
    if (!smem_set) {
        cudaFuncSetAttribute(edge_kernel, cudaFuncAttributeMaxDynamicSharedMemorySize, SM_TOTAL);
        smem_set = 1;
    }

    reduce_kernel<<<Bdim*Ndim, 256>>>(edge, block_id, vmask);

    node_kernel<<<Bdim*64, 256>>>(node, block_id,
                                  W_nt, b_nt, W_n1, b_n1, W_f1,
                                  W_no1, b_no1, g_no, be_no, W_no2, b_no2,
                                  out_node);

    edge_kernel<<<Bdim*256, 256, SM_TOTAL>>>(edge, block_id, vmask,
                                   W_e1, b_e1, b_f1, W_f2, b_f2,
                                   W_eo1, b_eo1, g_eo, be_eo, W_eo2, b_eo2,
                                   out_edge);
}

// round 13
// speedup vs baseline: 1.8929x; 1.0576x over previous
#include <cuda_runtime.h>
#include <cuda_fp16.h>
#include <stdint.h>

#define Bdim 4
#define Ndim 512
#define NCdim 128
#define ECdim 32
#define OCdim 64
#define KNdim 10
#define KEdim 5
#define NIN 192   // 2*EC + NC
#define EWARPS 8
#define PX 12     // node-kernel transposed pitch

// packed per-node vectors: {n1, n2, q1, q2} per channel (float4-interleaved)
__device__ float g_pk[Bdim*Ndim*OCdim*4];
// x_in (0..31) ++ x_out (32..63) per node
__device__ float g_x[Bdim*Ndim*64];

__device__ __forceinline__ float silu_f(float x) {
    return __fdividef(x, 1.0f + __expf(-x));
}
// fast silu: x * sigmoid(x) = 0.5x(1 + tanh(x/2)); 1 MUFU instead of 2
__device__ __forceinline__ float silu_t(float x) {
    float th;
    asm("tanh.approx.f32 %0, %1;" : "=f"(th) : "f"(x * 0.5f));
    return fmaf(0.5f*x, th, 0.5f*x);
}

__device__ __forceinline__ void mma16816(float& c0, float& c1, float& c2, float& c3,
                                         uint32_t a0, uint32_t a1, uint32_t a2, uint32_t a3,
                                         uint32_t b0, uint32_t b1) {
    asm volatile("mma.sync.aligned.m16n8k16.row.col.f32.f16.f16.f32 "
                 "{%0,%1,%2,%3},{%4,%5,%6,%7},{%8,%9},{%0,%1,%2,%3};\n"
                 : "+f"(c0), "+f"(c1), "+f"(c2), "+f"(c3)
                 : "r"(a0), "r"(a1), "r"(a2), "r"(a3), "r"(b0), "r"(b1));
}

__device__ __forceinline__ void split_h2(float x, float y, uint32_t& hi, uint32_t& lo) {
    __half hx = __float2half_rn(x), hy = __float2half_rn(y);
    __half lx = __float2half_rn(x - __half2float(hx));
    __half ly = __float2half_rn(y - __half2float(hy));
    __half2 h = __halves2half2(hx, hy), l = __halves2half2(lx, ly);
    hi = *(uint32_t*)&h;  lo = *(uint32_t*)&l;
}

__device__ __forceinline__ float2 unpack_sum(uint32_t h, uint32_t l) {
    float2 fh = __half22float2(*(__half2*)&h);
    float2 fl = __half22float2(*(__half2*)&l);
    return make_float2(fh.x + fl.x, fh.y + fl.y);
}

// ---------------------------------------------------------------------------
// Kernel A: masked-mean reduction. UNCONDITIONAL loads + FMA masking so ptxas
// front-batches 8 LDGs per step (MLP_p1 ~8 instead of ~1).
// ---------------------------------------------------------------------------
__global__ __launch_bounds__(256)
void reduce_kernel(const float* __restrict__ edge,
                   const int* __restrict__ block_id,
                   const int* __restrict__ vmask)
{
    const int bi = blockIdx.x;
    const int b  = bi / Ndim;
    const int i  = bi % Ndim;
    const int tid = threadIdx.x;

    __shared__ int           s_bid[Ndim];
    __shared__ unsigned char s_vm[Ndim];
    __shared__ float s_red[8][64];
    __shared__ float s_cnt[2][8];

    for (int k = tid; k < Ndim; k += 256) {
        s_bid[k] = block_id[b*Ndim + k];
        s_vm[k]  = (vmask[b*Ndim + k] != 0) ? 1 : 0;
    }
    __syncthreads();

    const int  bii  = s_bid[i];
    const bool nm_i = (bii >= 0);
    const bool vm_i = (s_vm[i] != 0);

    const int c  = tid & 31;
    const int jl = tid >> 5;

    float acc_in0 = 0.f, acc_in1 = 0.f, acc_out0 = 0.f, acc_out1 = 0.f;
    float cnt_in = 0.f, cnt_out = 0.f;
    const float* erow = edge + ((size_t)(b*Ndim + i) * Ndim) * ECdim;
    const float* ecol = edge + ((size_t)b*Ndim) * Ndim * ECdim + (size_t)i*ECdim;

    for (int j0 = jl*4; j0 < Ndim; j0 += 32) {
        float vin[4], vout[4], min_[4], mout_[4];
        #pragma unroll
        for (int u = 0; u < 4; u++) {
            int j = j0 + u;
            vin[u]  = erow[(size_t)j*ECdim + c];
            vout[u] = ecol[(size_t)j*Ndim*ECdim + c];
        }
        #pragma unroll
        for (int u = 0; u < 4; u++) {
            int j = j0 + u;
            int  bj   = s_bid[j];
            bool nm_j = (bj >= 0);
            bool pv   = nm_i && nm_j;
            bool cij  = pv && ((bii > bj) || (bii == bj && !vm_i));
            bool cji  = pv && ((bj > bii) || (bj == bii && (s_vm[j] == 0)));
            min_[u]  = cij ? 1.f : 0.f;
            mout_[u] = cji ? 1.f : 0.f;
            cnt_in  += min_[u];
            cnt_out += mout_[u];
        }
        acc_in0  = fmaf(vin[0],  min_[0],  acc_in0);
        acc_in1  = fmaf(vin[1],  min_[1],  acc_in1);
        acc_in0  = fmaf(vin[2],  min_[2],  acc_in0);
        acc_in1  = fmaf(vin[3],  min_[3],  acc_in1);
        acc_out0 = fmaf(vout[0], mout_[0], acc_out0);
        acc_out1 = fmaf(vout[1], mout_[1], acc_out1);
        acc_out0 = fmaf(vout[2], mout_[2], acc_out0);
        acc_out1 = fmaf(vout[3], mout_[3], acc_out1);
    }
    s_red[jl][c]      = acc_in0 + acc_in1;
    s_red[jl][c + 32] = acc_out0 + acc_out1;
    if (c == 0) { s_cnt[0][jl] = cnt_in; s_cnt[1][jl] = cnt_out; }
    __syncthreads();

    if (tid < 64) {
        float s = 0.f, cnt = 0.f;
        #pragma unroll
        for (int r2 = 0; r2 < 8; r2++) { s += s_red[r2][tid]; cnt += s_cnt[tid >> 5][r2]; }
        g_x[(size_t)(b*Ndim + i)*64 + tid] = s / fmaxf(cnt, 1.f);
    }
}

// ---------------------------------------------------------------------------
// Kernel B: batched node GEMVs (round-10 winner, unchanged).
// ---------------------------------------------------------------------------
__global__ __launch_bounds__(256)
void node_kernel(const float* __restrict__ node,
                 const int* __restrict__ block_id,
                 const float* __restrict__ W_nt, const float* __restrict__ b_nt,
                 const float* __restrict__ W_n1, const float* __restrict__ b_n1,
                 const float* __restrict__ W_f1,
                 const float* __restrict__ W_no1, const float* __restrict__ b_no1,
                 const float* __restrict__ g_no, const float* __restrict__ be_no,
                 const float* __restrict__ W_no2, const float* __restrict__ b_no2,
                 float* __restrict__ out_node)
{
    const int b  = blockIdx.x >> 6;
    const int i0 = (blockIdx.x & 63) * 8;
    const int tid = threadIdx.x;
    const int w    = tid >> 5;
    const int lane = tid & 31;

    __shared__ int s_bid8[8];
    __shared__ float s_x[NIN*PX];
    __shared__ float s_hT[NCdim*PX];
    __shared__ float s_nT[NCdim*PX];
    __shared__ float s_tT[NCdim*PX];
    __shared__ float s_vT[NCdim*PX];

    if (tid < 8) s_bid8[tid] = block_id[b*Ndim + i0 + tid];
    __syncthreads();

    {
        const int i = i0 + w;
        const bool nm_i = (s_bid8[w] >= 0);
        const size_t xo = (size_t)(b*Ndim + i)*64;
        s_x[lane*PX + w]      = g_x[xo + lane];
        s_x[(lane+32)*PX + w] = g_x[xo + 32 + lane];
        float msk = nm_i ? 1.f : 0.f;
        float4 nd = *(const float4*)&node[(size_t)(b*Ndim + i)*NCdim + lane*4];
        s_x[(64 + lane*4 + 0)*PX + w] = nd.x * msk;
        s_x[(64 + lane*4 + 1)*PX + w] = nd.y * msk;
        s_x[(64 + lane*4 + 2)*PX + w] = nd.z * msk;
        s_x[(64 + lane*4 + 3)*PX + w] = nd.w * msk;
    }
    __syncthreads();

    const int o = tid & 127;
    const int g = tid >> 7;

    {
        float bb = b_nt[o];
        float4 acc = make_float4(bb, bb, bb, bb);
        #pragma unroll 4
        for (int k = 0; k < NIN; k++) {
            float wv = W_nt[k*NCdim + o];
            float4 xi = *(const float4*)&s_x[k*PX + g*4];
            acc.x += wv*xi.x; acc.y += wv*xi.y; acc.z += wv*xi.z; acc.w += wv*xi.w;
        }
        #pragma unroll
        for (int c4 = 0; c4 < 4; c4++) {
            int nn = g*4 + c4;
            float v = (c4 == 0) ? acc.x : (c4 == 1) ? acc.y : (c4 == 2) ? acc.z : acc.w;
            s_hT[o*PX + nn] = (s_bid8[nn] >= 0) ? silu_f(v) : 0.f;
        }
    }
    __syncthreads();

    {
        float bn = b_n1[o], bt = b_no1[o];
        float4 an = make_float4(bn, bn, bn, bn);
        float4 at = make_float4(bt, bt, bt, bt);
        #pragma unroll 4
        for (int k = 0; k < NCdim; k++) {
            float wn = W_n1[k*NCdim + o];
            float wt = W_no1[k*NCdim + o];
            float4 xi = *(const float4*)&s_hT[k*PX + g*4];
            an.x += wn*xi.x; an.y += wn*xi.y; an.z += wn*xi.z; an.w += wn*xi.w;
            at.x += wt*xi.x; at.y += wt*xi.y; at.z += wt*xi.z; at.w += wt*xi.w;
        }
        s_nT[o*PX + g*4+0] = an.x; s_nT[o*PX + g*4+1] = an.y;
        s_nT[o*PX + g*4+2] = an.z; s_nT[o*PX + g*4+3] = an.w;
        s_tT[o*PX + g*4+0] = at.x; s_tT[o*PX + g*4+1] = at.y;
        s_tT[o*PX + g*4+2] = at.z; s_tT[o*PX + g*4+3] = at.w;
    }
    __syncthreads();

    {
        const int oq = tid & 63;
        const int wh = (tid >> 6) & 1;
        float4 aq = make_float4(0.f, 0.f, 0.f, 0.f);
        #pragma unroll 4
        for (int k = 0; k < OCdim; k++) {
            float wq = W_f1[k*OCdim + oq];
            float4 xi = *(const float4*)&s_nT[(wh*OCdim + k)*PX + g*4];
            aq.x += wq*xi.x; aq.y += wq*xi.y; aq.z += wq*xi.z; aq.w += wq*xi.w;
        }
        #pragma unroll
        for (int c4 = 0; c4 < 4; c4++) {
            int nn = g*4 + c4;
            float qv = (c4 == 0) ? aq.x : (c4 == 1) ? aq.y : (c4 == 2) ? aq.z : aq.w;
            size_t base = ((size_t)(b*Ndim + i0 + nn)*OCdim + oq)*4;
            g_pk[base + wh]     = s_nT[(wh*OCdim + oq)*PX + nn];
            g_pk[base + 2 + wh] = qv;
        }
    }

    {
        float tv0 = s_tT[lane*PX + w];
        float tv1 = s_tT[(lane+32)*PX + w];
        float tv2 = s_tT[(lane+64)*PX + w];
        float tv3 = s_tT[(lane+96)*PX + w];
        float s = tv0 + tv1 + tv2 + tv3;
        #pragma unroll
        for (int o2 = 16; o2; o2 >>= 1) s += __shfl_xor_sync(0xffffffffu, s, o2);
        float mean = s * (1.f/NCdim);
        float d0 = tv0-mean, d1 = tv1-mean, d2 = tv2-mean, d3 = tv3-mean;
        float var = d0*d0 + d1*d1 + d2*d2 + d3*d3;
        #pragma unroll
        for (int o2 = 16; o2; o2 >>= 1) var += __shfl_xor_sync(0xffffffffu, var, o2);
        float rstd = rsqrtf(var * (1.f/NCdim) + 1e-5f);
        s_vT[lane*PX + w]      = silu_f(d0*rstd*g_no[lane]    + be_no[lane]);
        s_vT[(lane+32)*PX + w] = silu_f(d1*rstd*g_no[lane+32] + be_no[lane+32]);
        s_vT[(lane+64)*PX + w] = silu_f(d2*rstd*g_no[lane+64] + be_no[lane+64]);
        s_vT[(lane+96)*PX + w] = silu_f(d3*rstd*g_no[lane+96] + be_no[lane+96]);
    }
    __syncthreads();

    if (lane < KNdim) {
        float a = b_no2[lane];
        #pragma unroll 4
        for (int k = 0; k < NCdim; k++)
            a += s_vT[k*PX + w] * W_no2[k*KNdim + lane];
        bool nm_i = (s_bid8[w] >= 0);
        out_node[(size_t)(b*Ndim + i0 + w)*KNdim + lane] = nm_i ? a : 0.f;
    }
}

// ---------------------------------------------------------------------------
// Kernel 2: edge work (round-12 winner, unchanged).
// ---------------------------------------------------------------------------
#define SM_KEY     0
#define SM_BE1B    2048
#define SM_BF2B    2304
#define SM_BF1     2560
#define SM_NIPK    2816
#define SM_BEO1    4864
#define SM_GEO     4992
#define SM_BEEO    5120
#define SM_BEO2    5248
#define SM_EO2T    5296
#define SM_BE1H    6448
#define SM_BE1L    10544
#define SM_BF2H    14640
#define SM_BF2L    22832
#define SM_BO1H    31024
#define SM_BO1L    35120
#define SM_WARP    39216
#define SM_PERW    1280
#define SM_TOTAL   (SM_WARP + EWARPS*SM_PERW)   // 49456

__global__ __launch_bounds__(256, 2)
void edge_kernel(const float* __restrict__ edge,
                 const int* __restrict__ block_id,
                 const int* __restrict__ vmask,
                 const float* __restrict__ W_e1, const float* __restrict__ b_e1,
                 const float* __restrict__ b_f1,
                 const float* __restrict__ W_f2, const float* __restrict__ b_f2,
                 const float* __restrict__ W_eo1, const float* __restrict__ b_eo1,
                 const float* __restrict__ g_eo, const float* __restrict__ be_eo,
                 const float* __restrict__ W_eo2, const float* __restrict__ b_eo2,
                 float* __restrict__ out_edge)
{
    extern __shared__ char dsm[];
    const int b = blockIdx.x >> 8;
    const int r = blockIdx.x & 255;
    const int tid  = threadIdx.x;
    const int w    = tid >> 5;
    const int lane = tid & 31;
    const int grp  = lane >> 2;
    const int q    = lane & 3;

    int*    s_key  = (int*)(dsm + SM_KEY);
    float*  sbe1b  = (float*)(dsm + SM_BE1B);
    float*  sbf2b  = (float*)(dsm + SM_BF2B);
    float*  sbF1   = (float*)(dsm + SM_BF1);
    float4* s_nipk = (float4*)(dsm + SM_NIPK);
    float*  sbeo1  = (float*)(dsm + SM_BEO1);
    float*  sgeo   = (float*)(dsm + SM_GEO);
    float*  sbeeo  = (float*)(dsm + SM_BEEO);
    float*  sbeo2  = (float*)(dsm + SM_BEO2);
    float*  sw_eo2T = (float*)(dsm + SM_EO2T);
    uint2*  be1h   = (uint2*)(dsm + SM_BE1H);
    uint2*  be1l   = (uint2*)(dsm + SM_BE1L);
    uint2*  bf2h   = (uint2*)(dsm + SM_BF2H);
    uint2*  bf2l   = (uint2*)(dsm + SM_BF2L);
    uint2*  bo1h   = (uint2*)(dsm + SM_BO1H);
    uint2*  bo1l   = (uint2*)(dsm + SM_BO1L);

    char*  wbase = dsm + SM_WARP + w*SM_PERW;
    float* sv    = (float*)wbase;            // [8][36]
    int*   smi   = (int*)(wbase + 1152);
    int*   smj   = smi + 8;
    float* sem   = (float*)(smi + 16);
    int*   sact  = smi + 24;

    const int i_a = r, i_b = Ndim - 1 - r;

    for (int k = tid; k < Ndim; k += 256)
        s_key[k] = block_id[b*Ndim + k]*2 + ((vmask[b*Ndim + k] != 0) ? 1 : 0);
    if (tid < 64)  sbe1b[tid] = b_e1[tid];
    if (tid >= 64 && tid < 128)  sbf2b[tid-64] = b_f2[tid-64];
    if (tid >= 128 && tid < 192) sbF1[tid-128] = b_f1[tid-128];
    if (tid >= 192 && tid < 224) sbeo1[tid-192] = b_eo1[tid-192];
    if (tid >= 224 && tid < 256) sgeo[tid-224] = g_eo[tid-224];
    if (tid < 32)  sbeeo[tid] = be_eo[tid];
    if (tid >= 32 && tid < 40) sbeo2[tid-32] = b_eo2[tid-32];
    if (tid >= 40 && tid < 168) {
        int k = tid - 40;
        int row = k >> 6, ch = k & 63;
        int irow = row ? i_b : i_a;
        s_nipk[k] = *(const float4*)&g_pk[((size_t)(b*Ndim + irow)*OCdim + ch)*4];
    }
    for (int k = tid; k < 8*36; k += 256) {
        int ch = k / 36, kk = k % 36;
        sw_eo2T[k] = (ch < KEdim && kk < ECdim) ? W_eo2[kk*KEdim + ch] : 0.f;
    }
    for (int e = tid; e < 512; e += 256) {
        int lane_ = e & 31, nt = (e >> 5) & 7, ks = e >> 8;
        int q_ = lane_ & 3, g_ = lane_ >> 2;
        int k0 = ks*16 + 2*q_;
        int n  = nt*8 + g_;
        uint32_t h0, l0, h1, l1;
        split_h2(W_e1[k0*OCdim + n],     W_e1[(k0+1)*OCdim + n], h0, l0);
        split_h2(W_e1[(k0+8)*OCdim + n], W_e1[(k0+9)*OCdim + n], h1, l1);
        be1h[e] = make_uint2(h0, h1);
        be1l[e] = make_uint2(l0, l1);
    }
    for (int e = tid; e < 1024; e += 256) {
        int lane_ = e & 31, nt = (e >> 5) & 7, ks = e >> 8;
        int q_ = lane_ & 3, g_ = lane_ >> 2;
        int k0 = ks*16 + 2*q_;
        int n  = nt*8 + g_;
        uint32_t h0, l0, h1, l1;
        split_h2(W_f2[k0*OCdim + n],     W_f2[(k0+1)*OCdim + n], h0, l0);
        split_h2(W_f2[(k0+8)*OCdim + n], W_f2[(k0+9)*OCdim + n], h1, l1);
        bf2h[e] = make_uint2(h0, h1);
        bf2l[e] = make_uint2(l0, l1);
    }
    for (int e = tid; e < 512; e += 256) {
        int lane_ = e & 31, nt = (e >> 5) & 3, ks = e >> 7;
        int q_ = lane_ & 3, g_ = lane_ >> 2;
        int k0 = ks*16 + 2*q_;
        int n  = nt*8 + g_;
        uint32_t h0, l0, h1, l1;
        split_h2(W_eo1[k0*32 + n],     W_eo1[(k0+1)*32 + n], h0, l0);
        split_h2(W_eo1[(k0+8)*32 + n], W_eo1[(k0+9)*32 + n], h1, l1);
        bo1h[e] = make_uint2(h0, h1);
        bo1l[e] = make_uint2(l0, l1);
    }
    __syncthreads();

    const int npa   = Ndim - i_a;
    const int total = Ndim + 1;

    for (int base = w*8; base < total; base += EWARPS*8) {
        if (lane < 8) {
            int p = base + lane;
            int act = (p < total) ? 1 : 0;
            int pc = act ? p : 0;
            bool aA = pc < npa;
            int i2 = aA ? i_a : i_b;
            int j2 = aA ? (i_a + pc) : (i_b + (pc - npa));
            int ki = s_key[i2], kj = s_key[j2];
            int bi_ = ki >> 1, bj_ = kj >> 1;
            bool nm2 = (bi_ >= 0) && (bj_ >= 0);
            bool cij = (bi_ > bj_) || (bi_ == bj_ && !(ki & 1));
            bool cji = (bj_ > bi_) || (bj_ == bi_ && !(kj & 1));
            smi[lane] = i2; smj[lane] = j2;
            sem[lane] = (nm2 && (cij || cji)) ? 1.f : 0.f;
            sact[lane] = act;
        }
        __syncwarp();

        const int   i2  = smi[grp];
        const int   j2  = smj[grp];
        const float emv = sem[grp];
        const bool  isA = (i2 == i_a);

        uint32_t aEh[8], aEl[8];
        {
            const float* eij = edge + ((size_t)(b*Ndim + i2)*Ndim + j2)*ECdim;
            const float* eji = edge + ((size_t)(b*Ndim + j2)*Ndim + i2)*ECdim;
            #pragma unroll
            for (int ks = 0; ks < 2; ks++) {
                float2 v0 = *(const float2*)(eij + ks*16 + 2*q);
                float2 v1 = *(const float2*)(eji + ks*16 + 2*q);
                float2 v2 = *(const float2*)(eij + ks*16 + 8 + 2*q);
                float2 v3 = *(const float2*)(eji + ks*16 + 8 + 2*q);
                split_h2(v0.x*emv, v0.y*emv, aEh[ks*4+0], aEl[ks*4+0]);
                split_h2(v1.x*emv, v1.y*emv, aEh[ks*4+1], aEl[ks*4+1]);
                split_h2(v2.x*emv, v2.y*emv, aEh[ks*4+2], aEl[ks*4+2]);
                split_h2(v3.x*emv, v3.y*emv, aEh[ks*4+3], aEl[ks*4+3]);
            }
        }

        float cE[8][4];
        #pragma unroll
        for (int nt = 0; nt < 8; nt++) {
            float2 bb = *(const float2*)&sbe1b[nt*8 + 2*q];
            cE[nt][0] = bb.x; cE[nt][1] = bb.y; cE[nt][2] = bb.x; cE[nt][3] = bb.y;
        }
        #pragma unroll
        for (int ks = 0; ks < 2; ks++) {
            #pragma unroll
            for (int nt = 0; nt < 8; nt++) {
                uint2 Bh = be1h[(ks*8 + nt)*32 + lane];
                uint2 Bl = be1l[(ks*8 + nt)*32 + lane];
                mma16816(cE[nt][0], cE[nt][1], cE[nt][2], cE[nt][3],
                         aEh[ks*4+0], aEh[ks*4+1], aEh[ks*4+2], aEh[ks*4+3], Bh.x, Bh.y);
                mma16816(cE[nt][0], cE[nt][1], cE[nt][2], cE[nt][3],
                         aEl[ks*4+0], aEl[ks*4+1], aEl[ks*4+2], aEl[ks*4+3], Bh.x, Bh.y);
                mma16816(cE[nt][0], cE[nt][1], cE[nt][2], cE[nt][3],
                         aEh[ks*4+0], aEh[ks*4+1], aEh[ks*4+2], aEh[ks*4+3], Bl.x, Bl.y);
            }
        }

        uint32_t e1h[16], e1l[16];
        #pragma unroll
        for (int ks = 0; ks < 4; ks++) {
            split_h2(cE[2*ks][0],   cE[2*ks][1],   e1h[ks*4+0], e1l[ks*4+0]);
            split_h2(cE[2*ks][2],   cE[2*ks][3],   e1h[ks*4+1], e1l[ks*4+1]);
            split_h2(cE[2*ks+1][0], cE[2*ks+1][1], e1h[ks*4+2], e1l[ks*4+2]);
            split_h2(cE[2*ks+1][2], cE[2*ks+1][3], e1h[ks*4+3], e1l[ks*4+3]);
        }

        float cF[8][4];
        #pragma unroll
        for (int nt = 0; nt < 8; nt++) {
            float2 bb = *(const float2*)&sbf2b[nt*8 + 2*q];
            cF[nt][0] = bb.x; cF[nt][1] = bb.y; cF[nt][2] = bb.x; cF[nt][3] = bb.y;
        }
        #pragma unroll
        for (int ks = 0; ks < 4; ks++) {
            #pragma unroll
            for (int nt = 0; nt < 8; nt++) {
                uint2 Bh = bf2h[(ks*8 + nt)*32 + lane];
                uint2 Bl = bf2l[(ks*8 + nt)*32 + lane];
                mma16816(cF[nt][0], cF[nt][1], cF[nt][2], cF[nt][3],
                         e1h[ks*4+0], e1h[ks*4+1], e1h[ks*4+2], e1h[ks*4+3], Bh.x, Bh.y);
                mma16816(cF[nt][0], cF[nt][1], cF[nt][2], cF[nt][3],
                         e1l[ks*4+0], e1l[ks*4+1], e1l[ks*4+2], e1l[ks*4+3], Bh.x, Bh.y);
                mma16816(cF[nt][0], cF[nt][1], cF[nt][2], cF[nt][3],
                         e1h[ks*4+0], e1h[ks*4+1], e1h[ks*4+2], e1h[ks*4+3], Bl.x, Bl.y);
            }
        }

        uint32_t aUh[16], aUl[16];
        {
            const float4* gpk = (const float4*)g_pk;
            const size_t jo = (size_t)(b*Ndim + j2)*OCdim;
            const int    ib = isA ? 0 : 64;
            #pragma unroll
            for (int nt = 0; nt < 8; nt++) {
                const int ch0 = nt*8 + 2*q;
                const int ksi = (nt >> 1)*4 + (nt & 1)*2;
                float2 e1a = unpack_sum(e1h[ksi],   e1l[ksi]);
                float2 e1b = unpack_sum(e1h[ksi+1], e1l[ksi+1]);
                float4 pj0 = gpk[jo + ch0];
                float4 pj1 = gpk[jo + ch0 + 1];
                float4 pi0 = s_nipk[ib + ch0];
                float4 pi1 = s_nipk[ib + ch0 + 1];
                float2 bf  = *(const float2*)&sbF1[ch0];
                float Q00 = silu_t(pj0.z + pi0.w + bf.x);
                float Q01 = silu_t(pj1.z + pi1.w + bf.y);
                float Q10 = silu_t(pi0.z + pj0.w + bf.x);
                float Q11 = silu_t(pi1.z + pj1.w + bf.y);
                float E00 = silu_t(pj0.x + pi0.y + e1a.x + Q00*silu_t(cF[nt][0])) * emv;
                float E01 = silu_t(pj1.x + pi1.y + e1a.y + Q01*silu_t(cF[nt][1])) * emv;
                float E10 = silu_t(pi0.x + pj0.y + e1b.x + Q10*silu_t(cF[nt][2])) * emv;
                float E11 = silu_t(pi1.x + pj1.y + e1b.y + Q11*silu_t(cF[nt][3])) * emv;
                const int bse = (nt >> 1)*4 + (nt & 1)*2;
                split_h2(E00, E01, aUh[bse],   aUl[bse]);
                split_h2(E10, E11, aUh[bse+1], aUl[bse+1]);
            }
        }

        float cU[4][4];
        #pragma unroll
        for (int nt = 0; nt < 4; nt++)
            cU[nt][0] = cU[nt][1] = cU[nt][2] = cU[nt][3] = 0.f;
        #pragma unroll
        for (int ks = 0; ks < 4; ks++) {
            #pragma unroll
            for (int nt = 0; nt < 4; nt++) {
                uint2 Bh = bo1h[(ks*4 + nt)*32 + lane];
                uint2 Bl = bo1l[(ks*4 + nt)*32 + lane];
                mma16816(cU[nt][0], cU[nt][1], cU[nt][2], cU[nt][3],
                         aUh[ks*4+0], aUh[ks*4+1], aUh[ks*4+2], aUh[ks*4+3], Bh.x, Bh.y);
                mma16816(cU[nt][0], cU[nt][1], cU[nt][2], cU[nt][3],
                         aUl[ks*4+0], aUl[ks*4+1], aUl[ks*4+2], aUl[ks*4+3], Bh.x, Bh.y);
                mma16816(cU[nt][0], cU[nt][1], cU[nt][2], cU[nt][3],
                         aUh[ks*4+0], aUh[ks*4+1], aUh[ks*4+2], aUh[ks*4+3], Bl.x, Bl.y);
            }
        }

        float u0[4], u1[4];
        float s = 0.f;
        #pragma unroll
        for (int nt = 0; nt < 4; nt++) {
            float2 bb = *(const float2*)&sbeo1[nt*8 + 2*q];
            u0[nt] = cU[nt][0] + cU[nt][2] + bb.x;
            u1[nt] = cU[nt][1] + cU[nt][3] + bb.y;
            s += u0[nt] + u1[nt];
        }
        s += __shfl_xor_sync(0xffffffffu, s, 1);
        s += __shfl_xor_sync(0xffffffffu, s, 2);
        const float mean = s * (1.f/32.f);
        float var = 0.f;
        #pragma unroll
        for (int nt = 0; nt < 4; nt++) {
            float d0 = u0[nt] - mean, d1 = u1[nt] - mean;
            var += d0*d0 + d1*d1;
        }
        var += __shfl_xor_sync(0xffffffffu, var, 1);
        var += __shfl_xor_sync(0xffffffffu, var, 2);
        const float rstd = rsqrtf(var * (1.f/32.f) + 1e-5f);
        #pragma unroll
        for (int nt = 0; nt < 4; nt++) {
            const int ch0 = nt*8 + 2*q;
            float2 ge = *(const float2*)&sgeo[ch0];
            float2 be = *(const float2*)&sbeeo[ch0];
            float v0 = silu_t((u0[nt] - mean)*rstd*ge.x + be.x);
            float v1 = silu_t((u1[nt] - mean)*rstd*ge.y + be.y);
            *(float2*)&sv[grp*36 + ch0] = make_float2(v0, v1);
        }
        __syncwarp();

        #pragma unroll
        for (int h = 0; h < 2; h++) {
            const int pr  = h*4 + (lane >> 3);
            const int ch2 = lane & 7;
            float t = 0.f;
            #pragma unroll
            for (int k4 = 0; k4 < 8; k4++) {
                float4 vv = *(const float4*)&sv[pr*36 + k4*4];
                float4 w4 = *(const float4*)&sw_eo2T[ch2*36 + k4*4];
                t += vv.x*w4.x + vv.y*w4.y + vv.z*w4.z + vv.w*w4.w;
            }
            if (ch2 < KEdim && sact[pr]) {
                const int io = smi[pr], jo2 = smj[pr];
                float outv = (t + sbeo2[ch2]) * sem[pr];
                out_edge[((size_t)(b*Ndim + io)*Ndim + jo2)*KEdim + ch2] = outv;
                out_edge[((size_t)(b*Ndim + jo2)*Ndim + io)*KEdim + ch2] = outv;
            }
        }
        __syncwarp();
    }
}

// ---------------------------------------------------------------------------
extern "C" void kernel_launch(void* const* d_in, const int* in_sizes, int n_in,
                              void* d_out, int out_size)
{
    const float* node      = (const float*)d_in[0];
    const float* edge      = (const float*)d_in[1];
    const int*   block_id  = (const int*)d_in[2];
    const int*   vmask     = (const int*)d_in[3];
    const float* W_nt  = (const float*)d_in[4];
    const float* b_nt  = (const float*)d_in[5];
    const float* W_n1  = (const float*)d_in[6];
    const float* b_n1  = (const float*)d_in[7];
    const float* W_e1  = (const float*)d_in[8];
    const float* b_e1  = (const float*)d_in[9];
    const float* W_f1  = (const float*)d_in[10];
    const float* b_f1  = (const float*)d_in[11];
    const float* W_f2  = (const float*)d_in[12];
    const float* b_f2  = (const float*)d_in[13];
    const float* W_no1 = (const float*)d_in[14];
    const float* b_no1 = (const float*)d_in[15];
    const float* g_no  = (const float*)d_in[16];
    const float* be_no = (const float*)d_in[17];
    const float* W_no2 = (const float*)d_in[18];
    const float* b_no2 = (const float*)d_in[19];
    const float* W_eo1 = (const float*)d_in[20];
    const float* b_eo1 = (const float*)d_in[21];
    const float* g_eo  = (const float*)d_in[22];
    const float* be_eo = (const float*)d_in[23];
    const float* W_eo2 = (const float*)d_in[24];
    const float* b_eo2 = (const float*)d_in[25];

    float* out_node = (float*)d_out;                       // (B,N,KN)
    float* out_edge = (float*)d_out + Bdim*Ndim*KNdim;     // (B,N,N,KE)

    static int smem_set = 0;
    if (!smem_set) {
        cudaFuncSetAttribute(edge_kernel, cudaFuncAttributeMaxDynamicSharedMemorySize, SM_TOTAL);
        smem_set = 1;
    }

    reduce_kernel<<<Bdim*Ndim, 256>>>(edge, block_id, vmask);

    node_kernel<<<Bdim*64, 256>>>(node, block_id,
                                  W_nt, b_nt, W_n1, b_n1, W_f1,
                                  W_no1, b_no1, g_no, be_no, W_no2, b_no2,
                                  out_node);

    edge_kernel<<<Bdim*256, 256, SM_TOTAL>>>(edge, block_id, vmask,
                                   W_e1, b_e1, b_f1, W_f2, b_f2,
                                   W_eo1, b_eo1, g_eo, be_eo, W_eo2, b_eo2,
                                   out_edge);
}

// round 14
// speedup vs baseline: 2.0769x; 1.0972x over previous
#include <cuda_runtime.h>
#include <cuda_fp16.h>
#include <stdint.h>

#define Bdim 4
#define Ndim 512
#define NCdim 128
#define ECdim 32
#define OCdim 64
#define KNdim 10
#define KEdim 5
#define NIN 192   // 2*EC + NC
#define EWARPS 8
#define PX 12     // node-kernel transposed pitch

// packed per-node vectors: {n1, n2, q1, q2} per channel (float4-interleaved)
__device__ float g_pk[Bdim*Ndim*OCdim*4];
// x_in (0..31) ++ x_out (32..63) per node
__device__ float g_x[Bdim*Ndim*64];

__device__ __forceinline__ float silu_f(float x) {
    return __fdividef(x, 1.0f + __expf(-x));
}
// fast silu: x * sigmoid(x) = 0.5x(1 + tanh(x/2)); 1 MUFU
__device__ __forceinline__ float silu_t(float x) {
    float th;
    asm("tanh.approx.f32 %0, %1;" : "=f"(th) : "f"(x * 0.5f));
    return fmaf(0.5f*x, th, 0.5f*x);
}

__device__ __forceinline__ void mma16816(float& c0, float& c1, float& c2, float& c3,
                                         uint32_t a0, uint32_t a1, uint32_t a2, uint32_t a3,
                                         uint32_t b0, uint32_t b1) {
    asm volatile("mma.sync.aligned.m16n8k16.row.col.f32.f16.f16.f32 "
                 "{%0,%1,%2,%3},{%4,%5,%6,%7},{%8,%9},{%0,%1,%2,%3};\n"
                 : "+f"(c0), "+f"(c1), "+f"(c2), "+f"(c3)
                 : "r"(a0), "r"(a1), "r"(a2), "r"(a3), "r"(b0), "r"(b1));
}

// packed split: 1 F2FP for hi pair, recompute residual, 1 F2FP for lo pair
__device__ __forceinline__ void split_h2(float x, float y, uint32_t& hi, uint32_t& lo) {
    __half2 h = __float22half2_rn(make_float2(x, y));
    float2 hf = __half22float2(h);
    __half2 l = __float22half2_rn(make_float2(x - hf.x, y - hf.y));
    hi = *(uint32_t*)&h;  lo = *(uint32_t*)&l;
}

__device__ __forceinline__ float2 unpack_sum(uint32_t h, uint32_t l) {
    float2 fh = __half22float2(*(__half2*)&h);
    float2 fl = __half22float2(*(__half2*)&l);
    return make_float2(fh.x + fl.x, fh.y + fl.y);
}

// ---------------------------------------------------------------------------
// Kernel A: masked-mean reduction. Masks precomputed to smem once per block;
// hot loop = pure loads + FMA with immediate-offset addressing.
// ---------------------------------------------------------------------------
__global__ __launch_bounds__(256)
void reduce_kernel(const float* __restrict__ edge,
                   const int* __restrict__ block_id,
                   const int* __restrict__ vmask)
{
    const int bi = blockIdx.x;
    const int b  = bi / Ndim;
    const int i  = bi % Ndim;
    const int tid = threadIdx.x;

    __shared__ int    s_bid[Ndim];
    __shared__ unsigned char s_vm[Ndim];
    __shared__ float2 s_mask[Ndim];
    __shared__ float  s_red[8][64];
    __shared__ float  s_cnt[2][8];

    for (int k = tid; k < Ndim; k += 256) {
        s_bid[k] = block_id[b*Ndim + k];
        s_vm[k]  = (vmask[b*Ndim + k] != 0) ? 1 : 0;
    }
    __syncthreads();

    const int  bii  = s_bid[i];
    const bool nm_i = (bii >= 0);
    const bool vm_i = (s_vm[i] != 0);

    for (int j = tid; j < Ndim; j += 256) {
        int  bj   = s_bid[j];
        bool nm_j = (bj >= 0);
        bool pv   = nm_i && nm_j;
        bool cij  = pv && ((bii > bj) || (bii == bj && !vm_i));
        bool cji  = pv && ((bj > bii) || (bj == bii && (s_vm[j] == 0)));
        s_mask[j] = make_float2(cij ? 1.f : 0.f, cji ? 1.f : 0.f);
    }
    __syncthreads();

    const int c  = tid & 31;
    const int jl = tid >> 5;

    float acc_in0 = 0.f, acc_in1 = 0.f, acc_out0 = 0.f, acc_out1 = 0.f;
    float cnt_in = 0.f, cnt_out = 0.f;
    const float* erow = edge + ((size_t)(b*Ndim + i) * Ndim) * ECdim + c;
    const float* ecol = edge + ((size_t)b*Ndim) * Ndim * ECdim + (size_t)i*ECdim + c;

    for (int j0 = jl*4; j0 < Ndim; j0 += 32) {
        const float* er = erow + (size_t)j0*ECdim;
        const float* ec = ecol + (size_t)j0*Ndim*ECdim;
        float vin0  = er[0*ECdim],        vin1  = er[1*ECdim];
        float vin2  = er[2*ECdim],        vin3  = er[3*ECdim];
        float vout0 = ec[0],              vout1 = ec[(size_t)1*Ndim*ECdim];
        float vout2 = ec[(size_t)2*Ndim*ECdim], vout3 = ec[(size_t)3*Ndim*ECdim];
        float2 m0 = s_mask[j0+0], m1 = s_mask[j0+1];
        float2 m2 = s_mask[j0+2], m3 = s_mask[j0+3];
        acc_in0  = fmaf(vin0,  m0.x, acc_in0);
        acc_in1  = fmaf(vin1,  m1.x, acc_in1);
        acc_in0  = fmaf(vin2,  m2.x, acc_in0);
        acc_in1  = fmaf(vin3,  m3.x, acc_in1);
        acc_out0 = fmaf(vout0, m0.y, acc_out0);
        acc_out1 = fmaf(vout1, m1.y, acc_out1);
        acc_out0 = fmaf(vout2, m2.y, acc_out0);
        acc_out1 = fmaf(vout3, m3.y, acc_out1);
        cnt_in  += (m0.x + m1.x) + (m2.x + m3.x);
        cnt_out += (m0.y + m1.y) + (m2.y + m3.y);
    }
    s_red[jl][c]      = acc_in0 + acc_in1;
    s_red[jl][c + 32] = acc_out0 + acc_out1;
    if (c == 0) { s_cnt[0][jl] = cnt_in; s_cnt[1][jl] = cnt_out; }
    __syncthreads();

    if (tid < 64) {
        float s = 0.f, cnt = 0.f;
        #pragma unroll
        for (int r2 = 0; r2 < 8; r2++) { s += s_red[r2][tid]; cnt += s_cnt[tid >> 5][r2]; }
        g_x[(size_t)(b*Ndim + i)*64 + tid] = s / fmaxf(cnt, 1.f);
    }
}

// ---------------------------------------------------------------------------
// Kernel B: batched node GEMVs (round-10 winner, unchanged).
// ---------------------------------------------------------------------------
__global__ __launch_bounds__(256)
void node_kernel(const float* __restrict__ node,
                 const int* __restrict__ block_id,
                 const float* __restrict__ W_nt, const float* __restrict__ b_nt,
                 const float* __restrict__ W_n1, const float* __restrict__ b_n1,
                 const float* __restrict__ W_f1,
                 const float* __restrict__ W_no1, const float* __restrict__ b_no1,
                 const float* __restrict__ g_no, const float* __restrict__ be_no,
                 const float* __restrict__ W_no2, const float* __restrict__ b_no2,
                 float* __restrict__ out_node)
{
    const int b  = blockIdx.x >> 6;
    const int i0 = (blockIdx.x & 63) * 8;
    const int tid = threadIdx.x;
    const int w    = tid >> 5;
    const int lane = tid & 31;

    __shared__ int s_bid8[8];
    __shared__ float s_x[NIN*PX];
    __shared__ float s_hT[NCdim*PX];
    __shared__ float s_nT[NCdim*PX];
    __shared__ float s_tT[NCdim*PX];
    __shared__ float s_vT[NCdim*PX];

    if (tid < 8) s_bid8[tid] = block_id[b*Ndim + i0 + tid];
    __syncthreads();

    {
        const int i = i0 + w;
        const bool nm_i = (s_bid8[w] >= 0);
        const size_t xo = (size_t)(b*Ndim + i)*64;
        s_x[lane*PX + w]      = g_x[xo + lane];
        s_x[(lane+32)*PX + w] = g_x[xo + 32 + lane];
        float msk = nm_i ? 1.f : 0.f;
        float4 nd = *(const float4*)&node[(size_t)(b*Ndim + i)*NCdim + lane*4];
        s_x[(64 + lane*4 + 0)*PX + w] = nd.x * msk;
        s_x[(64 + lane*4 + 1)*PX + w] = nd.y * msk;
        s_x[(64 + lane*4 + 2)*PX + w] = nd.z * msk;
        s_x[(64 + lane*4 + 3)*PX + w] = nd.w * msk;
    }
    __syncthreads();

    const int o = tid & 127;
    const int g = tid >> 7;

    {
        float bb = b_nt[o];
        float4 acc = make_float4(bb, bb, bb, bb);
        #pragma unroll 4
        for (int k = 0; k < NIN; k++) {
            float wv = W_nt[k*NCdim + o];
            float4 xi = *(const float4*)&s_x[k*PX + g*4];
            acc.x += wv*xi.x; acc.y += wv*xi.y; acc.z += wv*xi.z; acc.w += wv*xi.w;
        }
        #pragma unroll
        for (int c4 = 0; c4 < 4; c4++) {
            int nn = g*4 + c4;
            float v = (c4 == 0) ? acc.x : (c4 == 1) ? acc.y : (c4 == 2) ? acc.z : acc.w;
            s_hT[o*PX + nn] = (s_bid8[nn] >= 0) ? silu_f(v) : 0.f;
        }
    }
    __syncthreads();

    {
        float bn = b_n1[o], bt = b_no1[o];
        float4 an = make_float4(bn, bn, bn, bn);
        float4 at = make_float4(bt, bt, bt, bt);
        #pragma unroll 4
        for (int k = 0; k < NCdim; k++) {
            float wn = W_n1[k*NCdim + o];
            float wt = W_no1[k*NCdim + o];
            float4 xi = *(const float4*)&s_hT[k*PX + g*4];
            an.x += wn*xi.x; an.y += wn*xi.y; an.z += wn*xi.z; an.w += wn*xi.w;
            at.x += wt*xi.x; at.y += wt*xi.y; at.z += wt*xi.z; at.w += wt*xi.w;
        }
        s_nT[o*PX + g*4+0] = an.x; s_nT[o*PX + g*4+1] = an.y;
        s_nT[o*PX + g*4+2] = an.z; s_nT[o*PX + g*4+3] = an.w;
        s_tT[o*PX + g*4+0] = at.x; s_tT[o*PX + g*4+1] = at.y;
        s_tT[o*PX + g*4+2] = at.z; s_tT[o*PX + g*4+3] = at.w;
    }
    __syncthreads();

    {
        const int oq = tid & 63;
        const int wh = (tid >> 6) & 1;
        float4 aq = make_float4(0.f, 0.f, 0.f, 0.f);
        #pragma unroll 4
        for (int k = 0; k < OCdim; k++) {
            float wq = W_f1[k*OCdim + oq];
            float4 xi = *(const float4*)&s_nT[(wh*OCdim + k)*PX + g*4];
            aq.x += wq*xi.x; aq.y += wq*xi.y; aq.z += wq*xi.z; aq.w += wq*xi.w;
        }
        #pragma unroll
        for (int c4 = 0; c4 < 4; c4++) {
            int nn = g*4 + c4;
            float qv = (c4 == 0) ? aq.x : (c4 == 1) ? aq.y : (c4 == 2) ? aq.z : aq.w;
            size_t base = ((size_t)(b*Ndim + i0 + nn)*OCdim + oq)*4;
            g_pk[base + wh]     = s_nT[(wh*OCdim + oq)*PX + nn];
            g_pk[base + 2 + wh] = qv;
        }
    }

    {
        float tv0 = s_tT[lane*PX + w];
        float tv1 = s_tT[(lane+32)*PX + w];
        float tv2 = s_tT[(lane+64)*PX + w];
        float tv3 = s_tT[(lane+96)*PX + w];
        float s = tv0 + tv1 + tv2 + tv3;
        #pragma unroll
        for (int o2 = 16; o2; o2 >>= 1) s += __shfl_xor_sync(0xffffffffu, s, o2);
        float mean = s * (1.f/NCdim);
        float d0 = tv0-mean, d1 = tv1-mean, d2 = tv2-mean, d3 = tv3-mean;
        float var = d0*d0 + d1*d1 + d2*d2 + d3*d3;
        #pragma unroll
        for (int o2 = 16; o2; o2 >>= 1) var += __shfl_xor_sync(0xffffffffu, var, o2);
        float rstd = rsqrtf(var * (1.f/NCdim) + 1e-5f);
        s_vT[lane*PX + w]      = silu_f(d0*rstd*g_no[lane]    + be_no[lane]);
        s_vT[(lane+32)*PX + w] = silu_f(d1*rstd*g_no[lane+32] + be_no[lane+32]);
        s_vT[(lane+64)*PX + w] = silu_f(d2*rstd*g_no[lane+64] + be_no[lane+64]);
        s_vT[(lane+96)*PX + w] = silu_f(d3*rstd*g_no[lane+96] + be_no[lane+96]);
    }
    __syncthreads();

    if (lane < KNdim) {
        float a = b_no2[lane];
        #pragma unroll 4
        for (int k = 0; k < NCdim; k++)
            a += s_vT[k*PX + w] * W_no2[k*KNdim + lane];
        bool nm_i = (s_bid8[w] >= 0);
        out_node[(size_t)(b*Ndim + i0 + w)*KNdim + lane] = nm_i ? a : 0.f;
    }
}

// ---------------------------------------------------------------------------
// Kernel 2: edge work. Two-term compensated MMA (Ah*Bh + Al*Bh — weights fp16)
// for e1/f2/eo1; Bl arrays removed. smem ~33KB.
// ---------------------------------------------------------------------------
#define SM_KEY     0
#define SM_BE1B    2048
#define SM_BF2B    2304
#define SM_BF1     2560
#define SM_NIPK    2816
#define SM_BEO1    4864
#define SM_GEO     4992
#define SM_BEEO    5120
#define SM_BEO2    5248
#define SM_EO2T    5296      // 8*36 f -> ends 6448
#define SM_BE1H    6448      // 512 uint2 -> 10544
#define SM_BF2H    10544     // 1024 uint2 -> 18736
#define SM_BO1H    18736     // 512 uint2 -> 22832
#define SM_WARP    22832
#define SM_PERW    1280
#define SM_TOTAL   (SM_WARP + EWARPS*SM_PERW)   // 33072

__global__ __launch_bounds__(256, 2)
void edge_kernel(const float* __restrict__ edge,
                 const int* __restrict__ block_id,
                 const int* __restrict__ vmask,
                 const float* __restrict__ W_e1, const float* __restrict__ b_e1,
                 const float* __restrict__ b_f1,
                 const float* __restrict__ W_f2, const float* __restrict__ b_f2,
                 const float* __restrict__ W_eo1, const float* __restrict__ b_eo1,
                 const float* __restrict__ g_eo, const float* __restrict__ be_eo,
                 const float* __restrict__ W_eo2, const float* __restrict__ b_eo2,
                 float* __restrict__ out_edge)
{
    extern __shared__ char dsm[];
    const int b = blockIdx.x >> 8;
    const int r = blockIdx.x & 255;
    const int tid  = threadIdx.x;
    const int w    = tid >> 5;
    const int lane = tid & 31;
    const int grp  = lane >> 2;
    const int q    = lane & 3;

    int*    s_key  = (int*)(dsm + SM_KEY);
    float*  sbe1b  = (float*)(dsm + SM_BE1B);
    float*  sbf2b  = (float*)(dsm + SM_BF2B);
    float*  sbF1   = (float*)(dsm + SM_BF1);
    float4* s_nipk = (float4*)(dsm + SM_NIPK);
    float*  sbeo1  = (float*)(dsm + SM_BEO1);
    float*  sgeo   = (float*)(dsm + SM_GEO);
    float*  sbeeo  = (float*)(dsm + SM_BEEO);
    float*  sbeo2  = (float*)(dsm + SM_BEO2);
    float*  sw_eo2T = (float*)(dsm + SM_EO2T);
    uint2*  be1h   = (uint2*)(dsm + SM_BE1H);
    uint2*  bf2h   = (uint2*)(dsm + SM_BF2H);
    uint2*  bo1h   = (uint2*)(dsm + SM_BO1H);

    char*  wbase = dsm + SM_WARP + w*SM_PERW;
    float* sv    = (float*)wbase;            // [8][36]
    int*   smi   = (int*)(wbase + 1152);
    int*   smj   = smi + 8;
    float* sem   = (float*)(smi + 16);
    int*   sact  = smi + 24;

    const int i_a = r, i_b = Ndim - 1 - r;

    for (int k = tid; k < Ndim; k += 256)
        s_key[k] = block_id[b*Ndim + k]*2 + ((vmask[b*Ndim + k] != 0) ? 1 : 0);
    if (tid < 64)  sbe1b[tid] = b_e1[tid];
    if (tid >= 64 && tid < 128)  sbf2b[tid-64] = b_f2[tid-64];
    if (tid >= 128 && tid < 192) sbF1[tid-128] = b_f1[tid-128];
    if (tid >= 192 && tid < 224) sbeo1[tid-192] = b_eo1[tid-192];
    if (tid >= 224 && tid < 256) sgeo[tid-224] = g_eo[tid-224];
    if (tid < 32)  sbeeo[tid] = be_eo[tid];
    if (tid >= 32 && tid < 40) sbeo2[tid-32] = b_eo2[tid-32];
    if (tid >= 40 && tid < 168) {
        int k = tid - 40;
        int row = k >> 6, ch = k & 63;
        int irow = row ? i_b : i_a;
        s_nipk[k] = *(const float4*)&g_pk[((size_t)(b*Ndim + irow)*OCdim + ch)*4];
    }
    for (int k = tid; k < 8*36; k += 256) {
        int ch = k / 36, kk = k % 36;
        sw_eo2T[k] = (ch < KEdim && kk < ECdim) ? W_eo2[kk*KEdim + ch] : 0.f;
    }
    for (int e = tid; e < 512; e += 256) {
        int lane_ = e & 31, nt = (e >> 5) & 7, ks = e >> 8;
        int q_ = lane_ & 3, g_ = lane_ >> 2;
        int k0 = ks*16 + 2*q_;
        int n  = nt*8 + g_;
        __half2 h0 = __float22half2_rn(make_float2(W_e1[k0*OCdim + n],     W_e1[(k0+1)*OCdim + n]));
        __half2 h1 = __float22half2_rn(make_float2(W_e1[(k0+8)*OCdim + n], W_e1[(k0+9)*OCdim + n]));
        be1h[e] = make_uint2(*(uint32_t*)&h0, *(uint32_t*)&h1);
    }
    for (int e = tid; e < 1024; e += 256) {
        int lane_ = e & 31, nt = (e >> 5) & 7, ks = e >> 8;
        int q_ = lane_ & 3, g_ = lane_ >> 2;
        int k0 = ks*16 + 2*q_;
        int n  = nt*8 + g_;
        __half2 h0 = __float22half2_rn(make_float2(W_f2[k0*OCdim + n],     W_f2[(k0+1)*OCdim + n]));
        __half2 h1 = __float22half2_rn(make_float2(W_f2[(k0+8)*OCdim + n], W_f2[(k0+9)*OCdim + n]));
        bf2h[e] = make_uint2(*(uint32_t*)&h0, *(uint32_t*)&h1);
    }
    for (int e = tid; e < 512; e += 256) {
        int lane_ = e & 31, nt = (e >> 5) & 3, ks = e >> 7;
        int q_ = lane_ & 3, g_ = lane_ >> 2;
        int k0 = ks*16 + 2*q_;
        int n  = nt*8 + g_;
        __half2 h0 = __float22half2_rn(make_float2(W_eo1[k0*32 + n],     W_eo1[(k0+1)*32 + n]));
        __half2 h1 = __float22half2_rn(make_float2(W_eo1[(k0+8)*32 + n], W_eo1[(k0+9)*32 + n]));
        bo1h[e] = make_uint2(*(uint32_t*)&h0, *(uint32_t*)&h1);
    }
    __syncthreads();

    const int npa   = Ndim - i_a;
    const int total = Ndim + 1;

    for (int base = w*8; base < total; base += EWARPS*8) {
        if (lane < 8) {
            int p = base + lane;
            int act = (p < total) ? 1 : 0;
            int pc = act ? p : 0;
            bool aA = pc < npa;
            int i2 = aA ? i_a : i_b;
            int j2 = aA ? (i_a + pc) : (i_b + (pc - npa));
            int ki = s_key[i2], kj = s_key[j2];
            int bi_ = ki >> 1, bj_ = kj >> 1;
            bool nm2 = (bi_ >= 0) && (bj_ >= 0);
            bool cij = (bi_ > bj_) || (bi_ == bj_ && !(ki & 1));
            bool cji = (bj_ > bi_) || (bj_ == bi_ && !(kj & 1));
            smi[lane] = i2; smj[lane] = j2;
            sem[lane] = (nm2 && (cij || cji)) ? 1.f : 0.f;
            sact[lane] = act;
        }
        __syncwarp();

        const int   i2  = smi[grp];
        const int   j2  = smj[grp];
        const float emv = sem[grp];
        const bool  isA = (i2 == i_a);

        uint32_t aEh[8], aEl[8];
        {
            const float* eij = edge + ((size_t)(b*Ndim + i2)*Ndim + j2)*ECdim;
            const float* eji = edge + ((size_t)(b*Ndim + j2)*Ndim + i2)*ECdim;
            #pragma unroll
            for (int ks = 0; ks < 2; ks++) {
                float2 v0 = *(const float2*)(eij + ks*16 + 2*q);
                float2 v1 = *(const float2*)(eji + ks*16 + 2*q);
                float2 v2 = *(const float2*)(eij + ks*16 + 8 + 2*q);
                float2 v3 = *(const float2*)(eji + ks*16 + 8 + 2*q);
                split_h2(v0.x*emv, v0.y*emv, aEh[ks*4+0], aEl[ks*4+0]);
                split_h2(v1.x*emv, v1.y*emv, aEh[ks*4+1], aEl[ks*4+1]);
                split_h2(v2.x*emv, v2.y*emv, aEh[ks*4+2], aEl[ks*4+2]);
                split_h2(v3.x*emv, v3.y*emv, aEh[ks*4+3], aEl[ks*4+3]);
            }
        }

        float cE[8][4];
        #pragma unroll
        for (int nt = 0; nt < 8; nt++) {
            float2 bb = *(const float2*)&sbe1b[nt*8 + 2*q];
            cE[nt][0] = bb.x; cE[nt][1] = bb.y; cE[nt][2] = bb.x; cE[nt][3] = bb.y;
        }
        #pragma unroll
        for (int ks = 0; ks < 2; ks++) {
            #pragma unroll
            for (int nt = 0; nt < 8; nt++) {
                uint2 Bh = be1h[(ks*8 + nt)*32 + lane];
                mma16816(cE[nt][0], cE[nt][1], cE[nt][2], cE[nt][3],
                         aEh[ks*4+0], aEh[ks*4+1], aEh[ks*4+2], aEh[ks*4+3], Bh.x, Bh.y);
                mma16816(cE[nt][0], cE[nt][1], cE[nt][2], cE[nt][3],
                         aEl[ks*4+0], aEl[ks*4+1], aEl[ks*4+2], aEl[ks*4+3], Bh.x, Bh.y);
            }
        }

        uint32_t e1h[16], e1l[16];
        #pragma unroll
        for (int ks = 0; ks < 4; ks++) {
            split_h2(cE[2*ks][0],   cE[2*ks][1],   e1h[ks*4+0], e1l[ks*4+0]);
            split_h2(cE[2*ks][2],   cE[2*ks][3],   e1h[ks*4+1], e1l[ks*4+1]);
            split_h2(cE[2*ks+1][0], cE[2*ks+1][1], e1h[ks*4+2], e1l[ks*4+2]);
            split_h2(cE[2*ks+1][2], cE[2*ks+1][3], e1h[ks*4+3], e1l[ks*4+3]);
        }

        float cF[8][4];
        #pragma unroll
        for (int nt = 0; nt < 8; nt++) {
            float2 bb = *(const float2*)&sbf2b[nt*8 + 2*q];
            cF[nt][0] = bb.x; cF[nt][1] = bb.y; cF[nt][2] = bb.x; cF[nt][3] = bb.y;
        }
        #pragma unroll
        for (int ks = 0; ks < 4; ks++) {
            #pragma unroll
            for (int nt = 0; nt < 8; nt++) {
                uint2 Bh = bf2h[(ks*8 + nt)*32 + lane];
                mma16816(cF[nt][0], cF[nt][1], cF[nt][2], cF[nt][3],
                         e1h[ks*4+0], e1h[ks*4+1], e1h[ks*4+2], e1h[ks*4+3], Bh.x, Bh.y);
                mma16816(cF[nt][0], cF[nt][1], cF[nt][2], cF[nt][3],
                         e1l[ks*4+0], e1l[ks*4+1], e1l[ks*4+2], e1l[ks*4+3], Bh.x, Bh.y);
            }
        }

        uint32_t aUh[16], aUl[16];
        {
            const float4* gpk = (const float4*)g_pk;
            const size_t jo = (size_t)(b*Ndim + j2)*OCdim;
            const int    ib = isA ? 0 : 64;
            #pragma unroll
            for (int nt = 0; nt < 8; nt++) {
                const int ch0 = nt*8 + 2*q;
                const int ksi = (nt >> 1)*4 + (nt & 1)*2;
                float2 e1a = unpack_sum(e1h[ksi],   e1l[ksi]);
                float2 e1b = unpack_sum(e1h[ksi+1], e1l[ksi+1]);
                float4 pj0 = gpk[jo + ch0];
                float4 pj1 = gpk[jo + ch0 + 1];
                float4 pi0 = s_nipk[ib + ch0];
                float4 pi1 = s_nipk[ib + ch0 + 1];
                float2 bf  = *(const float2*)&sbF1[ch0];
                float Q00 = silu_t(pj0.z + pi0.w + bf.x);
                float Q01 = silu_t(pj1.z + pi1.w + bf.y);
                float Q10 = silu_t(pi0.z + pj0.w + bf.x);
                float Q11 = silu_t(pi1.z + pj1.w + bf.y);
                float E00 = silu_t(pj0.x + pi0.y + e1a.x + Q00*silu_t(cF[nt][0])) * emv;
                float E01 = silu_t(pj1.x + pi1.y + e1a.y + Q01*silu_t(cF[nt][1])) * emv;
                float E10 = silu_t(pi0.x + pj0.y + e1b.x + Q10*silu_t(cF[nt][2])) * emv;
                float E11 = silu_t(pi1.x + pj1.y + e1b.y + Q11*silu_t(cF[nt][3])) * emv;
                const int bse = (nt >> 1)*4 + (nt & 1)*2;
                split_h2(E00, E01, aUh[bse],   aUl[bse]);
                split_h2(E10, E11, aUh[bse+1], aUl[bse+1]);
            }
        }

        float cU[4][4];
        #pragma unroll
        for (int nt = 0; nt < 4; nt++)
            cU[nt][0] = cU[nt][1] = cU[nt][2] = cU[nt][3] = 0.f;
        #pragma unroll
        for (int ks = 0; ks < 4; ks++) {
            #pragma unroll
            for (int nt = 0; nt < 4; nt++) {
                uint2 Bh = bo1h[(ks*4 + nt)*32 + lane];
                mma16816(cU[nt][0], cU[nt][1], cU[nt][2], cU[nt][3],
                         aUh[ks*4+0], aUh[ks*4+1], aUh[ks*4+2], aUh[ks*4+3], Bh.x, Bh.y);
                mma16816(cU[nt][0], cU[nt][1], cU[nt][2], cU[nt][3],
                         aUl[ks*4+0], aUl[ks*4+1], aUl[ks*4+2], aUl[ks*4+3], Bh.x, Bh.y);
            }
        }

        float u0[4], u1[4];
        float s = 0.f;
        #pragma unroll
        for (int nt = 0; nt < 4; nt++) {
            float2 bb = *(const float2*)&sbeo1[nt*8 + 2*q];
            u0[nt] = cU[nt][0] + cU[nt][2] + bb.x;
            u1[nt] = cU[nt][1] + cU[nt][3] + bb.y;
            s += u0[nt] + u1[nt];
        }
        s += __shfl_xor_sync(0xffffffffu, s, 1);
        s += __shfl_xor_sync(0xffffffffu, s, 2);
        const float mean = s * (1.f/32.f);
        float var = 0.f;
        #pragma unroll
        for (int nt = 0; nt < 4; nt++) {
            float d0 = u0[nt] - mean, d1 = u1[nt] - mean;
            var += d0*d0 + d1*d1;
        }
        var += __shfl_xor_sync(0xffffffffu, var, 1);
        var += __shfl_xor_sync(0xffffffffu, var, 2);
        const float rstd = rsqrtf(var * (1.f/32.f) + 1e-5f);
        #pragma unroll
        for (int nt = 0; nt < 4; nt++) {
            const int ch0 = nt*8 + 2*q;
            float2 ge = *(const float2*)&sgeo[ch0];
            float2 be = *(const float2*)&sbeeo[ch0];
            float v0 = silu_t((u0[nt] - mean)*rstd*ge.x + be.x);
            float v1 = silu_t((u1[nt] - mean)*rstd*ge.y + be.y);
            *(float2*)&sv[grp*36 + ch0] = make_float2(v0, v1);
        }
        __syncwarp();

        #pragma unroll
        for (int h = 0; h < 2; h++) {
            const int pr  = h*4 + (lane >> 3);
            const int ch2 = lane & 7;
            float t = 0.f;
            #pragma unroll
            for (int k4 = 0; k4 < 8; k4++) {
                float4 vv = *(const float4*)&sv[pr*36 + k4*4];
                float4 w4 = *(const float4*)&sw_eo2T[ch2*36 + k4*4];
                t += vv.x*w4.x + vv.y*w4.y + vv.z*w4.z + vv.w*w4.w;
            }
            if (ch2 < KEdim && sact[pr]) {
                const int io = smi[pr], jo2 = smj[pr];
                float outv = (t + sbeo2[ch2]) * sem[pr];
                out_edge[((size_t)(b*Ndim + io)*Ndim + jo2)*KEdim + ch2] = outv;
                out_edge[((size_t)(b*Ndim + jo2)*Ndim + io)*KEdim + ch2] = outv;
            }
        }
        __syncwarp();
    }
}

// ---------------------------------------------------------------------------
extern "C" void kernel_launch(void* const* d_in, const int* in_sizes, int n_in,
                              void* d_out, int out_size)
{
    const float* node      = (const float*)d_in[0];
    const float* edge      = (const float*)d_in[1];
    const int*   block_id  = (const int*)d_in[2];
    const int*   vmask     = (const int*)d_in[3];
    const float* W_nt  = (const float*)d_in[4];
    const float* b_nt  = (const float*)d_in[5];
    const float* W_n1  = (const float*)d_in[6];
    const float* b_n1  = (const float*)d_in[7];
    const float* W_e1  = (const float*)d_in[8];
    const float* b_e1  = (const float*)d_in[9];
    const float* W_f1  = (const float*)d_in[10];
    const float* b_f1  = (const float*)d_in[11];
    const float* W_f2  = (const float*)d_in[12];
    const float* b_f2  = (const float*)d_in[13];
    const float* W_no1 = (const float*)d_in[14];
    const float* b_no1 = (const float*)d_in[15];
    const float* g_no  = (const float*)d_in[16];
    const float* be_no = (const float*)d_in[17];
    const float* W_no2 = (const float*)d_in[18];
    const float* b_no2 = (const float*)d_in[19];
    const float* W_eo1 = (const float*)d_in[20];
    const float* b_eo1 = (const float*)d_in[21];
    const float* g_eo  = (const float*)d_in[22];
    const float* be_eo = (const float*)d_in[23];
    const float* W_eo2 = (const float*)d_in[24];
    const float* b_eo2 = (const float*)d_in[25];

    float* out_node = (float*)d_out;                       // (B,N,KN)
    float* out_edge = (float*)d_out + Bdim*Ndim*KNdim;     // (B,N,N,KE)

    static int smem_set = 0;
    if (!smem_set) {
        cudaFuncSetAttribute(edge_kernel, cudaFuncAttributeMaxDynamicSharedMemorySize, SM_TOTAL);
        smem_set = 1;
    }

    reduce_kernel<<<Bdim*Ndim, 256>>>(edge, block_id, vmask);

    node_kernel<<<Bdim*64, 256>>>(node, block_id,
                                  W_nt, b_nt, W_n1, b_n1, W_f1,
                                  W_no1, b_no1, g_no, be_no, W_no2, b_no2,
                                  out_node);

    edge_kernel<<<Bdim*256, 256, SM_TOTAL>>>(edge, block_id, vmask,
                                   W_e1, b_e1, b_f1, W_f2, b_f2,
                                   W_eo1, b_eo1, g_eo, be_eo, W_eo2, b_eo2,
                                   out_edge);
}

// round 15
// speedup vs baseline: 2.0935x; 1.0080x over previous
#include <cuda_runtime.h>
#include <cuda_fp16.h>
#include <stdint.h>

#define Bdim 4
#define Ndim 512
#define NCdim 128
#define ECdim 32
#define OCdim 64
#define KNdim 10
#define KEdim 5
#define NIN 192   // 2*EC + NC
#define EWARPS 8
#define PX 12     // node-kernel transposed pitch

// packed per-node vectors: {n1, n2, q1, q2} per channel (float4-interleaved)
__device__ float g_pk[Bdim*Ndim*OCdim*4];
// x_in (0..31) ++ x_out (32..63) per node
__device__ float g_x[Bdim*Ndim*64];

__device__ __forceinline__ float silu_f(float x) {
    return __fdividef(x, 1.0f + __expf(-x));
}
// fast silu: x * sigmoid(x) = 0.5x(1 + tanh(x/2)); 1 MUFU
__device__ __forceinline__ float silu_t(float x) {
    float th;
    asm("tanh.approx.f32 %0, %1;" : "=f"(th) : "f"(x * 0.5f));
    return fmaf(0.5f*x, th, 0.5f*x);
}

__device__ __forceinline__ void mma16816(float& c0, float& c1, float& c2, float& c3,
                                         uint32_t a0, uint32_t a1, uint32_t a2, uint32_t a3,
                                         uint32_t b0, uint32_t b1) {
    asm volatile("mma.sync.aligned.m16n8k16.row.col.f32.f16.f16.f32 "
                 "{%0,%1,%2,%3},{%4,%5,%6,%7},{%8,%9},{%0,%1,%2,%3};\n"
                 : "+f"(c0), "+f"(c1), "+f"(c2), "+f"(c3)
                 : "r"(a0), "r"(a1), "r"(a2), "r"(a3), "r"(b0), "r"(b1));
}

__device__ __forceinline__ void split_h2(float x, float y, uint32_t& hi, uint32_t& lo) {
    __half2 h = __float22half2_rn(make_float2(x, y));
    float2 hf = __half22float2(h);
    __half2 l = __float22half2_rn(make_float2(x - hf.x, y - hf.y));
    hi = *(uint32_t*)&h;  lo = *(uint32_t*)&l;
}

__device__ __forceinline__ float2 unpack_sum(uint32_t h, uint32_t l) {
    float2 fh = __half22float2(*(__half2*)&h);
    float2 fl = __half22float2(*(__half2*)&l);
    return make_float2(fh.x + fl.x, fh.y + fl.y);
}

// ---------------------------------------------------------------------------
// Kernel A: masked-mean reduction. 8-wide unroll: 16 LDGs in flight per warp.
// ---------------------------------------------------------------------------
__global__ __launch_bounds__(256)
void reduce_kernel(const float* __restrict__ edge,
                   const int* __restrict__ block_id,
                   const int* __restrict__ vmask)
{
    const int bi = blockIdx.x;
    const int b  = bi / Ndim;
    const int i  = bi % Ndim;
    const int tid = threadIdx.x;

    __shared__ int    s_bid[Ndim];
    __shared__ unsigned char s_vm[Ndim];
    __shared__ float2 s_mask[Ndim];
    __shared__ float  s_red[8][64];
    __shared__ float  s_cnt[2][8];

    for (int k = tid; k < Ndim; k += 256) {
        s_bid[k] = block_id[b*Ndim + k];
        s_vm[k]  = (vmask[b*Ndim + k] != 0) ? 1 : 0;
    }
    __syncthreads();

    const int  bii  = s_bid[i];
    const bool nm_i = (bii >= 0);
    const bool vm_i = (s_vm[i] != 0);

    for (int j = tid; j < Ndim; j += 256) {
        int  bj   = s_bid[j];
        bool nm_j = (bj >= 0);
        bool pv   = nm_i && nm_j;
        bool cij  = pv && ((bii > bj) || (bii == bj && !vm_i));
        bool cji  = pv && ((bj > bii) || (bj == bii && (s_vm[j] == 0)));
        s_mask[j] = make_float2(cij ? 1.f : 0.f, cji ? 1.f : 0.f);
    }
    __syncthreads();

    const int c  = tid & 31;
    const int jl = tid >> 5;

    float acc_in0 = 0.f, acc_in1 = 0.f, acc_out0 = 0.f, acc_out1 = 0.f;
    float cnt_in = 0.f, cnt_out = 0.f;
    const float* erow = edge + ((size_t)(b*Ndim + i) * Ndim) * ECdim + c;
    const float* ecol = edge + ((size_t)b*Ndim) * Ndim * ECdim + (size_t)i*ECdim + c;

    for (int j0 = jl*8; j0 < Ndim; j0 += 64) {
        const float* er = erow + (size_t)j0*ECdim;
        const float* ec = ecol + (size_t)j0*Ndim*ECdim;
        float vin[8], vout[8];
        #pragma unroll
        for (int u = 0; u < 8; u++) {
            vin[u]  = er[(size_t)u*ECdim];
            vout[u] = ec[(size_t)u*Ndim*ECdim];
        }
        #pragma unroll
        for (int u = 0; u < 8; u += 2) {
            float2 m0 = s_mask[j0+u], m1 = s_mask[j0+u+1];
            acc_in0  = fmaf(vin[u],    m0.x, acc_in0);
            acc_in1  = fmaf(vin[u+1],  m1.x, acc_in1);
            acc_out0 = fmaf(vout[u],   m0.y, acc_out0);
            acc_out1 = fmaf(vout[u+1], m1.y, acc_out1);
            cnt_in  += m0.x + m1.x;
            cnt_out += m0.y + m1.y;
        }
    }
    s_red[jl][c]      = acc_in0 + acc_in1;
    s_red[jl][c + 32] = acc_out0 + acc_out1;
    if (c == 0) { s_cnt[0][jl] = cnt_in; s_cnt[1][jl] = cnt_out; }
    __syncthreads();

    if (tid < 64) {
        float s = 0.f, cnt = 0.f;
        #pragma unroll
        for (int r2 = 0; r2 < 8; r2++) { s += s_red[r2][tid]; cnt += s_cnt[tid >> 5][r2]; }
        g_x[(size_t)(b*Ndim + i)*64 + tid] = s / fmaxf(cnt, 1.f);
    }
}

// ---------------------------------------------------------------------------
// Kernel B: batched node GEMVs (unchanged winner).
// ---------------------------------------------------------------------------
__global__ __launch_bounds__(256)
void node_kernel(const float* __restrict__ node,
                 const int* __restrict__ block_id,
                 const float* __restrict__ W_nt, const float* __restrict__ b_nt,
                 const float* __restrict__ W_n1, const float* __restrict__ b_n1,
                 const float* __restrict__ W_f1,
                 const float* __restrict__ W_no1, const float* __restrict__ b_no1,
                 const float* __restrict__ g_no, const float* __restrict__ be_no,
                 const float* __restrict__ W_no2, const float* __restrict__ b_no2,
                 float* __restrict__ out_node)
{
    const int b  = blockIdx.x >> 6;
    const int i0 = (blockIdx.x & 63) * 8;
    const int tid = threadIdx.x;
    const int w    = tid >> 5;
    const int lane = tid & 31;

    __shared__ int s_bid8[8];
    __shared__ float s_x[NIN*PX];
    __shared__ float s_hT[NCdim*PX];
    __shared__ float s_nT[NCdim*PX];
    __shared__ float s_tT[NCdim*PX];
    __shared__ float s_vT[NCdim*PX];

    if (tid < 8) s_bid8[tid] = block_id[b*Ndim + i0 + tid];
    __syncthreads();

    {
        const int i = i0 + w;
        const bool nm_i = (s_bid8[w] >= 0);
        const size_t xo = (size_t)(b*Ndim + i)*64;
        s_x[lane*PX + w]      = g_x[xo + lane];
        s_x[(lane+32)*PX + w] = g_x[xo + 32 + lane];
        float msk = nm_i ? 1.f : 0.f;
        float4 nd = *(const float4*)&node[(size_t)(b*Ndim + i)*NCdim + lane*4];
        s_x[(64 + lane*4 + 0)*PX + w] = nd.x * msk;
        s_x[(64 + lane*4 + 1)*PX + w] = nd.y * msk;
        s_x[(64 + lane*4 + 2)*PX + w] = nd.z * msk;
        s_x[(64 + lane*4 + 3)*PX + w] = nd.w * msk;
    }
    __syncthreads();

    const int o = tid & 127;
    const int g = tid >> 7;

    {
        float bb = b_nt[o];
        float4 acc = make_float4(bb, bb, bb, bb);
        #pragma unroll 4
        for (int k = 0; k < NIN; k++) {
            float wv = W_nt[k*NCdim + o];
            float4 xi = *(const float4*)&s_x[k*PX + g*4];
            acc.x += wv*xi.x; acc.y += wv*xi.y; acc.z += wv*xi.z; acc.w += wv*xi.w;
        }
        #pragma unroll
        for (int c4 = 0; c4 < 4; c4++) {
            int nn = g*4 + c4;
            float v = (c4 == 0) ? acc.x : (c4 == 1) ? acc.y : (c4 == 2) ? acc.z : acc.w;
            s_hT[o*PX + nn] = (s_bid8[nn] >= 0) ? silu_f(v) : 0.f;
        }
    }
    __syncthreads();

    {
        float bn = b_n1[o], bt = b_no1[o];
        float4 an = make_float4(bn, bn, bn, bn);
        float4 at = make_float4(bt, bt, bt, bt);
        #pragma unroll 4
        for (int k = 0; k < NCdim; k++) {
            float wn = W_n1[k*NCdim + o];
            float wt = W_no1[k*NCdim + o];
            float4 xi = *(const float4*)&s_hT[k*PX + g*4];
            an.x += wn*xi.x; an.y += wn*xi.y; an.z += wn*xi.z; an.w += wn*xi.w;
            at.x += wt*xi.x; at.y += wt*xi.y; at.z += wt*xi.z; at.w += wt*xi.w;
        }
        s_nT[o*PX + g*4+0] = an.x; s_nT[o*PX + g*4+1] = an.y;
        s_nT[o*PX + g*4+2] = an.z; s_nT[o*PX + g*4+3] = an.w;
        s_tT[o*PX + g*4+0] = at.x; s_tT[o*PX + g*4+1] = at.y;
        s_tT[o*PX + g*4+2] = at.z; s_tT[o*PX + g*4+3] = at.w;
    }
    __syncthreads();

    {
        const int oq = tid & 63;
        const int wh = (tid >> 6) & 1;
        float4 aq = make_float4(0.f, 0.f, 0.f, 0.f);
        #pragma unroll 4
        for (int k = 0; k < OCdim; k++) {
            float wq = W_f1[k*OCdim + oq];
            float4 xi = *(const float4*)&s_nT[(wh*OCdim + k)*PX + g*4];
            aq.x += wq*xi.x; aq.y += wq*xi.y; aq.z += wq*xi.z; aq.w += wq*xi.w;
        }
        #pragma unroll
        for (int c4 = 0; c4 < 4; c4++) {
            int nn = g*4 + c4;
            float qv = (c4 == 0) ? aq.x : (c4 == 1) ? aq.y : (c4 == 2) ? aq.z : aq.w;
            size_t base = ((size_t)(b*Ndim + i0 + nn)*OCdim + oq)*4;
            g_pk[base + wh]     = s_nT[(wh*OCdim + oq)*PX + nn];
            g_pk[base + 2 + wh] = qv;
        }
    }

    {
        float tv0 = s_tT[lane*PX + w];
        float tv1 = s_tT[(lane+32)*PX + w];
        float tv2 = s_tT[(lane+64)*PX + w];
        float tv3 = s_tT[(lane+96)*PX + w];
        float s = tv0 + tv1 + tv2 + tv3;
        #pragma unroll
        for (int o2 = 16; o2; o2 >>= 1) s += __shfl_xor_sync(0xffffffffu, s, o2);
        float mean = s * (1.f/NCdim);
        float d0 = tv0-mean, d1 = tv1-mean, d2 = tv2-mean, d3 = tv3-mean;
        float var = d0*d0 + d1*d1 + d2*d2 + d3*d3;
        #pragma unroll
        for (int o2 = 16; o2; o2 >>= 1) var += __shfl_xor_sync(0xffffffffu, var, o2);
        float rstd = rsqrtf(var * (1.f/NCdim) + 1e-5f);
        s_vT[lane*PX + w]      = silu_f(d0*rstd*g_no[lane]    + be_no[lane]);
        s_vT[(lane+32)*PX + w] = silu_f(d1*rstd*g_no[lane+32] + be_no[lane+32]);
        s_vT[(lane+64)*PX + w] = silu_f(d2*rstd*g_no[lane+64] + be_no[lane+64]);
        s_vT[(lane+96)*PX + w] = silu_f(d3*rstd*g_no[lane+96] + be_no[lane+96]);
    }
    __syncthreads();

    if (lane < KNdim) {
        float a = b_no2[lane];
        #pragma unroll 4
        for (int k = 0; k < NCdim; k++)
            a += s_vT[k*PX + w] * W_no2[k*KNdim + lane];
        bool nm_i = (s_bid8[w] >= 0);
        out_node[(size_t)(b*Ndim + i0 + w)*KNdim + lane] = nm_i ? a : 0.f;
    }
}

// ---------------------------------------------------------------------------
// Kernel 2: edge work. Row pairing (m+1, 511-m) -> exactly 512 pairs/block
// (rows 0 and 256 get dedicated blocks): every warp runs exact iterations,
// no 9th-iteration straggler. grid = Bdim*257.
// ---------------------------------------------------------------------------
#define SM_KEY     0
#define SM_BE1B    2048
#define SM_BF2B    2304
#define SM_BF1     2560
#define SM_NIPK    2816
#define SM_BEO1    4864
#define SM_GEO     4992
#define SM_BEEO    5120
#define SM_BEO2    5248
#define SM_EO2T    5296
#define SM_BE1H    6448
#define SM_BF2H    10544
#define SM_BO1H    18736
#define SM_WARP    22832
#define SM_PERW    1280
#define SM_TOTAL   (SM_WARP + EWARPS*SM_PERW)   // 33072

__global__ __launch_bounds__(256, 2)
void edge_kernel(const float* __restrict__ edge,
                 const int* __restrict__ block_id,
                 const int* __restrict__ vmask,
                 const float* __restrict__ W_e1, const float* __restrict__ b_e1,
                 const float* __restrict__ b_f1,
                 const float* __restrict__ W_f2, const float* __restrict__ b_f2,
                 const float* __restrict__ W_eo1, const float* __restrict__ b_eo1,
                 const float* __restrict__ g_eo, const float* __restrict__ be_eo,
                 const float* __restrict__ W_eo2, const float* __restrict__ b_eo2,
                 float* __restrict__ out_edge)
{
    extern __shared__ char dsm[];
    const int b = blockIdx.x / 257;
    const int m = blockIdx.x % 257;
    const int tid  = threadIdx.x;
    const int w    = tid >> 5;
    const int lane = tid & 31;
    const int grp  = lane >> 2;
    const int q    = lane & 3;

    // row pairing: m<255 -> rows (m+1, 511-m) = 512 pairs; m==255 -> row 0
    // (512 pairs); m==256 -> row 256 (256 pairs).
    int i_a, i_b;
    if (m < 255)      { i_a = m + 1; i_b = 511 - m; }
    else if (m == 255){ i_a = 0;     i_b = 0;       }
    else              { i_a = 256;   i_b = 256;     }
    const int npa   = Ndim - i_a;
    const int total = (m < 255) ? 512 : npa;

    int*    s_key  = (int*)(dsm + SM_KEY);
    float*  sbe1b  = (float*)(dsm + SM_BE1B);
    float*  sbf2b  = (float*)(dsm + SM_BF2B);
    float*  sbF1   = (float*)(dsm + SM_BF1);
    float4* s_nipk = (float4*)(dsm + SM_NIPK);
    float*  sbeo1  = (float*)(dsm + SM_BEO1);
    float*  sgeo   = (float*)(dsm + SM_GEO);
    float*  sbeeo  = (float*)(dsm + SM_BEEO);
    float*  sbeo2  = (float*)(dsm + SM_BEO2);
    float*  sw_eo2T = (float*)(dsm + SM_EO2T);
    uint2*  be1h   = (uint2*)(dsm + SM_BE1H);
    uint2*  bf2h   = (uint2*)(dsm + SM_BF2H);
    uint2*  bo1h   = (uint2*)(dsm + SM_BO1H);

    char*  wbase = dsm + SM_WARP + w*SM_PERW;
    float* sv    = (float*)wbase;            // [8][36]
    int*   smi   = (int*)(wbase + 1152);
    int*   smj   = smi + 8;
    float* sem   = (float*)(smi + 16);
    int*   sact  = smi + 24;

    for (int k = tid; k < Ndim; k += 256)
        s_key[k] = block_id[b*Ndim + k]*2 + ((vmask[b*Ndim + k] != 0) ? 1 : 0);
    if (tid < 64)  sbe1b[tid] = b_e1[tid];
    if (tid >= 64 && tid < 128)  sbf2b[tid-64] = b_f2[tid-64];
    if (tid >= 128 && tid < 192) sbF1[tid-128] = b_f1[tid-128];
    if (tid >= 192 && tid < 224) sbeo1[tid-192] = b_eo1[tid-192];
    if (tid >= 224 && tid < 256) sgeo[tid-224] = g_eo[tid-224];
    if (tid < 32)  sbeeo[tid] = be_eo[tid];
    if (tid >= 32 && tid < 40) sbeo2[tid-32] = b_eo2[tid-32];
    if (tid >= 40 && tid < 168) {
        int k = tid - 40;
        int row = k >> 6, ch = k & 63;
        int irow = row ? i_b : i_a;
        s_nipk[k] = *(const float4*)&g_pk[((size_t)(b*Ndim + irow)*OCdim + ch)*4];
    }
    for (int k = tid; k < 8*36; k += 256) {
        int ch = k / 36, kk = k % 36;
        sw_eo2T[k] = (ch < KEdim && kk < ECdim) ? W_eo2[kk*KEdim + ch] : 0.f;
    }
    for (int e = tid; e < 512; e += 256) {
        int lane_ = e & 31, nt = (e >> 5) & 7, ks = e >> 8;
        int q_ = lane_ & 3, g_ = lane_ >> 2;
        int k0 = ks*16 + 2*q_;
        int n  = nt*8 + g_;
        __half2 h0 = __float22half2_rn(make_float2(W_e1[k0*OCdim + n],     W_e1[(k0+1)*OCdim + n]));
        __half2 h1 = __float22half2_rn(make_float2(W_e1[(k0+8)*OCdim + n], W_e1[(k0+9)*OCdim + n]));
        be1h[e] = make_uint2(*(uint32_t*)&h0, *(uint32_t*)&h1);
    }
    for (int e = tid; e < 1024; e += 256) {
        int lane_ = e & 31, nt = (e >> 5) & 7, ks = e >> 8;
        int q_ = lane_ & 3, g_ = lane_ >> 2;
        int k0 = ks*16 + 2*q_;
        int n  = nt*8 + g_;
        __half2 h0 = __float22half2_rn(make_float2(W_f2[k0*OCdim + n],     W_f2[(k0+1)*OCdim + n]));
        __half2 h1 = __float22half2_rn(make_float2(W_f2[(k0+8)*OCdim + n], W_f2[(k0+9)*OCdim + n]));
        bf2h[e] = make_uint2(*(uint32_t*)&h0, *(uint32_t*)&h1);
    }
    for (int e = tid; e < 512; e += 256) {
        int lane_ = e & 31, nt = (e >> 5) & 3, ks = e >> 7;
        int q_ = lane_ & 3, g_ = lane_ >> 2;
        int k0 = ks*16 + 2*q_;
        int n  = nt*8 + g_;
        __half2 h0 = __float22half2_rn(make_float2(W_eo1[k0*32 + n],     W_eo1[(k0+1)*32 + n]));
        __half2 h1 = __float22half2_rn(make_float2(W_eo1[(k0+8)*32 + n], W_eo1[(k0+9)*32 + n]));
        bo1h[e] = make_uint2(*(uint32_t*)&h0, *(uint32_t*)&h1);
    }
    __syncthreads();

    for (int base = w*8; base < total; base += EWARPS*8) {
        if (lane < 8) {
            int p = base + lane;
            int act = (p < total) ? 1 : 0;
            int pc = act ? p : 0;
            bool aA = pc < npa;
            int i2 = aA ? i_a : i_b;
            int j2 = aA ? (i_a + pc) : (i_b + (pc - npa));
            int ki = s_key[i2], kj = s_key[j2];
            int bi_ = ki >> 1, bj_ = kj >> 1;
            bool nm2 = (bi_ >= 0) && (bj_ >= 0);
            bool cij = (bi_ > bj_) || (bi_ == bj_ && !(ki & 1));
            bool cji = (bj_ > bi_) || (bj_ == bi_ && !(kj & 1));
            smi[lane] = i2; smj[lane] = j2;
            sem[lane] = (nm2 && (cij || cji)) ? 1.f : 0.f;
            sact[lane] = act;
        }
        __syncwarp();

        const int   i2  = smi[grp];
        const int   j2  = smj[grp];
        const float emv = sem[grp];
        const bool  isA = (i2 == i_a);

        uint32_t aEh[8], aEl[8];
        {
            const float* eij = edge + ((size_t)(b*Ndim + i2)*Ndim + j2)*ECdim;
            const float* eji = edge + ((size_t)(b*Ndim + j2)*Ndim + i2)*ECdim;
            #pragma unroll
            for (int ks = 0; ks < 2; ks++) {
                float2 v0 = *(const float2*)(eij + ks*16 + 2*q);
                float2 v1 = *(const float2*)(eji + ks*16 + 2*q);
                float2 v2 = *(const float2*)(eij + ks*16 + 8 + 2*q);
                float2 v3 = *(const float2*)(eji + ks*16 + 8 + 2*q);
                split_h2(v0.x*emv, v0.y*emv, aEh[ks*4+0], aEl[ks*4+0]);
                split_h2(v1.x*emv, v1.y*emv, aEh[ks*4+1], aEl[ks*4+1]);
                split_h2(v2.x*emv, v2.y*emv, aEh[ks*4+2], aEl[ks*4+2]);
                split_h2(v3.x*emv, v3.y*emv, aEh[ks*4+3], aEl[ks*4+3]);
            }
        }

        float cE[8][4];
        #pragma unroll
        for (int nt = 0; nt < 8; nt++) {
            float2 bb = *(const float2*)&sbe1b[nt*8 + 2*q];
            cE[nt][0] = bb.x; cE[nt][1] = bb.y; cE[nt][2] = bb.x; cE[nt][3] = bb.y;
        }
        #pragma unroll
        for (int ks = 0; ks < 2; ks++) {
            #pragma unroll
            for (int nt = 0; nt < 8; nt++) {
                uint2 Bh = be1h[(ks*8 + nt)*32 + lane];
                mma16816(cE[nt][0], cE[nt][1], cE[nt][2], cE[nt][3],
                         aEh[ks*4+0], aEh[ks*4+1], aEh[ks*4+2], aEh[ks*4+3], Bh.x, Bh.y);
                mma16816(cE[nt][0], cE[nt][1], cE[nt][2], cE[nt][3],
                         aEl[ks*4+0], aEl[ks*4+1], aEl[ks*4+2], aEl[ks*4+3], Bh.x, Bh.y);
            }
        }

        uint32_t e1h[16], e1l[16];
        #pragma unroll
        for (int ks = 0; ks < 4; ks++) {
            split_h2(cE[2*ks][0],   cE[2*ks][1],   e1h[ks*4+0], e1l[ks*4+0]);
            split_h2(cE[2*ks][2],   cE[2*ks][3],   e1h[ks*4+1], e1l[ks*4+1]);
            split_h2(cE[2*ks+1][0], cE[2*ks+1][1], e1h[ks*4+2], e1l[ks*4+2]);
            split_h2(cE[2*ks+1][2], cE[2*ks+1][3], e1h[ks*4+3], e1l[ks*4+3]);
        }

        float cF[8][4];
        #pragma unroll
        for (int nt = 0; nt < 8; nt++) {
            float2 bb = *(const float2*)&sbf2b[nt*8 + 2*q];
            cF[nt][0] = bb.x; cF[nt][1] = bb.y; cF[nt][2] = bb.x; cF[nt][3] = bb.y;
        }
        #pragma unroll
        for (int ks = 0; ks < 4; ks++) {
            #pragma unroll
            for (int nt = 0; nt < 8; nt++) {
                uint2 Bh = bf2h[(ks*8 + nt)*32 + lane];
                mma16816(cF[nt][0], cF[nt][1], cF[nt][2], cF[nt][3],
                         e1h[ks*4+0], e1h[ks*4+1], e1h[ks*4+2], e1h[ks*4+3], Bh.x, Bh.y);
                mma16816(cF[nt][0], cF[nt][1], cF[nt][2], cF[nt][3],
                         e1l[ks*4+0], e1l[ks*4+1], e1l[ks*4+2], e1l[ks*4+3], Bh.x, Bh.y);
            }
        }

        uint32_t aUh[16], aUl[16];
        {
            const float4* gpk = (const float4*)g_pk;
            const size_t jo = (size_t)(b*Ndim + j2)*OCdim;
            const int    ib = isA ? 0 : 64;
            #pragma unroll
            for (int nt = 0; nt < 8; nt++) {
                const int ch0 = nt*8 + 2*q;
                const int ksi = (nt >> 1)*4 + (nt & 1)*2;
                float2 e1a = unpack_sum(e1h[ksi],   e1l[ksi]);
                float2 e1b = unpack_sum(e1h[ksi+1], e1l[ksi+1]);
                float4 pj0 = gpk[jo + ch0];
                float4 pj1 = gpk[jo + ch0 + 1];
                float4 pi0 = s_nipk[ib + ch0];
                float4 pi1 = s_nipk[ib + ch0 + 1];
                float2 bf  = *(const float2*)&sbF1[ch0];
                float Q00 = silu_t(pj0.z + pi0.w + bf.x);
                float Q01 = silu_t(pj1.z + pi1.w + bf.y);
                float Q10 = silu_t(pi0.z + pj0.w + bf.x);
                float Q11 = silu_t(pi1.z + pj1.w + bf.y);
                float E00 = silu_t(pj0.x + pi0.y + e1a.x + Q00*silu_t(cF[nt][0])) * emv;
                float E01 = silu_t(pj1.x + pi1.y + e1a.y + Q01*silu_t(cF[nt][1])) * emv;
                float E10 = silu_t(pi0.x + pj0.y + e1b.x + Q10*silu_t(cF[nt][2])) * emv;
                float E11 = silu_t(pi1.x + pj1.y + e1b.y + Q11*silu_t(cF[nt][3])) * emv;
                const int bse = (nt >> 1)*4 + (nt & 1)*2;
                split_h2(E00, E01, aUh[bse],   aUl[bse]);
                split_h2(E10, E11, aUh[bse+1], aUl[bse+1]);
            }
        }

        float cU[4][4];
        #pragma unroll
        for (int nt = 0; nt < 4; nt++)
            cU[nt][0] = cU[nt][1] = cU[nt][2] = cU[nt][3] = 0.f;
        #pragma unroll
        for (int ks = 0; ks < 4; ks++) {
            #pragma unroll
            for (int nt = 0; nt < 4; nt++) {
                uint2 Bh = bo1h[(ks*4 + nt)*32 + lane];
                mma16816(cU[nt][0], cU[nt][1], cU[nt][2], cU[nt][3],
                         aUh[ks*4+0], aUh[ks*4+1], aUh[ks*4+2], aUh[ks*4+3], Bh.x, Bh.y);
                mma16816(cU[nt][0], cU[nt][1], cU[nt][2], cU[nt][3],
                         aUl[ks*4+0], aUl[ks*4+1], aUl[ks*4+2], aUl[ks*4+3], Bh.x, Bh.y);
            }
        }

        float u0[4], u1[4];
        float s = 0.f;
        #pragma unroll
        for (int nt = 0; nt < 4; nt++) {
            float2 bb = *(const float2*)&sbeo1[nt*8 + 2*q];
            u0[nt] = cU[nt][0] + cU[nt][2] + bb.x;
            u1[nt] = cU[nt][1] + cU[nt][3] + bb.y;
            s += u0[nt] + u1[nt];
        }
        s += __shfl_xor_sync(0xffffffffu, s, 1);
        s += __shfl_xor_sync(0xffffffffu, s, 2);
        const float mean = s * (1.f/32.f);
        float var = 0.f;
        #pragma unroll
        for (int nt = 0; nt < 4; nt++) {
            float d0 = u0[nt] - mean, d1 = u1[nt] - mean;
            var += d0*d0 + d1*d1;
        }
        var += __shfl_xor_sync(0xffffffffu, var, 1);
        var += __shfl_xor_sync(0xffffffffu, var, 2);
        const float rstd = rsqrtf(var * (1.f/32.f) + 1e-5f);
        #pragma unroll
        for (int nt = 0; nt < 4; nt++) {
            const int ch0 = nt*8 + 2*q;
            float2 ge = *(const float2*)&sgeo[ch0];
            float2 be = *(const float2*)&sbeeo[ch0];
            float v0 = silu_t((u0[nt] - mean)*rstd*ge.x + be.x);
            float v1 = silu_t((u1[nt] - mean)*rstd*ge.y + be.y);
            *(float2*)&sv[grp*36 + ch0] = make_float2(v0, v1);
        }
        __syncwarp();

        #pragma unroll
        for (int h = 0; h < 2; h++) {
            const int pr  = h*4 + (lane >> 3);
            const int ch2 = lane & 7;
            float t = 0.f;
            #pragma unroll
            for (int k4 = 0; k4 < 8; k4++) {
                float4 vv = *(const float4*)&sv[pr*36 + k4*4];
                float4 w4 = *(const float4*)&sw_eo2T[ch2*36 + k4*4];
                t += vv.x*w4.x + vv.y*w4.y + vv.z*w4.z + vv.w*w4.w;
            }
            if (ch2 < KEdim && sact[pr]) {
                const int io = smi[pr], jo2 = smj[pr];
                float outv = (t + sbeo2[ch2]) * sem[pr];
                out_edge[((size_t)(b*Ndim + io)*Ndim + jo2)*KEdim + ch2] = outv;
                out_edge[((size_t)(b*Ndim + jo2)*Ndim + io)*KEdim + ch2] = outv;
            }
        }
        __syncwarp();
    }
}

// ---------------------------------------------------------------------------
extern "C" void kernel_launch(void* const* d_in, const int* in_sizes, int n_in,
                              void* d_out, int out_size)
{
    const float* node      = (const float*)d_in[0];
    const float* edge      = (const float*)d_in[1];
    const int*   block_id  = (const int*)d_in[2];
    const int*   vmask     = (const int*)d_in[3];
    const float* W_nt  = (const float*)d_in[4];
    const float* b_nt  = (const float*)d_in[5];
    const float* W_n1  = (const float*)d_in[6];
    const float* b_n1  = (const float*)d_in[7];
    const float* W_e1  = (const float*)d_in[8];
    const float* b_e1  = (const float*)d_in[9];
    const float* W_f1  = (const float*)d_in[10];
    const float* b_f1  = (const float*)d_in[11];
    const float* W_f2  = (const float*)d_in[12];
    const float* b_f2  = (const float*)d_in[13];
    const float* W_no1 = (const float*)d_in[14];
    const float* b_no1 = (const float*)d_in[15];
    const float* g_no  = (const float*)d_in[16];
    const float* be_no = (const float*)d_in[17];
    const float* W_no2 = (const float*)d_in[18];
    const float* b_no2 = (const float*)d_in[19];
    const float* W_eo1 = (const float*)d_in[20];
    const float* b_eo1 = (const float*)d_in[21];
    const float* g_eo  = (const float*)d_in[22];
    const float* be_eo = (const float*)d_in[23];
    const float* W_eo2 = (const float*)d_in[24];
    const float* b_eo2 = (const float*)d_in[25];

    float* out_node = (float*)d_out;                       // (B,N,KN)
    float* out_edge = (float*)d_out + Bdim*Ndim*KNdim;     // (B,N,N,KE)

    static int smem_set = 0;
    if (!smem_set) {
        cudaFuncSetAttribute(edge_kernel, cudaFuncAttributeMaxDynamicSharedMemorySize, SM_TOTAL);
        smem_set = 1;
    }

    reduce_kernel<<<Bdim*Ndim, 256>>>(edge, block_id, vmask);

    node_kernel<<<Bdim*64, 256>>>(node, block_id,
                                  W_nt, b_nt, W_n1, b_n1, W_f1,
                                  W_no1, b_no1, g_no, be_no, W_no2, b_no2,
                                  out_node);

    edge_kernel<<<Bdim*257, 256, SM_TOTAL>>>(edge, block_id, vmask,
                                   W_e1, b_e1, b_f1, W_f2, b_f2,
                                   W_eo1, b_eo1, g_eo, be_eo, W_eo2, b_eo2,
                                   out_edge);
}

// round 16
// speedup vs baseline: 2.2335x; 1.0669x over previous
#include <cuda_runtime.h>
#include <cuda_fp16.h>
#include <stdint.h>

#define Bdim 4
#define Ndim 512
#define NCdim 128
#define ECdim 32
#define OCdim 64
#define KNdim 10
#define KEdim 5
#define NIN 192   // 2*EC + NC
#define EWARPS 8
#define PX 12     // node-kernel transposed pitch

// packed per-node vectors: {n1, n2, q1, q2} per channel (float4-interleaved)
__device__ float g_pk[Bdim*Ndim*OCdim*4];
// x_in (0..31) ++ x_out (32..63) per node
__device__ float g_x[Bdim*Ndim*64];

__device__ __forceinline__ float silu_f(float x) {
    return __fdividef(x, 1.0f + __expf(-x));
}
// fast silu: x * sigmoid(x) = 0.5x(1 + tanh(x/2)); 1 MUFU
__device__ __forceinline__ float silu_t(float x) {
    float th;
    asm("tanh.approx.f32 %0, %1;" : "=f"(th) : "f"(x * 0.5f));
    return fmaf(0.5f*x, th, 0.5f*x);
}

__device__ __forceinline__ void mma16816(float& c0, float& c1, float& c2, float& c3,
                                         uint32_t a0, uint32_t a1, uint32_t a2, uint32_t a3,
                                         uint32_t b0, uint32_t b1) {
    asm volatile("mma.sync.aligned.m16n8k16.row.col.f32.f16.f16.f32 "
                 "{%0,%1,%2,%3},{%4,%5,%6,%7},{%8,%9},{%0,%1,%2,%3};\n"
                 : "+f"(c0), "+f"(c1), "+f"(c2), "+f"(c3)
                 : "r"(a0), "r"(a1), "r"(a2), "r"(a3), "r"(b0), "r"(b1));
}

__device__ __forceinline__ void split_h2(float x, float y, uint32_t& hi, uint32_t& lo) {
    __half2 h = __float22half2_rn(make_float2(x, y));
    float2 hf = __half22float2(h);
    __half2 l = __float22half2_rn(make_float2(x - hf.x, y - hf.y));
    hi = *(uint32_t*)&h;  lo = *(uint32_t*)&l;
}
__device__ __forceinline__ uint32_t pack_h2(float x, float y) {
    __half2 h = __float22half2_rn(make_float2(x, y));
    return *(uint32_t*)&h;
}

__device__ __forceinline__ float2 unpack_sum(uint32_t h, uint32_t l) {
    float2 fh = __half22float2(*(__half2*)&h);
    float2 fl = __half22float2(*(__half2*)&l);
    return make_float2(fh.x + fl.x, fh.y + fl.y);
}

// ---------------------------------------------------------------------------
// Kernel A: masked-mean reduction. 16-wide unroll: 32 LDGs in flight per warp.
// ---------------------------------------------------------------------------
__global__ __launch_bounds__(256)
void reduce_kernel(const float* __restrict__ edge,
                   const int* __restrict__ block_id,
                   const int* __restrict__ vmask)
{
    const int bi = blockIdx.x;
    const int b  = bi / Ndim;
    const int i  = bi % Ndim;
    const int tid = threadIdx.x;

    __shared__ int    s_bid[Ndim];
    __shared__ unsigned char s_vm[Ndim];
    __shared__ float2 s_mask[Ndim];
    __shared__ float  s_red[8][64];
    __shared__ float  s_cnt[2][8];

    for (int k = tid; k < Ndim; k += 256) {
        s_bid[k] = block_id[b*Ndim + k];
        s_vm[k]  = (vmask[b*Ndim + k] != 0) ? 1 : 0;
    }
    __syncthreads();

    const int  bii  = s_bid[i];
    const bool nm_i = (bii >= 0);
    const bool vm_i = (s_vm[i] != 0);

    for (int j = tid; j < Ndim; j += 256) {
        int  bj   = s_bid[j];
        bool nm_j = (bj >= 0);
        bool pv   = nm_i && nm_j;
        bool cij  = pv && ((bii > bj) || (bii == bj && !vm_i));
        bool cji  = pv && ((bj > bii) || (bj == bii && (s_vm[j] == 0)));
        s_mask[j] = make_float2(cij ? 1.f : 0.f, cji ? 1.f : 0.f);
    }
    __syncthreads();

    const int c  = tid & 31;
    const int jl = tid >> 5;

    float acc_in0 = 0.f, acc_in1 = 0.f, acc_out0 = 0.f, acc_out1 = 0.f;
    float cnt_in = 0.f, cnt_out = 0.f;
    const float* erow = edge + ((size_t)(b*Ndim + i) * Ndim) * ECdim + c;
    const float* ecol = edge + ((size_t)b*Ndim) * Ndim * ECdim + (size_t)i*ECdim + c;

    for (int j0 = jl*16; j0 < Ndim; j0 += 128) {
        const float* er = erow + (size_t)j0*ECdim;
        const float* ec = ecol + (size_t)j0*Ndim*ECdim;
        float vin[16], vout[16];
        #pragma unroll
        for (int u = 0; u < 16; u++) {
            vin[u]  = er[(size_t)u*ECdim];
            vout[u] = ec[(size_t)u*Ndim*ECdim];
        }
        #pragma unroll
        for (int u = 0; u < 16; u += 2) {
            float2 m0 = s_mask[j0+u], m1 = s_mask[j0+u+1];
            acc_in0  = fmaf(vin[u],    m0.x, acc_in0);
            acc_in1  = fmaf(vin[u+1],  m1.x, acc_in1);
            acc_out0 = fmaf(vout[u],   m0.y, acc_out0);
            acc_out1 = fmaf(vout[u+1], m1.y, acc_out1);
            cnt_in  += m0.x + m1.x;
            cnt_out += m0.y + m1.y;
        }
    }
    s_red[jl][c]      = acc_in0 + acc_in1;
    s_red[jl][c + 32] = acc_out0 + acc_out1;
    if (c == 0) { s_cnt[0][jl] = cnt_in; s_cnt[1][jl] = cnt_out; }
    __syncthreads();

    if (tid < 64) {
        float s = 0.f, cnt = 0.f;
        #pragma unroll
        for (int r2 = 0; r2 < 8; r2++) { s += s_red[r2][tid]; cnt += s_cnt[tid >> 5][r2]; }
        g_x[(size_t)(b*Ndim + i)*64 + tid] = s / fmaxf(cnt, 1.f);
    }
}

// ---------------------------------------------------------------------------
// Kernel B: batched node GEMVs (unchanged winner).
// ---------------------------------------------------------------------------
__global__ __launch_bounds__(256)
void node_kernel(const float* __restrict__ node,
                 const int* __restrict__ block_id,
                 const float* __restrict__ W_nt, const float* __restrict__ b_nt,
                 const float* __restrict__ W_n1, const float* __restrict__ b_n1,
                 const float* __restrict__ W_f1,
                 const float* __restrict__ W_no1, const float* __restrict__ b_no1,
                 const float* __restrict__ g_no, const float* __restrict__ be_no,
                 const float* __restrict__ W_no2, const float* __restrict__ b_no2,
                 float* __restrict__ out_node)
{
    const int b  = blockIdx.x >> 6;
    const int i0 = (blockIdx.x & 63) * 8;
    const int tid = threadIdx.x;
    const int w    = tid >> 5;
    const int lane = tid & 31;

    __shared__ int s_bid8[8];
    __shared__ float s_x[NIN*PX];
    __shared__ float s_hT[NCdim*PX];
    __shared__ float s_nT[NCdim*PX];
    __shared__ float s_tT[NCdim*PX];
    __shared__ float s_vT[NCdim*PX];

    if (tid < 8) s_bid8[tid] = block_id[b*Ndim + i0 + tid];
    __syncthreads();

    {
        const int i = i0 + w;
        const bool nm_i = (s_bid8[w] >= 0);
        const size_t xo = (size_t)(b*Ndim + i)*64;
        s_x[lane*PX + w]      = g_x[xo + lane];
        s_x[(lane+32)*PX + w] = g_x[xo + 32 + lane];
        float msk = nm_i ? 1.f : 0.f;
        float4 nd = *(const float4*)&node[(size_t)(b*Ndim + i)*NCdim + lane*4];
        s_x[(64 + lane*4 + 0)*PX + w] = nd.x * msk;
        s_x[(64 + lane*4 + 1)*PX + w] = nd.y * msk;
        s_x[(64 + lane*4 + 2)*PX + w] = nd.z * msk;
        s_x[(64 + lane*4 + 3)*PX + w] = nd.w * msk;
    }
    __syncthreads();

    const int o = tid & 127;
    const int g = tid >> 7;

    {
        float bb = b_nt[o];
        float4 acc = make_float4(bb, bb, bb, bb);
        #pragma unroll 4
        for (int k = 0; k < NIN; k++) {
            float wv = W_nt[k*NCdim + o];
            float4 xi = *(const float4*)&s_x[k*PX + g*4];
            acc.x += wv*xi.x; acc.y += wv*xi.y; acc.z += wv*xi.z; acc.w += wv*xi.w;
        }
        #pragma unroll
        for (int c4 = 0; c4 < 4; c4++) {
            int nn = g*4 + c4;
            float v = (c4 == 0) ? acc.x : (c4 == 1) ? acc.y : (c4 == 2) ? acc.z : acc.w;
            s_hT[o*PX + nn] = (s_bid8[nn] >= 0) ? silu_f(v) : 0.f;
        }
    }
    __syncthreads();

    {
        float bn = b_n1[o], bt = b_no1[o];
        float4 an = make_float4(bn, bn, bn, bn);
        float4 at = make_float4(bt, bt, bt, bt);
        #pragma unroll 4
        for (int k = 0; k < NCdim; k++) {
            float wn = W_n1[k*NCdim + o];
            float wt = W_no1[k*NCdim + o];
            float4 xi = *(const float4*)&s_hT[k*PX + g*4];
            an.x += wn*xi.x; an.y += wn*xi.y; an.z += wn*xi.z; an.w += wn*xi.w;
            at.x += wt*xi.x; at.y += wt*xi.y; at.z += wt*xi.z; at.w += wt*xi.w;
        }
        s_nT[o*PX + g*4+0] = an.x; s_nT[o*PX + g*4+1] = an.y;
        s_nT[o*PX + g*4+2] = an.z; s_nT[o*PX + g*4+3] = an.w;
        s_tT[o*PX + g*4+0] = at.x; s_tT[o*PX + g*4+1] = at.y;
        s_tT[o*PX + g*4+2] = at.z; s_tT[o*PX + g*4+3] = at.w;
    }
    __syncthreads();

    {
        const int oq = tid & 63;
        const int wh = (tid >> 6) & 1;
        float4 aq = make_float4(0.f, 0.f, 0.f, 0.f);
        #pragma unroll 4
        for (int k = 0; k < OCdim; k++) {
            float wq = W_f1[k*OCdim + oq];
            float4 xi = *(const float4*)&s_nT[(wh*OCdim + k)*PX + g*4];
            aq.x += wq*xi.x; aq.y += wq*xi.y; aq.z += wq*xi.z; aq.w += wq*xi.w;
        }
        #pragma unroll
        for (int c4 = 0; c4 < 4; c4++) {
            int nn = g*4 + c4;
            float qv = (c4 == 0) ? aq.x : (c4 == 1) ? aq.y : (c4 == 2) ? aq.z : aq.w;
            size_t base = ((size_t)(b*Ndim + i0 + nn)*OCdim + oq)*4;
            g_pk[base + wh]     = s_nT[(wh*OCdim + oq)*PX + nn];
            g_pk[base + 2 + wh] = qv;
        }
    }

    {
        float tv0 = s_tT[lane*PX + w];
        float tv1 = s_tT[(lane+32)*PX + w];
        float tv2 = s_tT[(lane+64)*PX + w];
        float tv3 = s_tT[(lane+96)*PX + w];
        float s = tv0 + tv1 + tv2 + tv3;
        #pragma unroll
        for (int o2 = 16; o2; o2 >>= 1) s += __shfl_xor_sync(0xffffffffu, s, o2);
        float mean = s * (1.f/NCdim);
        float d0 = tv0-mean, d1 = tv1-mean, d2 = tv2-mean, d3 = tv3-mean;
        float var = d0*d0 + d1*d1 + d2*d2 + d3*d3;
        #pragma unroll
        for (int o2 = 16; o2; o2 >>= 1) var += __shfl_xor_sync(0xffffffffu, var, o2);
        float rstd = rsqrtf(var * (1.f/NCdim) + 1e-5f);
        s_vT[lane*PX + w]      = silu_f(d0*rstd*g_no[lane]    + be_no[lane]);
        s_vT[(lane+32)*PX + w] = silu_f(d1*rstd*g_no[lane+32] + be_no[lane+32]);
        s_vT[(lane+64)*PX + w] = silu_f(d2*rstd*g_no[lane+64] + be_no[lane+64]);
        s_vT[(lane+96)*PX + w] = silu_f(d3*rstd*g_no[lane+96] + be_no[lane+96]);
    }
    __syncthreads();

    if (lane < KNdim) {
        float a = b_no2[lane];
        #pragma unroll 4
        for (int k = 0; k < NCdim; k++)
            a += s_vT[k*PX + w] * W_no2[k*KNdim + lane];
        bool nm_i = (s_bid8[w] >= 0);
        out_node[(size_t)(b*Ndim + i0 + w)*KNdim + lane] = nm_i ? a : 0.f;
    }
}

// ---------------------------------------------------------------------------
// Kernel 2: edge work. Compensated MMA only on e1 (root of the chain);
// f2 and eo1 run single-pass fp16. 80 MMAs/iter (was 128).
// ---------------------------------------------------------------------------
#define SM_KEY     0
#define SM_BE1B    2048
#define SM_BF2B    2304
#define SM_BF1     2560
#define SM_NIPK    2816
#define SM_BEO1    4864
#define SM_GEO     4992
#define SM_BEEO    5120
#define SM_BEO2    5248
#define SM_EO2T    5296
#define SM_BE1H    6448
#define SM_BF2H    10544
#define SM_BO1H    18736
#define SM_WARP    22832
#define SM_PERW    1280
#define SM_TOTAL   (SM_WARP + EWARPS*SM_PERW)   // 33072

__global__ __launch_bounds__(256, 2)
void edge_kernel(const float* __restrict__ edge,
                 const int* __restrict__ block_id,
                 const int* __restrict__ vmask,
                 const float* __restrict__ W_e1, const float* __restrict__ b_e1,
                 const float* __restrict__ b_f1,
                 const float* __restrict__ W_f2, const float* __restrict__ b_f2,
                 const float* __restrict__ W_eo1, const float* __restrict__ b_eo1,
                 const float* __restrict__ g_eo, const float* __restrict__ be_eo,
                 const float* __restrict__ W_eo2, const float* __restrict__ b_eo2,
                 float* __restrict__ out_edge)
{
    extern __shared__ char dsm[];
    const int b = blockIdx.x / 257;
    const int m = blockIdx.x % 257;
    const int tid  = threadIdx.x;
    const int w    = tid >> 5;
    const int lane = tid & 31;
    const int grp  = lane >> 2;
    const int q    = lane & 3;

    int i_a, i_b;
    if (m < 255)      { i_a = m + 1; i_b = 511 - m; }
    else if (m == 255){ i_a = 0;     i_b = 0;       }
    else              { i_a = 256;   i_b = 256;     }
    const int npa   = Ndim - i_a;
    const int total = (m < 255) ? 512 : npa;

    int*    s_key  = (int*)(dsm + SM_KEY);
    float*  sbe1b  = (float*)(dsm + SM_BE1B);
    float*  sbf2b  = (float*)(dsm + SM_BF2B);
    float*  sbF1   = (float*)(dsm + SM_BF1);
    float4* s_nipk = (float4*)(dsm + SM_NIPK);
    float*  sbeo1  = (float*)(dsm + SM_BEO1);
    float*  sgeo   = (float*)(dsm + SM_GEO);
    float*  sbeeo  = (float*)(dsm + SM_BEEO);
    float*  sbeo2  = (float*)(dsm + SM_BEO2);
    float*  sw_eo2T = (float*)(dsm + SM_EO2T);
    uint2*  be1h   = (uint2*)(dsm + SM_BE1H);
    uint2*  bf2h   = (uint2*)(dsm + SM_BF2H);
    uint2*  bo1h   = (uint2*)(dsm + SM_BO1H);

    char*  wbase = dsm + SM_WARP + w*SM_PERW;
    float* sv    = (float*)wbase;            // [8][36]
    int*   smi   = (int*)(wbase + 1152);
    int*   smj   = smi + 8;
    float* sem   = (float*)(smi + 16);
    int*   sact  = smi + 24;

    for (int k = tid; k < Ndim; k += 256)
        s_key[k] = block_id[b*Ndim + k]*2 + ((vmask[b*Ndim + k] != 0) ? 1 : 0);
    if (tid < 64)  sbe1b[tid] = b_e1[tid];
    if (tid >= 64 && tid < 128)  sbf2b[tid-64] = b_f2[tid-64];
    if (tid >= 128 && tid < 192) sbF1[tid-128] = b_f1[tid-128];
    if (tid >= 192 && tid < 224) sbeo1[tid-192] = b_eo1[tid-192];
    if (tid >= 224 && tid < 256) sgeo[tid-224] = g_eo[tid-224];
    if (tid < 32)  sbeeo[tid] = be_eo[tid];
    if (tid >= 32 && tid < 40) sbeo2[tid-32] = b_eo2[tid-32];
    if (tid >= 40 && tid < 168) {
        int k = tid - 40;
        int row = k >> 6, ch = k & 63;
        int irow = row ? i_b : i_a;
        s_nipk[k] = *(const float4*)&g_pk[((size_t)(b*Ndim + irow)*OCdim + ch)*4];
    }
    for (int k = tid; k < 8*36; k += 256) {
        int ch = k / 36, kk = k % 36;
        sw_eo2T[k] = (ch < KEdim && kk < ECdim) ? W_eo2[kk*KEdim + ch] : 0.f;
    }
    for (int e = tid; e < 512; e += 256) {
        int lane_ = e & 31, nt = (e >> 5) & 7, ks = e >> 8;
        int q_ = lane_ & 3, g_ = lane_ >> 2;
        int k0 = ks*16 + 2*q_;
        int n  = nt*8 + g_;
        __half2 h0 = __float22half2_rn(make_float2(W_e1[k0*OCdim + n],     W_e1[(k0+1)*OCdim + n]));
        __half2 h1 = __float22half2_rn(make_float2(W_e1[(k0+8)*OCdim + n], W_e1[(k0+9)*OCdim + n]));
        be1h[e] = make_uint2(*(uint32_t*)&h0, *(uint32_t*)&h1);
    }
    for (int e = tid; e < 1024; e += 256) {
        int lane_ = e & 31, nt = (e >> 5) & 7, ks = e >> 8;
        int q_ = lane_ & 3, g_ = lane_ >> 2;
        int k0 = ks*16 + 2*q_;
        int n  = nt*8 + g_;
        __half2 h0 = __float22half2_rn(make_float2(W_f2[k0*OCdim + n],     W_f2[(k0+1)*OCdim + n]));
        __half2 h1 = __float22half2_rn(make_float2(W_f2[(k0+8)*OCdim + n], W_f2[(k0+9)*OCdim + n]));
        bf2h[e] = make_uint2(*(uint32_t*)&h0, *(uint32_t*)&h1);
    }
    for (int e = tid; e < 512; e += 256) {
        int lane_ = e & 31, nt = (e >> 5) & 3, ks = e >> 7;
        int q_ = lane_ & 3, g_ = lane_ >> 2;
        int k0 = ks*16 + 2*q_;
        int n  = nt*8 + g_;
        __half2 h0 = __float22half2_rn(make_float2(W_eo1[k0*32 + n],     W_eo1[(k0+1)*32 + n]));
        __half2 h1 = __float22half2_rn(make_float2(W_eo1[(k0+8)*32 + n], W_eo1[(k0+9)*32 + n]));
        bo1h[e] = make_uint2(*(uint32_t*)&h0, *(uint32_t*)&h1);
    }
    __syncthreads();

    for (int base = w*8; base < total; base += EWARPS*8) {
        if (lane < 8) {
            int p = base + lane;
            int act = (p < total) ? 1 : 0;
            int pc = act ? p : 0;
            bool aA = pc < npa;
            int i2 = aA ? i_a : i_b;
            int j2 = aA ? (i_a + pc) : (i_b + (pc - npa));
            int ki = s_key[i2], kj = s_key[j2];
            int bi_ = ki >> 1, bj_ = kj >> 1;
            bool nm2 = (bi_ >= 0) && (bj_ >= 0);
            bool cij = (bi_ > bj_) || (bi_ == bj_ && !(ki & 1));
            bool cji = (bj_ > bi_) || (bj_ == bi_ && !(kj & 1));
            smi[lane] = i2; smj[lane] = j2;
            sem[lane] = (nm2 && (cij || cji)) ? 1.f : 0.f;
            sact[lane] = act;
        }
        __syncwarp();

        const int   i2  = smi[grp];
        const int   j2  = smj[grp];
        const float emv = sem[grp];
        const bool  isA = (i2 == i_a);

        uint32_t aEh[8], aEl[8];
        {
            const float* eij = edge + ((size_t)(b*Ndim + i2)*Ndim + j2)*ECdim;
            const float* eji = edge + ((size_t)(b*Ndim + j2)*Ndim + i2)*ECdim;
            #pragma unroll
            for (int ks = 0; ks < 2; ks++) {
                float2 v0 = *(const float2*)(eij + ks*16 + 2*q);
                float2 v1 = *(const float2*)(eji + ks*16 + 2*q);
                float2 v2 = *(const float2*)(eij + ks*16 + 8 + 2*q);
                float2 v3 = *(const float2*)(eji + ks*16 + 8 + 2*q);
                split_h2(v0.x*emv, v0.y*emv, aEh[ks*4+0], aEl[ks*4+0]);
                split_h2(v1.x*emv, v1.y*emv, aEh[ks*4+1], aEl[ks*4+1]);
                split_h2(v2.x*emv, v2.y*emv, aEh[ks*4+2], aEl[ks*4+2]);
                split_h2(v3.x*emv, v3.y*emv, aEh[ks*4+3], aEl[ks*4+3]);
            }
        }

        // e1: keep 2-pass compensation (root of the chain)
        float cE[8][4];
        #pragma unroll
        for (int nt = 0; nt < 8; nt++) {
            float2 bb = *(const float2*)&sbe1b[nt*8 + 2*q];
            cE[nt][0] = bb.x; cE[nt][1] = bb.y; cE[nt][2] = bb.x; cE[nt][3] = bb.y;
        }
        #pragma unroll
        for (int ks = 0; ks < 2; ks++) {
            #pragma unroll
            for (int nt = 0; nt < 8; nt++) {
                uint2 Bh = be1h[(ks*8 + nt)*32 + lane];
                mma16816(cE[nt][0], cE[nt][1], cE[nt][2], cE[nt][3],
                         aEh[ks*4+0], aEh[ks*4+1], aEh[ks*4+2], aEh[ks*4+3], Bh.x, Bh.y);
                mma16816(cE[nt][0], cE[nt][1], cE[nt][2], cE[nt][3],
                         aEl[ks*4+0], aEl[ks*4+1], aEl[ks*4+2], aEl[ks*4+3], Bh.x, Bh.y);
            }
        }

        // repack e1 (hi only — f2 runs single-pass)
        uint32_t e1h[16];
        #pragma unroll
        for (int ks = 0; ks < 4; ks++) {
            e1h[ks*4+0] = pack_h2(cE[2*ks][0],   cE[2*ks][1]);
            e1h[ks*4+1] = pack_h2(cE[2*ks][2],   cE[2*ks][3]);
            e1h[ks*4+2] = pack_h2(cE[2*ks+1][0], cE[2*ks+1][1]);
            e1h[ks*4+3] = pack_h2(cE[2*ks+1][2], cE[2*ks+1][3]);
        }

        float cF[8][4];
        #pragma unroll
        for (int nt = 0; nt < 8; nt++) {
            float2 bb = *(const float2*)&sbf2b[nt*8 + 2*q];
            cF[nt][0] = bb.x; cF[nt][1] = bb.y; cF[nt][2] = bb.x; cF[nt][3] = bb.y;
        }
        #pragma unroll
        for (int ks = 0; ks < 4; ks++) {
            #pragma unroll
            for (int nt = 0; nt < 8; nt++) {
                uint2 Bh = bf2h[(ks*8 + nt)*32 + lane];
                mma16816(cF[nt][0], cF[nt][1], cF[nt][2], cF[nt][3],
                         e1h[ks*4+0], e1h[ks*4+1], e1h[ks*4+2], e1h[ks*4+3], Bh.x, Bh.y);
            }
        }

        // combine -> masked E -> eo1 A-fragments (hi only)
        uint32_t aUh[16];
        {
            const float4* gpk = (const float4*)g_pk;
            const size_t jo = (size_t)(b*Ndim + j2)*OCdim;
            const int    ib = isA ? 0 : 64;
            #pragma unroll
            for (int nt = 0; nt < 8; nt++) {
                const int ch0 = nt*8 + 2*q;
                const int ksi = (nt >> 1)*4 + (nt & 1)*2;
                // e1 values: use exact fp32 C-frag values directly
                float e1ax = cE[2*(nt>>1)    + ((ksi&2)>>1)][0];
                // index arithmetic: ksi maps back to cE[2*ks or 2*ks+1]; recompute cleanly:
                (void)e1ax;
                float2 e1a, e1b;
                {
                    const int kss = nt >> 1;       // 0..3
                    const int sub = nt & 1;        // 0: cE[2k], 1: cE[2k+1]
                    const float* src = cE[2*kss + sub];
                    e1a = make_float2(src[0], src[1]);
                    e1b = make_float2(src[2], src[3]);
                }
                float4 pj0 = gpk[jo + ch0];
                float4 pj1 = gpk[jo + ch0 + 1];
                float4 pi0 = s_nipk[ib + ch0];
                float4 pi1 = s_nipk[ib + ch0 + 1];
                float2 bf  = *(const float2*)&sbF1[ch0];
                float Q00 = silu_t(pj0.z + pi0.w + bf.x);
                float Q01 = silu_t(pj1.z + pi1.w + bf.y);
                float Q10 = silu_t(pi0.z + pj0.w + bf.x);
                float Q11 = silu_t(pi1.z + pj1.w + bf.y);
                float E00 = silu_t(pj0.x + pi0.y + e1a.x + Q00*silu_t(cF[nt][0])) * emv;
                float E01 = silu_t(pj1.x + pi1.y + e1a.y + Q01*silu_t(cF[nt][1])) * emv;
                float E10 = silu_t(pi0.x + pj0.y + e1b.x + Q10*silu_t(cF[nt][2])) * emv;
                float E11 = silu_t(pi1.x + pj1.y + e1b.y + Q11*silu_t(cF[nt][3])) * emv;
                const int bse = (nt >> 1)*4 + (nt & 1)*2;
                aUh[bse]   = pack_h2(E00, E01);
                aUh[bse+1] = pack_h2(E10, E11);
            }
        }

        // eo1 single-pass
        float cU[4][4];
        #pragma unroll
        for (int nt = 0; nt < 4; nt++)
            cU[nt][0] = cU[nt][1] = cU[nt][2] = cU[nt][3] = 0.f;
        #pragma unroll
        for (int ks = 0; ks < 4; ks++) {
            #pragma unroll
            for (int nt = 0; nt < 4; nt++) {
                uint2 Bh = bo1h[(ks*4 + nt)*32 + lane];
                mma16816(cU[nt][0], cU[nt][1], cU[nt][2], cU[nt][3],
                         aUh[ks*4+0], aUh[ks*4+1], aUh[ks*4+2], aUh[ks*4+3], Bh.x, Bh.y);
            }
        }

        float u0[4], u1[4];
        float s = 0.f;
        #pragma unroll
        for (int nt = 0; nt < 4; nt++) {
            float2 bb = *(const float2*)&sbeo1[nt*8 + 2*q];
            u0[nt] = cU[nt][0] + cU[nt][2] + bb.x;
            u1[nt] = cU[nt][1] + cU[nt][3] + bb.y;
            s += u0[nt] + u1[nt];
        }
        s += __shfl_xor_sync(0xffffffffu, s, 1);
        s += __shfl_xor_sync(0xffffffffu, s, 2);
        const float mean = s * (1.f/32.f);
        float var = 0.f;
        #pragma unroll
        for (int nt = 0; nt < 4; nt++) {
            float d0 = u0[nt] - mean, d1 = u1[nt] - mean;
            var += d0*d0 + d1*d1;
        }
        var += __shfl_xor_sync(0xffffffffu, var, 1);
        var += __shfl_xor_sync(0xffffffffu, var, 2);
        const float rstd = rsqrtf(var * (1.f/32.f) + 1e-5f);
        #pragma unroll
        for (int nt = 0; nt < 4; nt++) {
            const int ch0 = nt*8 + 2*q;
            float2 ge = *(const float2*)&sgeo[ch0];
            float2 be = *(const float2*)&sbeeo[ch0];
            float v0 = silu_t((u0[nt] - mean)*rstd*ge.x + be.x);
            float v1 = silu_t((u1[nt] - mean)*rstd*ge.y + be.y);
            *(float2*)&sv[grp*36 + ch0] = make_float2(v0, v1);
        }
        __syncwarp();

        #pragma unroll
        for (int h = 0; h < 2; h++) {
            const int pr  = h*4 + (lane >> 3);
            const int ch2 = lane & 7;
            float t = 0.f;
            #pragma unroll
            for (int k4 = 0; k4 < 8; k4++) {
                float4 vv = *(const float4*)&sv[pr*36 + k4*4];
                float4 w4 = *(const float4*)&sw_eo2T[ch2*36 + k4*4];
                t += vv.x*w4.x + vv.y*w4.y + vv.z*w4.z + vv.w*w4.w;
            }
            if (ch2 < KEdim && sact[pr]) {
                const int io = smi[pr], jo2 = smj[pr];
                float outv = (t + sbeo2[ch2]) * sem[pr];
                out_edge[((size_t)(b*Ndim + io)*Ndim + jo2)*KEdim + ch2] = outv;
                out_edge[((size_t)(b*Ndim + jo2)*Ndim + io)*KEdim + ch2] = outv;
            }
        }
        __syncwarp();
    }
}

// ---------------------------------------------------------------------------
extern "C" void kernel_launch(void* const* d_in, const int* in_sizes, int n_in,
                              void* d_out, int out_size)
{
    const float* node      = (const float*)d_in[0];
    const float* edge      = (const float*)d_in[1];
    const int*   block_id  = (const int*)d_in[2];
    const int*   vmask     = (const int*)d_in[3];
    const float* W_nt  = (const float*)d_in[4];
    const float* b_nt  = (const float*)d_in[5];
    const float* W_n1  = (const float*)d_in[6];
    const float* b_n1  = (const float*)d_in[7];
    const float* W_e1  = (const float*)d_in[8];
    const float* b_e1  = (const float*)d_in[9];
    const float* W_f1  = (const float*)d_in[10];
    const float* b_f1  = (const float*)d_in[11];
    const float* W_f2  = (const float*)d_in[12];
    const float* b_f2  = (const float*)d_in[13];
    const float* W_no1 = (const float*)d_in[14];
    const float* b_no1 = (const float*)d_in[15];
    const float* g_no  = (const float*)d_in[16];
    const float* be_no = (const float*)d_in[17];
    const float* W_no2 = (const float*)d_in[18];
    const float* b_no2 = (const float*)d_in[19];
    const float* W_eo1 = (const float*)d_in[20];
    const float* b_eo1 = (const float*)d_in[21];
    const float* g_eo  = (const float*)d_in[22];
    const float* be_eo = (const float*)d_in[23];
    const float* W_eo2 = (const float*)d_in[24];
    const float* b_eo2 = (const float*)d_in[25];

    float* out_node = (float*)d_out;                       // (B,N,KN)
    float* out_edge = (float*)d_out + Bdim*Ndim*KNdim;     // (B,N,N,KE)

    static int smem_set = 0;
    if (!smem_set) {
        cudaFuncSetAttribute(edge_kernel, cudaFuncAttributeMaxDynamicSharedMemorySize, SM_TOTAL);
        smem_set = 1;
    }

    reduce_kernel<<<Bdim*Ndim, 256>>>(edge, block_id, vmask);

    node_kernel<<<Bdim*64, 256>>>(node, block_id,
                                  W_nt, b_nt, W_n1, b_n1, W_f1,
                                  W_no1, b_no1, g_no, be_no, W_no2, b_no2,
                                  out_node);

    edge_kernel<<<Bdim*257, 256, SM_TOTAL>>>(edge, block_id, vmask,
                                   W_e1, b_e1, b_f1, W_f2, b_f2,
                                   W_eo1, b_eo1, g_eo, be_eo, W_eo2, b_eo2,
                                   out_edge);
}